// round 10
// baseline (speedup 1.0000x reference)
#include <cuda_runtime.h>
#include <cuda_fp16.h>
#include <cstdint>

#define FULL 0xffffffffu

constexpr int NN   = 50000;
constexpr int NE   = 400000;
constexpr int F    = 32;
constexpr int H    = 4;
constexpr int ROWS = NN * H;        // 200000 (n,h) rows
constexpr int NG   = NE / H;        // 100000 message groups

// ---- scratch (device globals; no allocation allowed) ----
__device__ float    g_h[ROWS * F];
__device__ float    g_atom[ROWS * F];
__device__ __half   g_xs[ROWS * F];
__device__ __half   g_xd[ROWS * F];
__device__ __half   g_xm[ROWS * F];
__device__ __half   g_ea[NE * F];       // layer 0
__device__ __half   g_em[NE * F];
__device__ __half   g_ea2[NE * F];      // layer 1
__device__ __half   g_em2[NE * F];
__device__ float    g_exp[NE * H];
__device__ float    g_nsum[NN];
__device__ float    g_aggr[ROWS * F];

__device__ __forceinline__ void mma16(float d[4], const uint32_t a[4],
                                      uint32_t b0, uint32_t b1) {
    asm("mma.sync.aligned.m16n8k16.row.col.f32.f16.f16.f32 "
        "{%0,%1,%2,%3}, {%4,%5,%6,%7}, {%8,%9}, {%0,%1,%2,%3};"
        : "+f"(d[0]), "+f"(d[1]), "+f"(d[2]), "+f"(d[3])
        : "r"(a[0]), "r"(a[1]), "r"(a[2]), "r"(a[3]), "r"(b0), "r"(b1));
}

// split fp32 pair -> fp16 hi + fp16 residual lo (packed half2 as u32)
__device__ __forceinline__ void splitH(float x, float y,
                                       uint32_t& hi, uint32_t& lo) {
    __half2 h = __floats2half2_rn(x, y);
    float2 hf = __half22float2(h);
    __half2 l = __floats2half2_rn(x - hf.x, y - hf.y);
    hi = *(uint32_t*)&h;
    lo = *(uint32_t*)&l;
}

struct GArgs {
    const float* A;
    const float* B[4];
    const float* bias[4];
    void*        out[4];
    void*        out2[4];
    int          M;
    int          Astride;
    int          Bstride;
    int          Ostride;
};

// ============================================================================
// gemm_body: out[m] = A @ B[m] + bias[m], K = KC16*16, N = 32/matrix.
// split-fp16 2-term scheme (AhiBhi + AhiBlo + AloBhi), smem-staged B.
// MODE 0 plain; MODE 1 relu + dual write; MODE 2 comb epilogue
// (+g_aggr +g_atom, relu, REZEROES g_aggr); MODE 3 = comb + head-mean.
// OUTH: store fp16.
// ============================================================================
template<int NM, int KC16, int MODE, int OUTH>
__device__ __forceinline__ void gemm_body(const GArgs& ga, uint32_t* sB,
                                          int bid, int nblocks, int tid) {
    constexpr int NT = NM * 4;
    constexpr int PITCH = NM * 32 + 8;   // % 32 == 8 -> conflict-free
    constexpr int KK = KC16 * 8;         // half2 k-rows
    uint32_t* sH = sB;
    uint32_t* sL = sB + KK * PITCH;

    for (int m = 0; m < NM; m++) {
        const float* Bp = ga.B[m];
        for (int i = tid; i < KK * 32; i += 256) {
            int kk = i >> 5, n = i & 31;
            float v0 = Bp[(size_t)(2 * kk)     * ga.Bstride + n];
            float v1 = Bp[(size_t)(2 * kk + 1) * ga.Bstride + n];
            uint32_t hi, lo;
            splitH(v0, v1, hi, lo);
            sH[kk * PITCH + m * 32 + n] = hi;
            sL[kk * PITCH + m * 32 + n] = lo;
        }
    }
    __syncthreads();

    int lane = tid & 31;
    int gid = lane >> 2, tig = lane & 3;
    int gw = bid * 8 + (tid >> 5);
    int nw = nblocks * 8;
    int ntile = ga.M >> 4;
    const int As = ga.Astride;

    for (int t = gw; t < ntile; t += nw) {
        const float* Ap = ga.A + (size_t)(t * 16) * As;
        float d[NT][4];
#pragma unroll
        for (int nt = 0; nt < NT; nt++) {
            d[nt][0] = 0.f; d[nt][1] = 0.f; d[nt][2] = 0.f; d[nt][3] = 0.f;
        }
#pragma unroll 2
        for (int kc = 0; kc < KC16; kc++) {
            float2 p0 = *(const float2*)(Ap + (size_t)gid * As + kc * 16 + 2 * tig);
            float2 p1 = *(const float2*)(Ap + (size_t)(gid + 8) * As + kc * 16 + 2 * tig);
            float2 p2 = *(const float2*)(Ap + (size_t)gid * As + kc * 16 + 2 * tig + 8);
            float2 p3 = *(const float2*)(Ap + (size_t)(gid + 8) * As + kc * 16 + 2 * tig + 8);
            uint32_t ah[4], al[4];
            splitH(p0.x, p0.y, ah[0], al[0]);
            splitH(p1.x, p1.y, ah[1], al[1]);
            splitH(p2.x, p2.y, ah[2], al[2]);
            splitH(p3.x, p3.y, ah[3], al[3]);
            int krow = (kc * 8 + tig) * PITCH + gid;
#pragma unroll
            for (int nt = 0; nt < NT; nt++) {
                int i0 = krow + nt * 8;
                uint32_t bh0 = sH[i0], bh1 = sH[i0 + 4 * PITCH];
                uint32_t bl0 = sL[i0], bl1 = sL[i0 + 4 * PITCH];
                mma16(d[nt], ah, bh0, bh1);
                mma16(d[nt], ah, bl0, bl1);
                mma16(d[nt], al, bh0, bh1);
            }
        }
        int ra = t * 16 + gid, rb = ra + 8;
#pragma unroll
        for (int nt = 0; nt < NT; nt++) {
            const int m = nt >> 2;
            int c = (nt & 3) * 8 + 2 * tig;
            float b0 = ga.bias[m][c], b1 = ga.bias[m][c + 1];
            float o0 = d[nt][0] + b0, o1 = d[nt][1] + b1;
            float o2 = d[nt][2] + b0, o3 = d[nt][3] + b1;
            if (MODE >= 2) {
                int ia = ra * 32 + c, ib = rb * 32 + c;
                o0 += g_aggr[ia]     + g_atom[ia];
                o1 += g_aggr[ia + 1] + g_atom[ia + 1];
                o2 += g_aggr[ib]     + g_atom[ib];
                o3 += g_aggr[ib + 1] + g_atom[ib + 1];
                if (MODE == 2) {
                    // re-zero aggr for the next layer's scatter
                    *(float2*)&g_aggr[ia] = make_float2(0.f, 0.f);
                    *(float2*)&g_aggr[ib] = make_float2(0.f, 0.f);
                }
            }
            if (MODE != 0) {
                o0 = fmaxf(o0, 0.f); o1 = fmaxf(o1, 0.f);
                o2 = fmaxf(o2, 0.f); o3 = fmaxf(o3, 0.f);
            }
            if (MODE == 3) {
                // head-mean: 4 consecutive rows = 4 heads of one node.
                float s0 = o0 + __shfl_xor_sync(FULL, o0, 4);
                s0 += __shfl_xor_sync(FULL, s0, 8);
                float s1 = o1 + __shfl_xor_sync(FULL, o1, 4);
                s1 += __shfl_xor_sync(FULL, s1, 8);
                float s2 = o2 + __shfl_xor_sync(FULL, o2, 4);
                s2 += __shfl_xor_sync(FULL, s2, 8);
                float s3 = o3 + __shfl_xor_sync(FULL, o3, 4);
                s3 += __shfl_xor_sync(FULL, s3, 8);
                if ((gid & 3) == 0) {
                    float* op = (float*)ga.out[0];
                    int na = ra >> 2;
                    int nb = rb >> 2;
                    *(float2*)&op[na * 32 + c] = make_float2(0.25f*s0, 0.25f*s1);
                    *(float2*)&op[nb * 32 + c] = make_float2(0.25f*s2, 0.25f*s3);
                }
                continue;
            }
            size_t ia = (size_t)ra * ga.Ostride + c;
            size_t ib = (size_t)rb * ga.Ostride + c;
            if (OUTH) {
                __half* op = (__half*)ga.out[m];
                *(__half2*)&op[ia] = __floats2half2_rn(o0, o1);
                *(__half2*)&op[ib] = __floats2half2_rn(o2, o3);
            } else {
                float* op = (float*)ga.out[m];
                *(float2*)&op[ia] = make_float2(o0, o1);
                *(float2*)&op[ib] = make_float2(o2, o3);
                if (MODE == 1) {
                    float* op2 = (float*)ga.out2[m];
                    *(float2*)&op2[ia] = make_float2(o0, o1);
                    *(float2*)&op2[ib] = make_float2(o2, o3);
                }
            }
        }
    }
}

template<int NM, int KC16, int MODE, int OUTH, int MINB>
__global__ void __launch_bounds__(256, MINB) k_g(GArgs ga) {
    extern __shared__ uint32_t sB[];
    gemm_body<NM, KC16, MODE, OUTH>(ga, sB, blockIdx.x, gridDim.x, threadIdx.x);
}

// nlin3 + optional nsum zeroing in trailing blocks
template<int MINB>
__global__ void __launch_bounds__(256, MINB) k_nlin(GArgs ga, int zeroNsum) {
    extern __shared__ uint32_t sB[];
    if (blockIdx.x < 444) {
        gemm_body<3, 2, 0, 1>(ga, sB, blockIdx.x, 444, threadIdx.x);
    } else if (zeroNsum) {
        int i = (blockIdx.x - 444) * 256 + threadIdx.x;
        int stride = (gridDim.x - 444) * 256;
        for (int j = i; j < NN; j += stride)
            g_nsum[j] = 0.f;
    }
}

// ---- zero aggr/nsum (once, at start) ----
__global__ void k_init() {
    int i = blockIdx.x * blockDim.x + threadIdx.x;
    int stride = gridDim.x * blockDim.x;
    for (int j = i; j < ROWS * F / 4; j += stride)
        ((float4*)g_aggr)[j] = make_float4(0.f, 0.f, 0.f, 0.f);
    for (int j = i; j < NN; j += stride)
        g_nsum[j] = 0.f;
}

__device__ __forceinline__ float4 ld4h(const __half* p) {
    uint2 u = *(const uint2*)p;
    float2 lo = __half22float2(*(__half2*)&u.x);
    float2 hi = __half22float2(*(__half2*)&u.y);
    return make_float4(lo.x, lo.y, hi.x, hi.y);
}

// ---- edge attention: scores -> exp -> segment sum, fused; 2-edge unroll ----
__global__ void k_attn(const int* __restrict__ ei, const __half* __restrict__ ea_p,
                       const float* __restrict__ dw, const float* __restrict__ db) {
    int lane = threadIdx.x & 31;
    int q = lane & 7;
    float4 dw4 = ((const float4*)dw)[q];
    float dbv = db[0];
    int gw = (blockIdx.x * blockDim.x + threadIdx.x) >> 5;
    int nw = (gridDim.x * blockDim.x) >> 5;
    for (int e0 = gw * 2; e0 < NE; e0 += nw * 2) {
        int sA = __ldg(ei + e0),     dA = __ldg(ei + NE + e0);
        int sB = __ldg(ei + e0 + 1), dB = __ldg(ei + NE + e0 + 1);
        float4 aA  = ld4h(g_xs + (size_t)dA * 128 + lane * 4);
        float4 cA  = ld4h(g_xd + (size_t)sA * 128 + lane * 4);
        float4 eA  = ld4h(ea_p + (size_t)e0 * 32 + q * 4);
        float4 aB  = ld4h(g_xs + (size_t)dB * 128 + lane * 4);
        float4 cB  = ld4h(g_xd + (size_t)sB * 128 + lane * 4);
        float4 eB  = ld4h(ea_p + (size_t)(e0 + 1) * 32 + q * 4);
        float vA = fmaxf(aA.x + cA.x + eA.x, 0.f) * dw4.x
                 + fmaxf(aA.y + cA.y + eA.y, 0.f) * dw4.y
                 + fmaxf(aA.z + cA.z + eA.z, 0.f) * dw4.z
                 + fmaxf(aA.w + cA.w + eA.w, 0.f) * dw4.w;
        float vB = fmaxf(aB.x + cB.x + eB.x, 0.f) * dw4.x
                 + fmaxf(aB.y + cB.y + eB.y, 0.f) * dw4.y
                 + fmaxf(aB.z + cB.z + eB.z, 0.f) * dw4.z
                 + fmaxf(aB.w + cB.w + eB.w, 0.f) * dw4.w;
        vA += __shfl_xor_sync(FULL, vA, 4);
        vB += __shfl_xor_sync(FULL, vB, 4);
        vA += __shfl_xor_sync(FULL, vA, 2);
        vB += __shfl_xor_sync(FULL, vB, 2);
        vA += __shfl_xor_sync(FULL, vA, 1);
        vB += __shfl_xor_sync(FULL, vB, 1);
        float arA = __shfl_sync(FULL, vA, (lane & 3) * 8) + dbv;
        float arB = __shfl_sync(FULL, vB, (lane & 3) * 8) + dbv;
        float exA = __expf(arA);
        float exB = __expf(arB);
        float tA = exA + __shfl_xor_sync(FULL, exA, 1);
        float tB = exB + __shfl_xor_sync(FULL, exB, 1);
        tA += __shfl_xor_sync(FULL, tA, 2);
        tB += __shfl_xor_sync(FULL, tB, 2);
        if (lane < 4) g_exp[e0 * 4 + lane] = exA;
        else if (lane < 8) g_exp[(e0 + 1) * 4 + (lane & 3)] = exB;
        if (lane == 0) atomicAdd(&g_nsum[dA], tA);
        if (lane == 8) atomicAdd(&g_nsum[dB], tB);
    }
}

// ---- messages + tiled scatter (lane = j*8+q; one red.v4 per lane) ----
__global__ void k_msg(const int* __restrict__ ei, const __half* __restrict__ em_p) {
    int lane = threadIdx.x & 31;
    int q = lane & 7;
    int j = lane >> 3;
    int gw = (blockIdx.x * blockDim.x + threadIdx.x) >> 5;
    int nw = (gridDim.x * blockDim.x) >> 5;
    for (int g = gw; g < NG; g += nw) {
        float4 T = make_float4(0.f, 0.f, 0.f, 0.f);
#pragma unroll
        for (int c = 0; c < 4; c++) {
            int e = c * NG + g;
            int d = __ldg(ei + NE + e);
            float4 ex = ((const float4*)g_exp)[e];
            float inv = 1.f / (g_nsum[d] + 1e-8f);
            float exh = (j == 0) ? ex.x : (j == 1) ? ex.y : (j == 2) ? ex.z : ex.w;
            float sA = exh * inv;
            float4 xm = ld4h(g_xm + (size_t)d * 128 + lane * 4);
            float4 em = ld4h(em_p + (size_t)e * 32 + q * 4);
            T.x += sA * (xm.x + em.x);
            T.y += sA * (xm.y + em.y);
            T.z += sA * (xm.z + em.z);
            T.w += sA * (xm.w + em.w);
        }
        int tgt = __ldg(ei + NE + 4 * g + j);
        float* p = g_aggr + (size_t)tgt * 32 + q * 4;
        asm volatile("red.global.add.v4.f32 [%0], {%1,%2,%3,%4};"
                     :: "l"(p), "f"(T.x), "f"(T.y), "f"(T.z), "f"(T.w)
                     : "memory");
    }
}

extern "C" void kernel_launch(void* const* d_in, const int* in_sizes, int n_in,
                              void* d_out, int out_size) {
    const float* x      = (const float*)d_in[0];
    const float* eattr  = (const float*)d_in[1];
    const int*   ei     = (const int*)d_in[2];
    const float* atom_w = (const float*)d_in[3];
    const float* atom_b = (const float*)d_in[4];
    const float* asw  = (const float*)d_in[5];
    const float* asb  = (const float*)d_in[6];
    const float* adw  = (const float*)d_in[7];
    const float* adb  = (const float*)d_in[8];
    const float* aew  = (const float*)d_in[9];
    const float* aeb  = (const float*)d_in[10];
    const float* dotw = (const float*)d_in[11];
    const float* dotb = (const float*)d_in[12];
    const float* mdw  = (const float*)d_in[13];
    const float* mdb  = (const float*)d_in[14];
    const float* mew  = (const float*)d_in[15];
    const float* meb  = (const float*)d_in[16];
    const float* wnw  = (const float*)d_in[17];
    const float* wnb  = (const float*)d_in[18];
    float* out = (float*)d_out;

    float *p_h, *p_atom;
    __half *p_xs, *p_xd, *p_xm, *p_ea, *p_em, *p_ea2, *p_em2;
    cudaGetSymbolAddress((void**)&p_h,    g_h);
    cudaGetSymbolAddress((void**)&p_atom, g_atom);
    cudaGetSymbolAddress((void**)&p_xs,   g_xs);
    cudaGetSymbolAddress((void**)&p_xd,   g_xd);
    cudaGetSymbolAddress((void**)&p_xm,   g_xm);
    cudaGetSymbolAddress((void**)&p_ea,   g_ea);
    cudaGetSymbolAddress((void**)&p_em,   g_em);
    cudaGetSymbolAddress((void**)&p_ea2,  g_ea2);
    cudaGetSymbolAddress((void**)&p_em2,  g_em2);

    // smem = 2 * KK * PITCH * 4
    const int smem_atom = 2 * 64 * (4 * 32 + 8) * 4;    // 69632
    const int smem_e4   = 2 * 16 * (4 * 32 + 8) * 4;    // 17408
    const int smem_n3   = 2 * 16 * (3 * 32 + 8) * 4;    // 13312
    const int smem_c1   = 2 * 16 * (1 * 32 + 8) * 4;    // 5120
    cudaFuncSetAttribute(k_g<4, 8, 1, 0, 1>,
                         cudaFuncAttributeMaxDynamicSharedMemorySize, smem_atom);

    k_init<<<512, 256>>>();

    // atom: (50000 x 128) @ (128 x 128), relu, dual fp32 write g_atom/g_h
    {
        GArgs ga;
        ga.A = x; ga.M = NN; ga.Astride = 128; ga.Bstride = 128; ga.Ostride = 128;
        for (int m = 0; m < 4; m++) {
            ga.B[m]    = atom_w + m * 32;
            ga.bias[m] = atom_b + m * 32;
            ga.out[m]  = p_atom + m * 32;
            ga.out2[m] = p_h    + m * 32;
        }
        k_g<4, 8, 1, 0, 1><<<296, 256, smem_atom>>>(ga);
    }

    // elin both layers in ONE pass over eattr: ea0, em0, ea1, em1 (fp16 out)
    {
        GArgs ge;
        ge.A = eattr; ge.M = NE; ge.Astride = 32; ge.Bstride = 32; ge.Ostride = 32;
        ge.B[0] = aew;        ge.B[1] = mew;        ge.B[2] = aew + 1024; ge.B[3] = mew + 1024;
        ge.bias[0] = aeb;     ge.bias[1] = meb;     ge.bias[2] = aeb + 32; ge.bias[3] = meb + 32;
        ge.out[0] = p_ea; ge.out[1] = p_em; ge.out[2] = p_ea2; ge.out[3] = p_em2;
        for (int m = 0; m < 4; m++) ge.out2[m] = p_ea;
        k_g<4, 2, 0, 1, 2><<<444, 256, smem_e4>>>(ge);
    }

    for (int l = 0; l < 2; l++) {
        int wo = l * 32 * 32, bo = l * 32;
        const __half* ea_l = l ? p_ea2 : p_ea;
        const __half* em_l = l ? p_em2 : p_em;

        GArgs gn;
        gn.A = p_h; gn.M = ROWS; gn.Astride = 32; gn.Bstride = 32; gn.Ostride = 32;
        gn.B[0] = asw + wo; gn.B[1] = adw + wo; gn.B[2] = mdw + wo; gn.B[3] = asw + wo;
        gn.bias[0] = asb + bo; gn.bias[1] = adb + bo; gn.bias[2] = mdb + bo; gn.bias[3] = asb + bo;
        gn.out[0] = p_xs; gn.out[1] = p_xd; gn.out[2] = p_xm; gn.out[3] = p_xs;
        for (int m = 0; m < 4; m++) gn.out2[m] = p_xs;
        k_nlin<2><<<444 + 49, 256, smem_n3>>>(gn, l);   // trailing blocks zero nsum (l=1)

        k_attn<<<1024, 256>>>(ei, ea_l, dotw + l * 32, dotb + l);
        k_msg<<<1024, 256>>>(ei, em_l);

        GArgs gc;
        gc.A = p_h; gc.M = ROWS; gc.Astride = 32; gc.Bstride = 32; gc.Ostride = 32;
        gc.B[0] = wnw + wo; gc.B[1] = wnw + wo; gc.B[2] = wnw + wo; gc.B[3] = wnw + wo;
        gc.bias[0] = wnb + bo; gc.bias[1] = wnb + bo; gc.bias[2] = wnb + bo; gc.bias[3] = wnb + bo;
        gc.out2[0] = gc.out2[1] = gc.out2[2] = gc.out2[3] = p_h;
        if (l == 0) {
            gc.out[0] = p_h; gc.out[1] = p_h; gc.out[2] = p_h; gc.out[3] = p_h;
            k_g<1, 2, 2, 0, 2><<<444, 256, smem_c1>>>(gc);   // re-zeroes aggr
        } else {
            gc.out[0] = out; gc.out[1] = out; gc.out[2] = out; gc.out[3] = out;
            k_g<1, 2, 3, 0, 2><<<444, 256, smem_c1>>>(gc);
        }
    }
}

// round 11
// speedup vs baseline: 1.0534x; 1.0534x over previous
#include <cuda_runtime.h>
#include <cuda_fp16.h>
#include <cstdint>

#define FULL 0xffffffffu

constexpr int NN   = 50000;
constexpr int NE   = 400000;
constexpr int F    = 32;
constexpr int H    = 4;
constexpr int ROWS = NN * H;        // 200000 (n,h) rows
constexpr int NG   = NE / H;        // 100000 message groups

// ---- scratch (device globals; no allocation allowed) ----
__device__ float    g_h[ROWS * F];
__device__ float    g_atom[ROWS * F];
__device__ __half   g_xs[ROWS * F];
__device__ __half   g_xd[ROWS * F];
__device__ __half   g_xm[ROWS * F];
__device__ __half   g_ea[NE * F];       // layer 0
__device__ __half   g_em[NE * F];
__device__ __half   g_ea2[NE * F];      // layer 1
__device__ __half   g_em2[NE * F];
__device__ float    g_exp[NE * H];
__device__ float    g_nsum[NN];
__device__ float    g_aggr[ROWS * F];

__device__ __forceinline__ void mma16(float d[4], const uint32_t a[4],
                                      uint32_t b0, uint32_t b1) {
    asm("mma.sync.aligned.m16n8k16.row.col.f32.f16.f16.f32 "
        "{%0,%1,%2,%3}, {%4,%5,%6,%7}, {%8,%9}, {%0,%1,%2,%3};"
        : "+f"(d[0]), "+f"(d[1]), "+f"(d[2]), "+f"(d[3])
        : "r"(a[0]), "r"(a[1]), "r"(a[2]), "r"(a[3]), "r"(b0), "r"(b1));
}

// split fp32 pair -> fp16 hi + fp16 residual lo (packed half2 as u32)
__device__ __forceinline__ void splitH(float x, float y,
                                       uint32_t& hi, uint32_t& lo) {
    __half2 h = __floats2half2_rn(x, y);
    float2 hf = __half22float2(h);
    __half2 l = __floats2half2_rn(x - hf.x, y - hf.y);
    hi = *(uint32_t*)&h;
    lo = *(uint32_t*)&l;
}

struct GArgs {
    const float* A;
    const float* B[4];
    const float* bias[4];
    void*        out[4];
    void*        out2[4];
    int          M;
    int          Astride;
    int          Bstride;
    int          Ostride;
};

// ============================================================================
// gemm_body: out[m] = A @ B[m] + bias[m], K = KC16*16, N = 32/matrix.
// split-fp16 2-term scheme (AhiBhi + AhiBlo + AloBhi), smem-staged B.
// MODE 0 plain; MODE 1 relu + dual write; MODE 2 comb epilogue
// (+g_aggr +g_atom, relu, REZEROES g_aggr); MODE 3 = comb + head-mean.
// OUTH: store fp16.
// ============================================================================
template<int NM, int KC16, int MODE, int OUTH>
__device__ __forceinline__ void gemm_body(const GArgs& ga, uint32_t* sB,
                                          int bid, int nblocks, int tid) {
    constexpr int NT = NM * 4;
    constexpr int PITCH = NM * 32 + 8;   // % 32 == 8 -> conflict-free
    constexpr int KK = KC16 * 8;         // half2 k-rows
    uint32_t* sH = sB;
    uint32_t* sL = sB + KK * PITCH;

    for (int m = 0; m < NM; m++) {
        const float* Bp = ga.B[m];
        for (int i = tid; i < KK * 32; i += 256) {
            int kk = i >> 5, n = i & 31;
            float v0 = Bp[(size_t)(2 * kk)     * ga.Bstride + n];
            float v1 = Bp[(size_t)(2 * kk + 1) * ga.Bstride + n];
            uint32_t hi, lo;
            splitH(v0, v1, hi, lo);
            sH[kk * PITCH + m * 32 + n] = hi;
            sL[kk * PITCH + m * 32 + n] = lo;
        }
    }
    __syncthreads();

    int lane = tid & 31;
    int gid = lane >> 2, tig = lane & 3;
    int gw = bid * 8 + (tid >> 5);
    int nw = nblocks * 8;
    int ntile = ga.M >> 4;
    const int As = ga.Astride;

    for (int t = gw; t < ntile; t += nw) {
        const float* Ap = ga.A + (size_t)(t * 16) * As;
        float d[NT][4];
#pragma unroll
        for (int nt = 0; nt < NT; nt++) {
            d[nt][0] = 0.f; d[nt][1] = 0.f; d[nt][2] = 0.f; d[nt][3] = 0.f;
        }
#pragma unroll 2
        for (int kc = 0; kc < KC16; kc++) {
            float2 p0 = *(const float2*)(Ap + (size_t)gid * As + kc * 16 + 2 * tig);
            float2 p1 = *(const float2*)(Ap + (size_t)(gid + 8) * As + kc * 16 + 2 * tig);
            float2 p2 = *(const float2*)(Ap + (size_t)gid * As + kc * 16 + 2 * tig + 8);
            float2 p3 = *(const float2*)(Ap + (size_t)(gid + 8) * As + kc * 16 + 2 * tig + 8);
            uint32_t ah[4], al[4];
            splitH(p0.x, p0.y, ah[0], al[0]);
            splitH(p1.x, p1.y, ah[1], al[1]);
            splitH(p2.x, p2.y, ah[2], al[2]);
            splitH(p3.x, p3.y, ah[3], al[3]);
            int krow = (kc * 8 + tig) * PITCH + gid;
#pragma unroll
            for (int nt = 0; nt < NT; nt++) {
                int i0 = krow + nt * 8;
                uint32_t bh0 = sH[i0], bh1 = sH[i0 + 4 * PITCH];
                uint32_t bl0 = sL[i0], bl1 = sL[i0 + 4 * PITCH];
                mma16(d[nt], ah, bh0, bh1);
                mma16(d[nt], ah, bl0, bl1);
                mma16(d[nt], al, bh0, bh1);
            }
        }
        int ra = t * 16 + gid, rb = ra + 8;
#pragma unroll
        for (int nt = 0; nt < NT; nt++) {
            const int m = nt >> 2;
            int c = (nt & 3) * 8 + 2 * tig;
            float b0 = ga.bias[m][c], b1 = ga.bias[m][c + 1];
            float o0 = d[nt][0] + b0, o1 = d[nt][1] + b1;
            float o2 = d[nt][2] + b0, o3 = d[nt][3] + b1;
            if (MODE >= 2) {
                int ia = ra * 32 + c, ib = rb * 32 + c;
                o0 += g_aggr[ia]     + g_atom[ia];
                o1 += g_aggr[ia + 1] + g_atom[ia + 1];
                o2 += g_aggr[ib]     + g_atom[ib];
                o3 += g_aggr[ib + 1] + g_atom[ib + 1];
                if (MODE == 2) {
                    // re-zero aggr for the next layer's scatter
                    *(float2*)&g_aggr[ia] = make_float2(0.f, 0.f);
                    *(float2*)&g_aggr[ib] = make_float2(0.f, 0.f);
                }
            }
            if (MODE != 0) {
                o0 = fmaxf(o0, 0.f); o1 = fmaxf(o1, 0.f);
                o2 = fmaxf(o2, 0.f); o3 = fmaxf(o3, 0.f);
            }
            if (MODE == 3) {
                // head-mean: 4 consecutive rows = 4 heads of one node.
                float s0 = o0 + __shfl_xor_sync(FULL, o0, 4);
                s0 += __shfl_xor_sync(FULL, s0, 8);
                float s1 = o1 + __shfl_xor_sync(FULL, o1, 4);
                s1 += __shfl_xor_sync(FULL, s1, 8);
                float s2 = o2 + __shfl_xor_sync(FULL, o2, 4);
                s2 += __shfl_xor_sync(FULL, s2, 8);
                float s3 = o3 + __shfl_xor_sync(FULL, o3, 4);
                s3 += __shfl_xor_sync(FULL, s3, 8);
                if ((gid & 3) == 0) {
                    float* op = (float*)ga.out[0];
                    int na = ra >> 2;
                    int nb = rb >> 2;
                    *(float2*)&op[na * 32 + c] = make_float2(0.25f*s0, 0.25f*s1);
                    *(float2*)&op[nb * 32 + c] = make_float2(0.25f*s2, 0.25f*s3);
                }
                continue;
            }
            size_t ia = (size_t)ra * ga.Ostride + c;
            size_t ib = (size_t)rb * ga.Ostride + c;
            if (OUTH) {
                __half* op = (__half*)ga.out[m];
                *(__half2*)&op[ia] = __floats2half2_rn(o0, o1);
                *(__half2*)&op[ib] = __floats2half2_rn(o2, o3);
            } else {
                float* op = (float*)ga.out[m];
                *(float2*)&op[ia] = make_float2(o0, o1);
                *(float2*)&op[ib] = make_float2(o2, o3);
                if (MODE == 1) {
                    float* op2 = (float*)ga.out2[m];
                    *(float2*)&op2[ia] = make_float2(o0, o1);
                    *(float2*)&op2[ib] = make_float2(o2, o3);
                }
            }
        }
    }
}

template<int NM, int KC16, int MODE, int OUTH, int MINB>
__global__ void __launch_bounds__(256, MINB) k_g(GArgs ga) {
    extern __shared__ uint32_t sB[];
    gemm_body<NM, KC16, MODE, OUTH>(ga, sB, blockIdx.x, gridDim.x, threadIdx.x);
}

// nlin3 + optional nsum zeroing in trailing blocks
template<int MINB>
__global__ void __launch_bounds__(256, MINB) k_nlin(GArgs ga, int zeroNsum) {
    extern __shared__ uint32_t sB[];
    if (blockIdx.x < 444) {
        gemm_body<3, 2, 0, 1>(ga, sB, blockIdx.x, 444, threadIdx.x);
    } else if (zeroNsum) {
        int i = (blockIdx.x - 444) * 256 + threadIdx.x;
        int stride = (gridDim.x - 444) * 256;
        for (int j = i; j < NN; j += stride)
            g_nsum[j] = 0.f;
    }
}

// ---- zero aggr/nsum (once, at start) ----
__global__ void k_init() {
    int i = blockIdx.x * blockDim.x + threadIdx.x;
    int stride = gridDim.x * blockDim.x;
    for (int j = i; j < ROWS * F / 4; j += stride)
        ((float4*)g_aggr)[j] = make_float4(0.f, 0.f, 0.f, 0.f);
    for (int j = i; j < NN; j += stride)
        g_nsum[j] = 0.f;
}

__device__ __forceinline__ float4 ld4h(const __half* p) {
    uint2 u = *(const uint2*)p;
    float2 lo = __half22float2(*(__half2*)&u.x);
    float2 hi = __half22float2(*(__half2*)&u.y);
    return make_float4(lo.x, lo.y, hi.x, hi.y);
}

// ---- edge attention: scores -> exp -> segment sum, fused; 2-edge unroll ----
__global__ void k_attn(const int* __restrict__ ei, const __half* __restrict__ ea_p,
                       const float* __restrict__ dw, const float* __restrict__ db) {
    int lane = threadIdx.x & 31;
    int q = lane & 7;
    float4 dw4 = ((const float4*)dw)[q];
    float dbv = db[0];
    int gw = (blockIdx.x * blockDim.x + threadIdx.x) >> 5;
    int nw = (gridDim.x * blockDim.x) >> 5;
    for (int e0 = gw * 2; e0 < NE; e0 += nw * 2) {
        int sA = __ldg(ei + e0),     dA = __ldg(ei + NE + e0);
        int sB = __ldg(ei + e0 + 1), dB = __ldg(ei + NE + e0 + 1);
        float4 aA  = ld4h(g_xs + (size_t)dA * 128 + lane * 4);
        float4 cA  = ld4h(g_xd + (size_t)sA * 128 + lane * 4);
        float4 eA  = ld4h(ea_p + (size_t)e0 * 32 + q * 4);
        float4 aB  = ld4h(g_xs + (size_t)dB * 128 + lane * 4);
        float4 cB  = ld4h(g_xd + (size_t)sB * 128 + lane * 4);
        float4 eB  = ld4h(ea_p + (size_t)(e0 + 1) * 32 + q * 4);
        float vA = fmaxf(aA.x + cA.x + eA.x, 0.f) * dw4.x
                 + fmaxf(aA.y + cA.y + eA.y, 0.f) * dw4.y
                 + fmaxf(aA.z + cA.z + eA.z, 0.f) * dw4.z
                 + fmaxf(aA.w + cA.w + eA.w, 0.f) * dw4.w;
        float vB = fmaxf(aB.x + cB.x + eB.x, 0.f) * dw4.x
                 + fmaxf(aB.y + cB.y + eB.y, 0.f) * dw4.y
                 + fmaxf(aB.z + cB.z + eB.z, 0.f) * dw4.z
                 + fmaxf(aB.w + cB.w + eB.w, 0.f) * dw4.w;
        vA += __shfl_xor_sync(FULL, vA, 4);
        vB += __shfl_xor_sync(FULL, vB, 4);
        vA += __shfl_xor_sync(FULL, vA, 2);
        vB += __shfl_xor_sync(FULL, vB, 2);
        vA += __shfl_xor_sync(FULL, vA, 1);
        vB += __shfl_xor_sync(FULL, vB, 1);
        float arA = __shfl_sync(FULL, vA, (lane & 3) * 8) + dbv;
        float arB = __shfl_sync(FULL, vB, (lane & 3) * 8) + dbv;
        float exA = __expf(arA);
        float exB = __expf(arB);
        float tA = exA + __shfl_xor_sync(FULL, exA, 1);
        float tB = exB + __shfl_xor_sync(FULL, exB, 1);
        tA += __shfl_xor_sync(FULL, tA, 2);
        tB += __shfl_xor_sync(FULL, tB, 2);
        if (lane < 4) g_exp[e0 * 4 + lane] = exA;
        else if (lane < 8) g_exp[(e0 + 1) * 4 + (lane & 3)] = exB;
        if (lane == 0) atomicAdd(&g_nsum[dA], tA);
        if (lane == 8) atomicAdd(&g_nsum[dB], tB);
    }
}

// ---- messages + tiled scatter (lane = j*8+q; one red.v4 per lane) ----
__global__ void k_msg(const int* __restrict__ ei, const __half* __restrict__ em_p) {
    int lane = threadIdx.x & 31;
    int q = lane & 7;
    int j = lane >> 3;
    int gw = (blockIdx.x * blockDim.x + threadIdx.x) >> 5;
    int nw = (gridDim.x * blockDim.x) >> 5;
    for (int g = gw; g < NG; g += nw) {
        float4 T = make_float4(0.f, 0.f, 0.f, 0.f);
#pragma unroll
        for (int c = 0; c < 4; c++) {
            int e = c * NG + g;
            int d = __ldg(ei + NE + e);
            float4 ex = ((const float4*)g_exp)[e];
            float inv = 1.f / (g_nsum[d] + 1e-8f);
            float exh = (j == 0) ? ex.x : (j == 1) ? ex.y : (j == 2) ? ex.z : ex.w;
            float sA = exh * inv;
            float4 xm = ld4h(g_xm + (size_t)d * 128 + lane * 4);
            float4 em = ld4h(em_p + (size_t)e * 32 + q * 4);
            T.x += sA * (xm.x + em.x);
            T.y += sA * (xm.y + em.y);
            T.z += sA * (xm.z + em.z);
            T.w += sA * (xm.w + em.w);
        }
        int tgt = __ldg(ei + NE + 4 * g + j);
        float* p = g_aggr + (size_t)tgt * 32 + q * 4;
        asm volatile("red.global.add.v4.f32 [%0], {%1,%2,%3,%4};"
                     :: "l"(p), "f"(T.x), "f"(T.y), "f"(T.z), "f"(T.w)
                     : "memory");
    }
}

extern "C" void kernel_launch(void* const* d_in, const int* in_sizes, int n_in,
                              void* d_out, int out_size) {
    const float* x      = (const float*)d_in[0];
    const float* eattr  = (const float*)d_in[1];
    const int*   ei     = (const int*)d_in[2];
    const float* atom_w = (const float*)d_in[3];
    const float* atom_b = (const float*)d_in[4];
    const float* asw  = (const float*)d_in[5];
    const float* asb  = (const float*)d_in[6];
    const float* adw  = (const float*)d_in[7];
    const float* adb  = (const float*)d_in[8];
    const float* aew  = (const float*)d_in[9];
    const float* aeb  = (const float*)d_in[10];
    const float* dotw = (const float*)d_in[11];
    const float* dotb = (const float*)d_in[12];
    const float* mdw  = (const float*)d_in[13];
    const float* mdb  = (const float*)d_in[14];
    const float* mew  = (const float*)d_in[15];
    const float* meb  = (const float*)d_in[16];
    const float* wnw  = (const float*)d_in[17];
    const float* wnb  = (const float*)d_in[18];
    float* out = (float*)d_out;

    float *p_h, *p_atom;
    __half *p_xs, *p_xd, *p_xm, *p_ea, *p_em, *p_ea2, *p_em2;
    cudaGetSymbolAddress((void**)&p_h,    g_h);
    cudaGetSymbolAddress((void**)&p_atom, g_atom);
    cudaGetSymbolAddress((void**)&p_xs,   g_xs);
    cudaGetSymbolAddress((void**)&p_xd,   g_xd);
    cudaGetSymbolAddress((void**)&p_xm,   g_xm);
    cudaGetSymbolAddress((void**)&p_ea,   g_ea);
    cudaGetSymbolAddress((void**)&p_em,   g_em);
    cudaGetSymbolAddress((void**)&p_ea2,  g_ea2);
    cudaGetSymbolAddress((void**)&p_em2,  g_em2);

    // smem = 2 * KK * PITCH * 4
    const int smem_atom = 2 * 64 * (4 * 32 + 8) * 4;    // 69632
    const int smem_e4   = 2 * 16 * (4 * 32 + 8) * 4;    // 17408
    const int smem_n3   = 2 * 16 * (3 * 32 + 8) * 4;    // 13312
    const int smem_c1   = 2 * 16 * (1 * 32 + 8) * 4;    // 5120
    cudaFuncSetAttribute(k_g<4, 8, 1, 0, 1>,
                         cudaFuncAttributeMaxDynamicSharedMemorySize, smem_atom);

    k_init<<<512, 256>>>();

    // atom: (50000 x 128) @ (128 x 128), relu, dual fp32 write g_atom/g_h
    {
        GArgs ga;
        ga.A = x; ga.M = NN; ga.Astride = 128; ga.Bstride = 128; ga.Ostride = 128;
        for (int m = 0; m < 4; m++) {
            ga.B[m]    = atom_w + m * 32;
            ga.bias[m] = atom_b + m * 32;
            ga.out[m]  = p_atom + m * 32;
            ga.out2[m] = p_h    + m * 32;
        }
        k_g<4, 8, 1, 0, 1><<<296, 256, smem_atom>>>(ga);
    }

    // elin both layers in ONE pass over eattr: ea0, em0, ea1, em1 (fp16 out)
    // MINB=1: NM=4 carries 64 accumulators; a 128-reg cap spills (R10 lesson)
    {
        GArgs ge;
        ge.A = eattr; ge.M = NE; ge.Astride = 32; ge.Bstride = 32; ge.Ostride = 32;
        ge.B[0] = aew;        ge.B[1] = mew;        ge.B[2] = aew + 1024; ge.B[3] = mew + 1024;
        ge.bias[0] = aeb;     ge.bias[1] = meb;     ge.bias[2] = aeb + 32; ge.bias[3] = meb + 32;
        ge.out[0] = p_ea; ge.out[1] = p_em; ge.out[2] = p_ea2; ge.out[3] = p_em2;
        for (int m = 0; m < 4; m++) ge.out2[m] = p_ea;
        k_g<4, 2, 0, 1, 1><<<444, 256, smem_e4>>>(ge);
    }

    for (int l = 0; l < 2; l++) {
        int wo = l * 32 * 32, bo = l * 32;
        const __half* ea_l = l ? p_ea2 : p_ea;
        const __half* em_l = l ? p_em2 : p_em;

        GArgs gn;
        gn.A = p_h; gn.M = ROWS; gn.Astride = 32; gn.Bstride = 32; gn.Ostride = 32;
        gn.B[0] = asw + wo; gn.B[1] = adw + wo; gn.B[2] = mdw + wo; gn.B[3] = asw + wo;
        gn.bias[0] = asb + bo; gn.bias[1] = adb + bo; gn.bias[2] = mdb + bo; gn.bias[3] = asb + bo;
        gn.out[0] = p_xs; gn.out[1] = p_xd; gn.out[2] = p_xm; gn.out[3] = p_xs;
        for (int m = 0; m < 4; m++) gn.out2[m] = p_xs;
        k_nlin<2><<<444 + 49, 256, smem_n3>>>(gn, l);   // trailing blocks zero nsum (l=1)

        k_attn<<<1184, 256>>>(ei, ea_l, dotw + l * 32, dotb + l);
        k_msg<<<1184, 256>>>(ei, em_l);

        GArgs gc;
        gc.A = p_h; gc.M = ROWS; gc.Astride = 32; gc.Bstride = 32; gc.Ostride = 32;
        gc.B[0] = wnw + wo; gc.B[1] = wnw + wo; gc.B[2] = wnw + wo; gc.B[3] = wnw + wo;
        gc.bias[0] = wnb + bo; gc.bias[1] = wnb + bo; gc.bias[2] = wnb + bo; gc.bias[3] = wnb + bo;
        gc.out2[0] = gc.out2[1] = gc.out2[2] = gc.out2[3] = p_h;
        if (l == 0) {
            gc.out[0] = p_h; gc.out[1] = p_h; gc.out[2] = p_h; gc.out[3] = p_h;
            k_g<1, 2, 2, 0, 2><<<444, 256, smem_c1>>>(gc);   // re-zeroes aggr
        } else {
            gc.out[0] = out; gc.out[1] = out; gc.out[2] = out; gc.out[3] = out;
            k_g<1, 2, 3, 0, 2><<<444, 256, smem_c1>>>(gc);
        }
    }
}

// round 12
// speedup vs baseline: 1.3490x; 1.2807x over previous
#include <cuda_runtime.h>
#include <cuda_fp16.h>
#include <cstdint>

#define FULL 0xffffffffu

constexpr int NN   = 50000;
constexpr int NE   = 400000;
constexpr int F    = 32;
constexpr int H    = 4;
constexpr int ROWS = NN * H;        // 200000 (n,h) rows
constexpr int NG   = NE / H;        // 100000 message groups

// ---- scratch (device globals; no allocation allowed) ----
__device__ float    g_h[ROWS * F];
__device__ float    g_atom[ROWS * F];
__device__ __half   g_xs[ROWS * F];
__device__ __half   g_xd[ROWS * F];
__device__ __half   g_xm[ROWS * F];
__device__ __half   g_ea[NE * F];       // layer 0
__device__ __half   g_em[NE * F];
__device__ __half   g_ea2[NE * F];      // layer 1
__device__ __half   g_em2[NE * F];
__device__ float    g_exp[NE * H];
__device__ float    g_nsum[NN];
__device__ float    g_aggr[ROWS * F];

__device__ __forceinline__ void mma16(float d[4], const uint32_t a[4],
                                      uint32_t b0, uint32_t b1) {
    asm("mma.sync.aligned.m16n8k16.row.col.f32.f16.f16.f32 "
        "{%0,%1,%2,%3}, {%4,%5,%6,%7}, {%8,%9}, {%0,%1,%2,%3};"
        : "+f"(d[0]), "+f"(d[1]), "+f"(d[2]), "+f"(d[3])
        : "r"(a[0]), "r"(a[1]), "r"(a[2]), "r"(a[3]), "r"(b0), "r"(b1));
}

// split fp32 pair -> fp16 hi + fp16 residual lo (packed half2 as u32)
__device__ __forceinline__ void splitH(float x, float y,
                                       uint32_t& hi, uint32_t& lo) {
    __half2 h = __floats2half2_rn(x, y);
    float2 hf = __half22float2(h);
    __half2 l = __floats2half2_rn(x - hf.x, y - hf.y);
    hi = *(uint32_t*)&h;
    lo = *(uint32_t*)&l;
}

struct GArgs {
    const float* A;
    const float* B[4];
    const float* bias[4];
    void*        out[4];
    void*        out2[4];
    int          M;
    int          Astride;
    int          Bstride;
    int          Ostride;
};

// ============================================================================
// gemm_body: out[m] = A @ B[m] + bias[m], K = KC16*16, N = 32/matrix.
// split-fp16 2-term scheme (AhiBhi + AhiBlo + AloBhi), smem-staged B.
// MODE 0 plain; MODE 1 relu + dual write; MODE 2 comb epilogue
// (+g_aggr +g_atom, relu); MODE 3 = comb + head-mean into ga.out[0].
// OUTH: store fp16.
// ============================================================================
template<int NM, int KC16, int MODE, int OUTH>
__device__ __forceinline__ void gemm_body(const GArgs& ga, uint32_t* sB,
                                          int bid, int nblocks, int tid) {
    constexpr int NT = NM * 4;
    constexpr int PITCH = NM * 32 + 8;   // % 32 == 8 -> conflict-free
    constexpr int KK = KC16 * 8;         // half2 k-rows
    uint32_t* sH = sB;
    uint32_t* sL = sB + KK * PITCH;

    for (int m = 0; m < NM; m++) {
        const float* Bp = ga.B[m];
        for (int i = tid; i < KK * 32; i += 256) {
            int kk = i >> 5, n = i & 31;
            float v0 = Bp[(size_t)(2 * kk)     * ga.Bstride + n];
            float v1 = Bp[(size_t)(2 * kk + 1) * ga.Bstride + n];
            uint32_t hi, lo;
            splitH(v0, v1, hi, lo);
            sH[kk * PITCH + m * 32 + n] = hi;
            sL[kk * PITCH + m * 32 + n] = lo;
        }
    }
    __syncthreads();

    int lane = tid & 31;
    int gid = lane >> 2, tig = lane & 3;
    int gw = bid * 8 + (tid >> 5);
    int nw = nblocks * 8;
    int ntile = ga.M >> 4;
    const int As = ga.Astride;

    for (int t = gw; t < ntile; t += nw) {
        const float* Ap = ga.A + (size_t)(t * 16) * As;
        float d[NT][4];
#pragma unroll
        for (int nt = 0; nt < NT; nt++) {
            d[nt][0] = 0.f; d[nt][1] = 0.f; d[nt][2] = 0.f; d[nt][3] = 0.f;
        }
#pragma unroll 2
        for (int kc = 0; kc < KC16; kc++) {
            float2 p0 = *(const float2*)(Ap + (size_t)gid * As + kc * 16 + 2 * tig);
            float2 p1 = *(const float2*)(Ap + (size_t)(gid + 8) * As + kc * 16 + 2 * tig);
            float2 p2 = *(const float2*)(Ap + (size_t)gid * As + kc * 16 + 2 * tig + 8);
            float2 p3 = *(const float2*)(Ap + (size_t)(gid + 8) * As + kc * 16 + 2 * tig + 8);
            uint32_t ah[4], al[4];
            splitH(p0.x, p0.y, ah[0], al[0]);
            splitH(p1.x, p1.y, ah[1], al[1]);
            splitH(p2.x, p2.y, ah[2], al[2]);
            splitH(p3.x, p3.y, ah[3], al[3]);
            int krow = (kc * 8 + tig) * PITCH + gid;
#pragma unroll
            for (int nt = 0; nt < NT; nt++) {
                int i0 = krow + nt * 8;
                uint32_t bh0 = sH[i0], bh1 = sH[i0 + 4 * PITCH];
                uint32_t bl0 = sL[i0], bl1 = sL[i0 + 4 * PITCH];
                mma16(d[nt], ah, bh0, bh1);
                mma16(d[nt], ah, bl0, bl1);
                mma16(d[nt], al, bh0, bh1);
            }
        }
        int ra = t * 16 + gid, rb = ra + 8;
#pragma unroll
        for (int nt = 0; nt < NT; nt++) {
            const int m = nt >> 2;
            int c = (nt & 3) * 8 + 2 * tig;
            float b0 = ga.bias[m][c], b1 = ga.bias[m][c + 1];
            float o0 = d[nt][0] + b0, o1 = d[nt][1] + b1;
            float o2 = d[nt][2] + b0, o3 = d[nt][3] + b1;
            if (MODE >= 2) {
                int ia = ra * 32 + c, ib = rb * 32 + c;
                o0 += g_aggr[ia]     + g_atom[ia];
                o1 += g_aggr[ia + 1] + g_atom[ia + 1];
                o2 += g_aggr[ib]     + g_atom[ib];
                o3 += g_aggr[ib + 1] + g_atom[ib + 1];
            }
            if (MODE != 0) {
                o0 = fmaxf(o0, 0.f); o1 = fmaxf(o1, 0.f);
                o2 = fmaxf(o2, 0.f); o3 = fmaxf(o3, 0.f);
            }
            if (MODE == 3) {
                // head-mean: 4 consecutive rows = 4 heads of one node.
                float s0 = o0 + __shfl_xor_sync(FULL, o0, 4);
                s0 += __shfl_xor_sync(FULL, s0, 8);
                float s1 = o1 + __shfl_xor_sync(FULL, o1, 4);
                s1 += __shfl_xor_sync(FULL, s1, 8);
                float s2 = o2 + __shfl_xor_sync(FULL, o2, 4);
                s2 += __shfl_xor_sync(FULL, s2, 8);
                float s3 = o3 + __shfl_xor_sync(FULL, o3, 4);
                s3 += __shfl_xor_sync(FULL, s3, 8);
                if ((gid & 3) == 0) {
                    float* op = (float*)ga.out[0];
                    int na = ra >> 2;
                    int nb = rb >> 2;
                    *(float2*)&op[na * 32 + c] = make_float2(0.25f*s0, 0.25f*s1);
                    *(float2*)&op[nb * 32 + c] = make_float2(0.25f*s2, 0.25f*s3);
                }
                continue;
            }
            size_t ia = (size_t)ra * ga.Ostride + c;
            size_t ib = (size_t)rb * ga.Ostride + c;
            if (OUTH) {
                __half* op = (__half*)ga.out[m];
                *(__half2*)&op[ia] = __floats2half2_rn(o0, o1);
                *(__half2*)&op[ib] = __floats2half2_rn(o2, o3);
            } else {
                float* op = (float*)ga.out[m];
                *(float2*)&op[ia] = make_float2(o0, o1);
                *(float2*)&op[ib] = make_float2(o2, o3);
                if (MODE == 1) {
                    float* op2 = (float*)ga.out2[m];
                    *(float2*)&op2[ia] = make_float2(o0, o1);
                    *(float2*)&op2[ib] = make_float2(o2, o3);
                }
            }
        }
    }
}

template<int NM, int KC16, int MODE, int OUTH>
__global__ void __launch_bounds__(256) k_g(GArgs ga) {
    extern __shared__ uint32_t sB[];
    gemm_body<NM, KC16, MODE, OUTH>(ga, sB, blockIdx.x, gridDim.x, threadIdx.x);
}

// ---- zero aggr/nsum (per layer) ----
__global__ void k_init() {
    int i = blockIdx.x * blockDim.x + threadIdx.x;
    int stride = gridDim.x * blockDim.x;
    for (int j = i; j < ROWS * F / 4; j += stride)
        ((float4*)g_aggr)[j] = make_float4(0.f, 0.f, 0.f, 0.f);
    for (int j = i; j < NN; j += stride)
        g_nsum[j] = 0.f;
}

__device__ __forceinline__ float4 ld4h(const __half* p) {
    uint2 u = *(const uint2*)p;
    float2 lo = __half22float2(*(__half2*)&u.x);
    float2 hi = __half22float2(*(__half2*)&u.y);
    return make_float4(lo.x, lo.y, hi.x, hi.y);
}

// ---- edge attention: scores -> exp -> segment sum, fused; 2-edge unroll ----
__global__ void k_attn(const int* __restrict__ ei, const __half* __restrict__ ea_p,
                       const float* __restrict__ dw, const float* __restrict__ db) {
    int lane = threadIdx.x & 31;
    int q = lane & 7;
    float4 dw4 = ((const float4*)dw)[q];
    float dbv = db[0];
    int gw = (blockIdx.x * blockDim.x + threadIdx.x) >> 5;
    int nw = (gridDim.x * blockDim.x) >> 5;
    for (int e0 = gw * 2; e0 < NE; e0 += nw * 2) {
        int sA = __ldg(ei + e0),     dA = __ldg(ei + NE + e0);
        int sB = __ldg(ei + e0 + 1), dB = __ldg(ei + NE + e0 + 1);
        float4 aA  = ld4h(g_xs + (size_t)dA * 128 + lane * 4);
        float4 cA  = ld4h(g_xd + (size_t)sA * 128 + lane * 4);
        float4 eA  = ld4h(ea_p + (size_t)e0 * 32 + q * 4);
        float4 aB  = ld4h(g_xs + (size_t)dB * 128 + lane * 4);
        float4 cB  = ld4h(g_xd + (size_t)sB * 128 + lane * 4);
        float4 eB  = ld4h(ea_p + (size_t)(e0 + 1) * 32 + q * 4);
        float vA = fmaxf(aA.x + cA.x + eA.x, 0.f) * dw4.x
                 + fmaxf(aA.y + cA.y + eA.y, 0.f) * dw4.y
                 + fmaxf(aA.z + cA.z + eA.z, 0.f) * dw4.z
                 + fmaxf(aA.w + cA.w + eA.w, 0.f) * dw4.w;
        float vB = fmaxf(aB.x + cB.x + eB.x, 0.f) * dw4.x
                 + fmaxf(aB.y + cB.y + eB.y, 0.f) * dw4.y
                 + fmaxf(aB.z + cB.z + eB.z, 0.f) * dw4.z
                 + fmaxf(aB.w + cB.w + eB.w, 0.f) * dw4.w;
        vA += __shfl_xor_sync(FULL, vA, 4);
        vB += __shfl_xor_sync(FULL, vB, 4);
        vA += __shfl_xor_sync(FULL, vA, 2);
        vB += __shfl_xor_sync(FULL, vB, 2);
        vA += __shfl_xor_sync(FULL, vA, 1);
        vB += __shfl_xor_sync(FULL, vB, 1);
        float arA = __shfl_sync(FULL, vA, (lane & 3) * 8) + dbv;
        float arB = __shfl_sync(FULL, vB, (lane & 3) * 8) + dbv;
        float exA = __expf(arA);
        float exB = __expf(arB);
        float tA = exA + __shfl_xor_sync(FULL, exA, 1);
        float tB = exB + __shfl_xor_sync(FULL, exB, 1);
        tA += __shfl_xor_sync(FULL, tA, 2);
        tB += __shfl_xor_sync(FULL, tB, 2);
        if (lane < 4) g_exp[e0 * 4 + lane] = exA;
        else if (lane < 8) g_exp[(e0 + 1) * 4 + (lane & 3)] = exB;
        if (lane == 0) atomicAdd(&g_nsum[dA], tA);
        if (lane == 8) atomicAdd(&g_nsum[dB], tB);
    }
}

// ---- messages + tiled scatter; 2-group unroll for MLP ----
// lane = j*8+q: head j, feature chunk q. One red.v4 per lane per group.
__global__ void k_msg(const int* __restrict__ ei, const __half* __restrict__ em_p) {
    int lane = threadIdx.x & 31;
    int q = lane & 7;
    int j = lane >> 3;
    int gw = (blockIdx.x * blockDim.x + threadIdx.x) >> 5;
    int nw = (gridDim.x * blockDim.x) >> 5;
    for (int g0 = gw * 2; g0 < NG; g0 += nw * 2) {   // NG even
        int g1 = g0 + 1;
        float4 T0 = make_float4(0.f, 0.f, 0.f, 0.f);
        float4 T1 = make_float4(0.f, 0.f, 0.f, 0.f);
#pragma unroll
        for (int c = 0; c < 4; c++) {
            int e0 = c * NG + g0;
            int e1 = c * NG + g1;
            int d0 = __ldg(ei + NE + e0);
            int d1 = __ldg(ei + NE + e1);
            float4 ex0 = ((const float4*)g_exp)[e0];
            float4 ex1 = ((const float4*)g_exp)[e1];
            float inv0 = 1.f / (g_nsum[d0] + 1e-8f);
            float inv1 = 1.f / (g_nsum[d1] + 1e-8f);
            float eh0 = (j == 0) ? ex0.x : (j == 1) ? ex0.y : (j == 2) ? ex0.z : ex0.w;
            float eh1 = (j == 0) ? ex1.x : (j == 1) ? ex1.y : (j == 2) ? ex1.z : ex1.w;
            float s0 = eh0 * inv0;
            float s1 = eh1 * inv1;
            float4 xm0 = ld4h(g_xm + (size_t)d0 * 128 + lane * 4);
            float4 xm1 = ld4h(g_xm + (size_t)d1 * 128 + lane * 4);
            float4 em0 = ld4h(em_p + (size_t)e0 * 32 + q * 4);
            float4 em1 = ld4h(em_p + (size_t)e1 * 32 + q * 4);
            T0.x += s0 * (xm0.x + em0.x);
            T0.y += s0 * (xm0.y + em0.y);
            T0.z += s0 * (xm0.z + em0.z);
            T0.w += s0 * (xm0.w + em0.w);
            T1.x += s1 * (xm1.x + em1.x);
            T1.y += s1 * (xm1.y + em1.y);
            T1.z += s1 * (xm1.z + em1.z);
            T1.w += s1 * (xm1.w + em1.w);
        }
        int tgt0 = __ldg(ei + NE + 4 * g0 + j);
        int tgt1 = __ldg(ei + NE + 4 * g1 + j);
        float* p0 = g_aggr + (size_t)tgt0 * 32 + q * 4;
        float* p1 = g_aggr + (size_t)tgt1 * 32 + q * 4;
        asm volatile("red.global.add.v4.f32 [%0], {%1,%2,%3,%4};"
                     :: "l"(p0), "f"(T0.x), "f"(T0.y), "f"(T0.z), "f"(T0.w)
                     : "memory");
        asm volatile("red.global.add.v4.f32 [%0], {%1,%2,%3,%4};"
                     :: "l"(p1), "f"(T1.x), "f"(T1.y), "f"(T1.z), "f"(T1.w)
                     : "memory");
    }
}

extern "C" void kernel_launch(void* const* d_in, const int* in_sizes, int n_in,
                              void* d_out, int out_size) {
    const float* x      = (const float*)d_in[0];
    const float* eattr  = (const float*)d_in[1];
    const int*   ei     = (const int*)d_in[2];
    const float* atom_w = (const float*)d_in[3];
    const float* atom_b = (const float*)d_in[4];
    const float* asw  = (const float*)d_in[5];
    const float* asb  = (const float*)d_in[6];
    const float* adw  = (const float*)d_in[7];
    const float* adb  = (const float*)d_in[8];
    const float* aew  = (const float*)d_in[9];
    const float* aeb  = (const float*)d_in[10];
    const float* dotw = (const float*)d_in[11];
    const float* dotb = (const float*)d_in[12];
    const float* mdw  = (const float*)d_in[13];
    const float* mdb  = (const float*)d_in[14];
    const float* mew  = (const float*)d_in[15];
    const float* meb  = (const float*)d_in[16];
    const float* wnw  = (const float*)d_in[17];
    const float* wnb  = (const float*)d_in[18];
    float* out = (float*)d_out;

    float *p_h, *p_atom;
    __half *p_xs, *p_xd, *p_xm, *p_ea, *p_em, *p_ea2, *p_em2;
    cudaGetSymbolAddress((void**)&p_h,    g_h);
    cudaGetSymbolAddress((void**)&p_atom, g_atom);
    cudaGetSymbolAddress((void**)&p_xs,   g_xs);
    cudaGetSymbolAddress((void**)&p_xd,   g_xd);
    cudaGetSymbolAddress((void**)&p_xm,   g_xm);
    cudaGetSymbolAddress((void**)&p_ea,   g_ea);
    cudaGetSymbolAddress((void**)&p_em,   g_em);
    cudaGetSymbolAddress((void**)&p_ea2,  g_ea2);
    cudaGetSymbolAddress((void**)&p_em2,  g_em2);

    // smem = 2 * KK * PITCH * 4
    const int smem_atom = 2 * 64 * (4 * 32 + 8) * 4;    // 69632
    const int smem_e4   = 2 * 16 * (4 * 32 + 8) * 4;    // 17408
    const int smem_n3   = 2 * 16 * (3 * 32 + 8) * 4;    // 13312
    const int smem_c1   = 2 * 16 * (1 * 32 + 8) * 4;    // 5120
    cudaFuncSetAttribute(k_g<4, 8, 1, 0>,
                         cudaFuncAttributeMaxDynamicSharedMemorySize, smem_atom);

    // atom: (50000 x 128) @ (128 x 128), relu, dual fp32 write g_atom/g_h
    {
        GArgs ga;
        ga.A = x; ga.M = NN; ga.Astride = 128; ga.Bstride = 128; ga.Ostride = 128;
        for (int m = 0; m < 4; m++) {
            ga.B[m]    = atom_w + m * 32;
            ga.bias[m] = atom_b + m * 32;
            ga.out[m]  = p_atom + m * 32;
            ga.out2[m] = p_h    + m * 32;
        }
        k_g<4, 8, 1, 0><<<296, 256, smem_atom>>>(ga);
    }

    // elin both layers in ONE pass over eattr: ea0, em0, ea1, em1 (fp16 out)
    {
        GArgs ge;
        ge.A = eattr; ge.M = NE; ge.Astride = 32; ge.Bstride = 32; ge.Ostride = 32;
        ge.B[0] = aew;        ge.B[1] = mew;        ge.B[2] = aew + 1024; ge.B[3] = mew + 1024;
        ge.bias[0] = aeb;     ge.bias[1] = meb;     ge.bias[2] = aeb + 32; ge.bias[3] = meb + 32;
        ge.out[0] = p_ea; ge.out[1] = p_em; ge.out[2] = p_ea2; ge.out[3] = p_em2;
        for (int m = 0; m < 4; m++) ge.out2[m] = p_ea;
        k_g<4, 2, 0, 1><<<444, 256, smem_e4>>>(ge);
    }

    for (int l = 0; l < 2; l++) {
        int wo = l * 32 * 32, bo = l * 32;
        const __half* ea_l = l ? p_ea2 : p_ea;
        const __half* em_l = l ? p_em2 : p_em;

        k_init<<<512, 256>>>();

        GArgs gn;
        gn.A = p_h; gn.M = ROWS; gn.Astride = 32; gn.Bstride = 32; gn.Ostride = 32;
        gn.B[0] = asw + wo; gn.B[1] = adw + wo; gn.B[2] = mdw + wo; gn.B[3] = asw + wo;
        gn.bias[0] = asb + bo; gn.bias[1] = adb + bo; gn.bias[2] = mdb + bo; gn.bias[3] = asb + bo;
        gn.out[0] = p_xs; gn.out[1] = p_xd; gn.out[2] = p_xm; gn.out[3] = p_xs;
        for (int m = 0; m < 4; m++) gn.out2[m] = p_xs;
        k_g<3, 2, 0, 1><<<444, 256, smem_n3>>>(gn);

        k_attn<<<740, 256>>>(ei, ea_l, dotw + l * 32, dotb + l);
        k_msg<<<740, 256>>>(ei, em_l);

        GArgs gc;
        gc.A = p_h; gc.M = ROWS; gc.Astride = 32; gc.Bstride = 32; gc.Ostride = 32;
        gc.B[0] = wnw + wo; gc.B[1] = wnw + wo; gc.B[2] = wnw + wo; gc.B[3] = wnw + wo;
        gc.bias[0] = wnb + bo; gc.bias[1] = wnb + bo; gc.bias[2] = wnb + bo; gc.bias[3] = wnb + bo;
        gc.out2[0] = gc.out2[1] = gc.out2[2] = gc.out2[3] = p_h;
        if (l == 0) {
            gc.out[0] = p_h; gc.out[1] = p_h; gc.out[2] = p_h; gc.out[3] = p_h;
            k_g<1, 2, 2, 0><<<444, 256, smem_c1>>>(gc);
        } else {
            gc.out[0] = out; gc.out[1] = out; gc.out[2] = out; gc.out[3] = out;
            k_g<1, 2, 3, 0><<<444, 256, smem_c1>>>(gc);
        }
    }
}

// round 13
// speedup vs baseline: 1.3619x; 1.0095x over previous
#include <cuda_runtime.h>
#include <cuda_fp16.h>
#include <cstdint>

#define FULL 0xffffffffu

constexpr int NN   = 50000;
constexpr int NE   = 400000;
constexpr int F    = 32;
constexpr int H    = 4;
constexpr int ROWS = NN * H;        // 200000 (n,h) rows
constexpr int NG   = NE / H;        // 100000 message groups

// ---- scratch (device globals; no allocation allowed) ----
__device__ float    g_h[ROWS * F];
__device__ float    g_atom[ROWS * F];
__device__ __half   g_xs[ROWS * F];
__device__ __half   g_xd[ROWS * F];
__device__ __half   g_xm[ROWS * F];
__device__ __half   g_ea[NE * F];       // layer 0
__device__ __half   g_em[NE * F];
__device__ __half   g_ea2[NE * F];      // layer 1
__device__ __half   g_em2[NE * F];
__device__ float    g_exp[NE * H];
__device__ float    g_nsum[NN];
__device__ float    g_aggr[ROWS * F];

__device__ __forceinline__ void mma16(float d[4], const uint32_t a[4],
                                      uint32_t b0, uint32_t b1) {
    asm("mma.sync.aligned.m16n8k16.row.col.f32.f16.f16.f32 "
        "{%0,%1,%2,%3}, {%4,%5,%6,%7}, {%8,%9}, {%0,%1,%2,%3};"
        : "+f"(d[0]), "+f"(d[1]), "+f"(d[2]), "+f"(d[3])
        : "r"(a[0]), "r"(a[1]), "r"(a[2]), "r"(a[3]), "r"(b0), "r"(b1));
}

// split fp32 pair -> fp16 hi + fp16 residual lo (packed half2 as u32)
__device__ __forceinline__ void splitH(float x, float y,
                                       uint32_t& hi, uint32_t& lo) {
    __half2 h = __floats2half2_rn(x, y);
    float2 hf = __half22float2(h);
    __half2 l = __floats2half2_rn(x - hf.x, y - hf.y);
    hi = *(uint32_t*)&h;
    lo = *(uint32_t*)&l;
}

struct GArgs {
    const float* A;
    const float* B[4];
    const float* bias[4];
    void*        out[4];
    void*        out2[4];
    int          M;
    int          Astride;
    int          Bstride;
    int          Ostride;
};

// ============================================================================
// gemm_body: out[m] = A @ B[m] + bias[m], K = KC16*16, N = 32/matrix.
// split-fp16 2-term scheme (AhiBhi + AhiBlo + AloBhi), smem-staged B.
// MODE 0 plain; MODE 1 relu + dual write; MODE 2 comb epilogue
// (+g_aggr +g_atom, relu); MODE 3 = comb + head-mean into ga.out[0].
// OUTH: store fp16.
// ============================================================================
template<int NM, int KC16, int MODE, int OUTH>
__device__ __forceinline__ void gemm_body(const GArgs& ga, uint32_t* sB,
                                          int bid, int nblocks, int tid) {
    constexpr int NT = NM * 4;
    constexpr int PITCH = NM * 32 + 8;   // % 32 == 8 -> conflict-free
    constexpr int KK = KC16 * 8;         // half2 k-rows
    uint32_t* sH = sB;
    uint32_t* sL = sB + KK * PITCH;

    for (int m = 0; m < NM; m++) {
        const float* Bp = ga.B[m];
        for (int i = tid; i < KK * 32; i += 256) {
            int kk = i >> 5, n = i & 31;
            float v0 = Bp[(size_t)(2 * kk)     * ga.Bstride + n];
            float v1 = Bp[(size_t)(2 * kk + 1) * ga.Bstride + n];
            uint32_t hi, lo;
            splitH(v0, v1, hi, lo);
            sH[kk * PITCH + m * 32 + n] = hi;
            sL[kk * PITCH + m * 32 + n] = lo;
        }
    }
    __syncthreads();

    int lane = tid & 31;
    int gid = lane >> 2, tig = lane & 3;
    int gw = bid * 8 + (tid >> 5);
    int nw = nblocks * 8;
    int ntile = ga.M >> 4;
    const int As = ga.Astride;

    for (int t = gw; t < ntile; t += nw) {
        const float* Ap = ga.A + (size_t)(t * 16) * As;
        float d[NT][4];
#pragma unroll
        for (int nt = 0; nt < NT; nt++) {
            d[nt][0] = 0.f; d[nt][1] = 0.f; d[nt][2] = 0.f; d[nt][3] = 0.f;
        }
#pragma unroll 2
        for (int kc = 0; kc < KC16; kc++) {
            float2 p0 = *(const float2*)(Ap + (size_t)gid * As + kc * 16 + 2 * tig);
            float2 p1 = *(const float2*)(Ap + (size_t)(gid + 8) * As + kc * 16 + 2 * tig);
            float2 p2 = *(const float2*)(Ap + (size_t)gid * As + kc * 16 + 2 * tig + 8);
            float2 p3 = *(const float2*)(Ap + (size_t)(gid + 8) * As + kc * 16 + 2 * tig + 8);
            uint32_t ah[4], al[4];
            splitH(p0.x, p0.y, ah[0], al[0]);
            splitH(p1.x, p1.y, ah[1], al[1]);
            splitH(p2.x, p2.y, ah[2], al[2]);
            splitH(p3.x, p3.y, ah[3], al[3]);
            int krow = (kc * 8 + tig) * PITCH + gid;
#pragma unroll
            for (int nt = 0; nt < NT; nt++) {
                int i0 = krow + nt * 8;
                uint32_t bh0 = sH[i0], bh1 = sH[i0 + 4 * PITCH];
                uint32_t bl0 = sL[i0], bl1 = sL[i0 + 4 * PITCH];
                mma16(d[nt], ah, bh0, bh1);
                mma16(d[nt], ah, bl0, bl1);
                mma16(d[nt], al, bh0, bh1);
            }
        }
        int ra = t * 16 + gid, rb = ra + 8;
#pragma unroll
        for (int nt = 0; nt < NT; nt++) {
            const int m = nt >> 2;
            int c = (nt & 3) * 8 + 2 * tig;
            float b0 = ga.bias[m][c], b1 = ga.bias[m][c + 1];
            float o0 = d[nt][0] + b0, o1 = d[nt][1] + b1;
            float o2 = d[nt][2] + b0, o3 = d[nt][3] + b1;
            if (MODE >= 2) {
                int ia = ra * 32 + c, ib = rb * 32 + c;
                o0 += g_aggr[ia]     + g_atom[ia];
                o1 += g_aggr[ia + 1] + g_atom[ia + 1];
                o2 += g_aggr[ib]     + g_atom[ib];
                o3 += g_aggr[ib + 1] + g_atom[ib + 1];
            }
            if (MODE != 0) {
                o0 = fmaxf(o0, 0.f); o1 = fmaxf(o1, 0.f);
                o2 = fmaxf(o2, 0.f); o3 = fmaxf(o3, 0.f);
            }
            if (MODE == 3) {
                // head-mean: 4 consecutive rows = 4 heads of one node.
                float s0 = o0 + __shfl_xor_sync(FULL, o0, 4);
                s0 += __shfl_xor_sync(FULL, s0, 8);
                float s1 = o1 + __shfl_xor_sync(FULL, o1, 4);
                s1 += __shfl_xor_sync(FULL, s1, 8);
                float s2 = o2 + __shfl_xor_sync(FULL, o2, 4);
                s2 += __shfl_xor_sync(FULL, s2, 8);
                float s3 = o3 + __shfl_xor_sync(FULL, o3, 4);
                s3 += __shfl_xor_sync(FULL, s3, 8);
                if ((gid & 3) == 0) {
                    float* op = (float*)ga.out[0];
                    int na = ra >> 2;
                    int nb = rb >> 2;
                    *(float2*)&op[na * 32 + c] = make_float2(0.25f*s0, 0.25f*s1);
                    *(float2*)&op[nb * 32 + c] = make_float2(0.25f*s2, 0.25f*s3);
                }
                continue;
            }
            size_t ia = (size_t)ra * ga.Ostride + c;
            size_t ib = (size_t)rb * ga.Ostride + c;
            if (OUTH) {
                __half* op = (__half*)ga.out[m];
                *(__half2*)&op[ia] = __floats2half2_rn(o0, o1);
                *(__half2*)&op[ib] = __floats2half2_rn(o2, o3);
            } else {
                float* op = (float*)ga.out[m];
                *(float2*)&op[ia] = make_float2(o0, o1);
                *(float2*)&op[ib] = make_float2(o2, o3);
                if (MODE == 1) {
                    float* op2 = (float*)ga.out2[m];
                    *(float2*)&op2[ia] = make_float2(o0, o1);
                    *(float2*)&op2[ib] = make_float2(o2, o3);
                }
            }
        }
    }
}

template<int NM, int KC16, int MODE, int OUTH>
__global__ void __launch_bounds__(256) k_g(GArgs ga) {
    extern __shared__ uint32_t sB[];
    gemm_body<NM, KC16, MODE, OUTH>(ga, sB, blockIdx.x, gridDim.x, threadIdx.x);
}

// ---- zero aggr/nsum (per layer) ----
__global__ void k_init() {
    int i = blockIdx.x * blockDim.x + threadIdx.x;
    int stride = gridDim.x * blockDim.x;
    for (int j = i; j < ROWS * F / 4; j += stride)
        ((float4*)g_aggr)[j] = make_float4(0.f, 0.f, 0.f, 0.f);
    for (int j = i; j < NN; j += stride)
        g_nsum[j] = 0.f;
}

__device__ __forceinline__ float4 ld4h(const __half* p) {
    uint2 u = *(const uint2*)p;
    float2 lo = __half22float2(*(__half2*)&u.x);
    float2 hi = __half22float2(*(__half2*)&u.y);
    return make_float4(lo.x, lo.y, hi.x, hi.y);
}

// ---- edge attention: scores -> exp -> segment sum, fused; 4-edge unroll ----
// warp handles edges e0..e0+3; lane = h*8+q covers head h, chunk q.
__global__ void k_attn(const int* __restrict__ ei, const __half* __restrict__ ea_p,
                       const float* __restrict__ dw, const float* __restrict__ db) {
    int lane = threadIdx.x & 31;
    int q = lane & 7;
    float4 dw4 = ((const float4*)dw)[q];
    float dbv = db[0];
    int gw = (blockIdx.x * blockDim.x + threadIdx.x) >> 5;
    int nw = (gridDim.x * blockDim.x) >> 5;
    for (int e0 = gw * 4; e0 < NE; e0 += nw * 4) {   // NE % 4 == 0
        int s[4], dd[4];
#pragma unroll
        for (int k = 0; k < 4; k++) {
            s[k]  = __ldg(ei + e0 + k);
            dd[k] = __ldg(ei + NE + e0 + k);
        }
        float v[4];
#pragma unroll
        for (int k = 0; k < 4; k++) {
            float4 a  = ld4h(g_xs + (size_t)dd[k] * 128 + lane * 4);
            float4 c  = ld4h(g_xd + (size_t)s[k]  * 128 + lane * 4);
            float4 ea = ld4h(ea_p + (size_t)(e0 + k) * 32 + q * 4);
            v[k] = fmaxf(a.x + c.x + ea.x, 0.f) * dw4.x
                 + fmaxf(a.y + c.y + ea.y, 0.f) * dw4.y
                 + fmaxf(a.z + c.z + ea.z, 0.f) * dw4.z
                 + fmaxf(a.w + c.w + ea.w, 0.f) * dw4.w;
        }
#pragma unroll
        for (int k = 0; k < 4; k++) {
            v[k] += __shfl_xor_sync(FULL, v[k], 4);
            v[k] += __shfl_xor_sync(FULL, v[k], 2);
            v[k] += __shfl_xor_sync(FULL, v[k], 1);
        }
        // per edge k: all lanes fetch head (lane&3) score, exponentiate, and
        // reduce within each aligned 4-lane group -> every group holds total.
        float ex[4], tt[4];
#pragma unroll
        for (int k = 0; k < 4; k++) {
            float ar = __shfl_sync(FULL, v[k], (lane & 3) * 8) + dbv;
            ex[k] = __expf(ar);
            float t = ex[k] + __shfl_xor_sync(FULL, ex[k], 1);
            t += __shfl_xor_sync(FULL, t, 2);
            tt[k] = t;
        }
        // lane group [4k,4k+4) stores edge k's 4 exps; lane 4k does the atomic
        int kk = lane >> 2;
        if (kk < 4) {
            g_exp[(e0 + kk) * 4 + (lane & 3)] = ex[kk];
            if ((lane & 3) == 0)
                atomicAdd(&g_nsum[dd[kk]], tt[kk]);
        }
    }
}

// ---- messages + tiled scatter; 2-group unroll for MLP ----
// lane = j*8+q: head j, feature chunk q. One red.v4 per lane per group.
__global__ void k_msg(const int* __restrict__ ei, const __half* __restrict__ em_p) {
    int lane = threadIdx.x & 31;
    int q = lane & 7;
    int j = lane >> 3;
    int gw = (blockIdx.x * blockDim.x + threadIdx.x) >> 5;
    int nw = (gridDim.x * blockDim.x) >> 5;
    for (int g0 = gw * 2; g0 < NG; g0 += nw * 2) {   // NG even
        int g1 = g0 + 1;
        float4 T0 = make_float4(0.f, 0.f, 0.f, 0.f);
        float4 T1 = make_float4(0.f, 0.f, 0.f, 0.f);
#pragma unroll
        for (int c = 0; c < 4; c++) {
            int e0 = c * NG + g0;
            int e1 = c * NG + g1;
            int d0 = __ldg(ei + NE + e0);
            int d1 = __ldg(ei + NE + e1);
            float4 ex0 = ((const float4*)g_exp)[e0];
            float4 ex1 = ((const float4*)g_exp)[e1];
            float inv0 = 1.f / (g_nsum[d0] + 1e-8f);
            float inv1 = 1.f / (g_nsum[d1] + 1e-8f);
            float eh0 = (j == 0) ? ex0.x : (j == 1) ? ex0.y : (j == 2) ? ex0.z : ex0.w;
            float eh1 = (j == 0) ? ex1.x : (j == 1) ? ex1.y : (j == 2) ? ex1.z : ex1.w;
            float s0 = eh0 * inv0;
            float s1 = eh1 * inv1;
            float4 xm0 = ld4h(g_xm + (size_t)d0 * 128 + lane * 4);
            float4 xm1 = ld4h(g_xm + (size_t)d1 * 128 + lane * 4);
            float4 em0 = ld4h(em_p + (size_t)e0 * 32 + q * 4);
            float4 em1 = ld4h(em_p + (size_t)e1 * 32 + q * 4);
            T0.x += s0 * (xm0.x + em0.x);
            T0.y += s0 * (xm0.y + em0.y);
            T0.z += s0 * (xm0.z + em0.z);
            T0.w += s0 * (xm0.w + em0.w);
            T1.x += s1 * (xm1.x + em1.x);
            T1.y += s1 * (xm1.y + em1.y);
            T1.z += s1 * (xm1.z + em1.z);
            T1.w += s1 * (xm1.w + em1.w);
        }
        int tgt0 = __ldg(ei + NE + 4 * g0 + j);
        int tgt1 = __ldg(ei + NE + 4 * g1 + j);
        float* p0 = g_aggr + (size_t)tgt0 * 32 + q * 4;
        float* p1 = g_aggr + (size_t)tgt1 * 32 + q * 4;
        asm volatile("red.global.add.v4.f32 [%0], {%1,%2,%3,%4};"
                     :: "l"(p0), "f"(T0.x), "f"(T0.y), "f"(T0.z), "f"(T0.w)
                     : "memory");
        asm volatile("red.global.add.v4.f32 [%0], {%1,%2,%3,%4};"
                     :: "l"(p1), "f"(T1.x), "f"(T1.y), "f"(T1.z), "f"(T1.w)
                     : "memory");
    }
}

extern "C" void kernel_launch(void* const* d_in, const int* in_sizes, int n_in,
                              void* d_out, int out_size) {
    const float* x      = (const float*)d_in[0];
    const float* eattr  = (const float*)d_in[1];
    const int*   ei     = (const int*)d_in[2];
    const float* atom_w = (const float*)d_in[3];
    const float* atom_b = (const float*)d_in[4];
    const float* asw  = (const float*)d_in[5];
    const float* asb  = (const float*)d_in[6];
    const float* adw  = (const float*)d_in[7];
    const float* adb  = (const float*)d_in[8];
    const float* aew  = (const float*)d_in[9];
    const float* aeb  = (const float*)d_in[10];
    const float* dotw = (const float*)d_in[11];
    const float* dotb = (const float*)d_in[12];
    const float* mdw  = (const float*)d_in[13];
    const float* mdb  = (const float*)d_in[14];
    const float* mew  = (const float*)d_in[15];
    const float* meb  = (const float*)d_in[16];
    const float* wnw  = (const float*)d_in[17];
    const float* wnb  = (const float*)d_in[18];
    float* out = (float*)d_out;

    float *p_h, *p_atom;
    __half *p_xs, *p_xd, *p_xm, *p_ea, *p_em, *p_ea2, *p_em2;
    cudaGetSymbolAddress((void**)&p_h,    g_h);
    cudaGetSymbolAddress((void**)&p_atom, g_atom);
    cudaGetSymbolAddress((void**)&p_xs,   g_xs);
    cudaGetSymbolAddress((void**)&p_xd,   g_xd);
    cudaGetSymbolAddress((void**)&p_xm,   g_xm);
    cudaGetSymbolAddress((void**)&p_ea,   g_ea);
    cudaGetSymbolAddress((void**)&p_em,   g_em);
    cudaGetSymbolAddress((void**)&p_ea2,  g_ea2);
    cudaGetSymbolAddress((void**)&p_em2,  g_em2);

    // smem = 2 * KK * PITCH * 4
    const int smem_atom = 2 * 64 * (4 * 32 + 8) * 4;    // 69632
    const int smem_e4   = 2 * 16 * (4 * 32 + 8) * 4;    // 17408
    const int smem_n3   = 2 * 16 * (3 * 32 + 8) * 4;    // 13312
    const int smem_c1   = 2 * 16 * (1 * 32 + 8) * 4;    // 5120
    cudaFuncSetAttribute(k_g<4, 8, 1, 0>,
                         cudaFuncAttributeMaxDynamicSharedMemorySize, smem_atom);

    // atom: (50000 x 128) @ (128 x 128), relu, dual fp32 write g_atom/g_h
    {
        GArgs ga;
        ga.A = x; ga.M = NN; ga.Astride = 128; ga.Bstride = 128; ga.Ostride = 128;
        for (int m = 0; m < 4; m++) {
            ga.B[m]    = atom_w + m * 32;
            ga.bias[m] = atom_b + m * 32;
            ga.out[m]  = p_atom + m * 32;
            ga.out2[m] = p_h    + m * 32;
        }
        k_g<4, 8, 1, 0><<<296, 256, smem_atom>>>(ga);
    }

    // elin both layers in ONE pass over eattr: ea0, em0, ea1, em1 (fp16 out)
    {
        GArgs ge;
        ge.A = eattr; ge.M = NE; ge.Astride = 32; ge.Bstride = 32; ge.Ostride = 32;
        ge.B[0] = aew;        ge.B[1] = mew;        ge.B[2] = aew + 1024; ge.B[3] = mew + 1024;
        ge.bias[0] = aeb;     ge.bias[1] = meb;     ge.bias[2] = aeb + 32; ge.bias[3] = meb + 32;
        ge.out[0] = p_ea; ge.out[1] = p_em; ge.out[2] = p_ea2; ge.out[3] = p_em2;
        for (int m = 0; m < 4; m++) ge.out2[m] = p_ea;
        k_g<4, 2, 0, 1><<<444, 256, smem_e4>>>(ge);
    }

    for (int l = 0; l < 2; l++) {
        int wo = l * 32 * 32, bo = l * 32;
        const __half* ea_l = l ? p_ea2 : p_ea;
        const __half* em_l = l ? p_em2 : p_em;

        k_init<<<512, 256>>>();

        GArgs gn;
        gn.A = p_h; gn.M = ROWS; gn.Astride = 32; gn.Bstride = 32; gn.Ostride = 32;
        gn.B[0] = asw + wo; gn.B[1] = adw + wo; gn.B[2] = mdw + wo; gn.B[3] = asw + wo;
        gn.bias[0] = asb + bo; gn.bias[1] = adb + bo; gn.bias[2] = mdb + bo; gn.bias[3] = asb + bo;
        gn.out[0] = p_xs; gn.out[1] = p_xd; gn.out[2] = p_xm; gn.out[3] = p_xs;
        for (int m = 0; m < 4; m++) gn.out2[m] = p_xs;
        k_g<3, 2, 0, 1><<<444, 256, smem_n3>>>(gn);

        k_attn<<<740, 256>>>(ei, ea_l, dotw + l * 32, dotb + l);
        k_msg<<<740, 256>>>(ei, em_l);

        GArgs gc;
        gc.A = p_h; gc.M = ROWS; gc.Astride = 32; gc.Bstride = 32; gc.Ostride = 32;
        gc.B[0] = wnw + wo; gc.B[1] = wnw + wo; gc.B[2] = wnw + wo; gc.B[3] = wnw + wo;
        gc.bias[0] = wnb + bo; gc.bias[1] = wnb + bo; gc.bias[2] = wnb + bo; gc.bias[3] = wnb + bo;
        gc.out2[0] = gc.out2[1] = gc.out2[2] = gc.out2[3] = p_h;
        if (l == 0) {
            gc.out[0] = p_h; gc.out[1] = p_h; gc.out[2] = p_h; gc.out[3] = p_h;
            k_g<1, 2, 2, 0><<<444, 256, smem_c1>>>(gc);
        } else {
            gc.out[0] = out; gc.out[1] = out; gc.out[2] = out; gc.out[3] = out;
            k_g<1, 2, 3, 0><<<444, 256, smem_c1>>>(gc);
        }
    }
}

// round 14
// speedup vs baseline: 1.3678x; 1.0043x over previous
#include <cuda_runtime.h>
#include <cuda_fp16.h>
#include <cstdint>

#define FULL 0xffffffffu

constexpr int NN   = 50000;
constexpr int NE   = 400000;
constexpr int F    = 32;
constexpr int H    = 4;
constexpr int ROWS = NN * H;        // 200000 (n,h) rows
constexpr int NG   = NE / H;        // 100000 message groups

// ---- scratch (device globals; no allocation allowed) ----
__device__ float    g_h[ROWS * F];
__device__ float    g_atom[ROWS * F];
__device__ __half   g_xs[ROWS * F];
__device__ __half   g_xd[ROWS * F];
__device__ __half   g_xm[ROWS * F];
__device__ __half   g_ea[NE * F];       // layer 0
__device__ __half   g_em[NE * F];
__device__ __half   g_ea2[NE * F];      // layer 1
__device__ __half   g_em2[NE * F];
__device__ float    g_exp[NE * H];
__device__ float    g_nsum[NN];
__device__ float    g_aggr[ROWS * F];

__device__ __forceinline__ void mma16(float d[4], const uint32_t a[4],
                                      uint32_t b0, uint32_t b1) {
    asm("mma.sync.aligned.m16n8k16.row.col.f32.f16.f16.f32 "
        "{%0,%1,%2,%3}, {%4,%5,%6,%7}, {%8,%9}, {%0,%1,%2,%3};"
        : "+f"(d[0]), "+f"(d[1]), "+f"(d[2]), "+f"(d[3])
        : "r"(a[0]), "r"(a[1]), "r"(a[2]), "r"(a[3]), "r"(b0), "r"(b1));
}

// split fp32 pair -> fp16 hi + fp16 residual lo (packed half2 as u32)
__device__ __forceinline__ void splitH(float x, float y,
                                       uint32_t& hi, uint32_t& lo) {
    __half2 h = __floats2half2_rn(x, y);
    float2 hf = __half22float2(h);
    __half2 l = __floats2half2_rn(x - hf.x, y - hf.y);
    hi = *(uint32_t*)&h;
    lo = *(uint32_t*)&l;
}

struct GArgs {
    const float* A;
    const float* B[4];
    const float* bias[4];
    void*        out[4];
    void*        out2[4];
    int          M;
    int          Astride;
    int          Bstride;
    int          Ostride;
};

// ---- fused node-linear stage (xs/xd/xm GEMM on an in-register h tile) ----
constexpr int PITCHN = 3 * 32 + 8;   // 104, % 32 == 8 -> conflict-free

struct NArgs {
    const float* W[3];
    const float* bias[3];
    __half*      out[3];
};

__device__ __forceinline__ void stage_nlin(uint32_t* sH2, uint32_t* sL2,
                                           const NArgs& na, int tid) {
    for (int m = 0; m < 3; m++) {
        const float* Bp = na.W[m];
        for (int i = tid; i < 16 * 32; i += 256) {
            int kk = i >> 5, n = i & 31;
            float v0 = Bp[(2 * kk) * 32 + n];
            float v1 = Bp[(2 * kk + 1) * 32 + n];
            uint32_t hi, lo; splitH(v0, v1, hi, lo);
            sH2[kk * PITCHN + m * 32 + n] = hi;
            sL2[kk * PITCHN + m * 32 + n] = lo;
        }
    }
}

// hh[nt][0..3] = h values: rows (gid, gid+8) x cols (nt*8+2tig, +1) of a
// 16x32 tile. These are exactly the mma A-fragments for K=32 (2 chunks).
__device__ __forceinline__ void nlin_on_tile(const float (*hh)[4],
        const uint32_t* sH2, const uint32_t* sL2, const NArgs& na,
        int ra, int rb, int lane) {
    int gid = lane >> 2, tig = lane & 3;
    float d2[12][4];
#pragma unroll
    for (int nt = 0; nt < 12; nt++) {
        d2[nt][0] = 0.f; d2[nt][1] = 0.f; d2[nt][2] = 0.f; d2[nt][3] = 0.f;
    }
#pragma unroll
    for (int kc = 0; kc < 2; kc++) {
        uint32_t ah[4], al[4];
        splitH(hh[kc*2][0],   hh[kc*2][1],   ah[0], al[0]);
        splitH(hh[kc*2][2],   hh[kc*2][3],   ah[1], al[1]);
        splitH(hh[kc*2+1][0], hh[kc*2+1][1], ah[2], al[2]);
        splitH(hh[kc*2+1][2], hh[kc*2+1][3], ah[3], al[3]);
        int krow = (kc * 8 + tig) * PITCHN + gid;
#pragma unroll
        for (int nt = 0; nt < 12; nt++) {
            int i0 = krow + nt * 8;
            uint32_t bh0 = sH2[i0], bh1 = sH2[i0 + 4 * PITCHN];
            uint32_t bl0 = sL2[i0], bl1 = sL2[i0 + 4 * PITCHN];
            mma16(d2[nt], ah, bh0, bh1);
            mma16(d2[nt], ah, bl0, bl1);
            mma16(d2[nt], al, bh0, bh1);
        }
    }
#pragma unroll
    for (int nt = 0; nt < 12; nt++) {
        int m = nt >> 2;
        int c = (nt & 3) * 8 + 2 * tig;
        float b0 = na.bias[m][c], b1 = na.bias[m][c + 1];
        __half* op = na.out[m];
        *(__half2*)&op[(size_t)ra * 32 + c] =
            __floats2half2_rn(d2[nt][0] + b0, d2[nt][1] + b1);
        *(__half2*)&op[(size_t)rb * 32 + c] =
            __floats2half2_rn(d2[nt][2] + b0, d2[nt][3] + b1);
    }
}

// ============================================================================
// generic gemm (still used for elin and final comb)
// ============================================================================
template<int NM, int KC16, int MODE, int OUTH>
__device__ __forceinline__ void gemm_body(const GArgs& ga, uint32_t* sB,
                                          int bid, int nblocks, int tid) {
    constexpr int NT = NM * 4;
    constexpr int PITCH = NM * 32 + 8;
    constexpr int KK = KC16 * 8;
    uint32_t* sH = sB;
    uint32_t* sL = sB + KK * PITCH;

    for (int m = 0; m < NM; m++) {
        const float* Bp = ga.B[m];
        for (int i = tid; i < KK * 32; i += 256) {
            int kk = i >> 5, n = i & 31;
            float v0 = Bp[(size_t)(2 * kk)     * ga.Bstride + n];
            float v1 = Bp[(size_t)(2 * kk + 1) * ga.Bstride + n];
            uint32_t hi, lo;
            splitH(v0, v1, hi, lo);
            sH[kk * PITCH + m * 32 + n] = hi;
            sL[kk * PITCH + m * 32 + n] = lo;
        }
    }
    __syncthreads();

    int lane = tid & 31;
    int gid = lane >> 2, tig = lane & 3;
    int gw = bid * 8 + (tid >> 5);
    int nw = nblocks * 8;
    int ntile = ga.M >> 4;
    const int As = ga.Astride;

    for (int t = gw; t < ntile; t += nw) {
        const float* Ap = ga.A + (size_t)(t * 16) * As;
        float d[NT][4];
#pragma unroll
        for (int nt = 0; nt < NT; nt++) {
            d[nt][0] = 0.f; d[nt][1] = 0.f; d[nt][2] = 0.f; d[nt][3] = 0.f;
        }
#pragma unroll 2
        for (int kc = 0; kc < KC16; kc++) {
            float2 p0 = *(const float2*)(Ap + (size_t)gid * As + kc * 16 + 2 * tig);
            float2 p1 = *(const float2*)(Ap + (size_t)(gid + 8) * As + kc * 16 + 2 * tig);
            float2 p2 = *(const float2*)(Ap + (size_t)gid * As + kc * 16 + 2 * tig + 8);
            float2 p3 = *(const float2*)(Ap + (size_t)(gid + 8) * As + kc * 16 + 2 * tig + 8);
            uint32_t ah[4], al[4];
            splitH(p0.x, p0.y, ah[0], al[0]);
            splitH(p1.x, p1.y, ah[1], al[1]);
            splitH(p2.x, p2.y, ah[2], al[2]);
            splitH(p3.x, p3.y, ah[3], al[3]);
            int krow = (kc * 8 + tig) * PITCH + gid;
#pragma unroll
            for (int nt = 0; nt < NT; nt++) {
                int i0 = krow + nt * 8;
                uint32_t bh0 = sH[i0], bh1 = sH[i0 + 4 * PITCH];
                uint32_t bl0 = sL[i0], bl1 = sL[i0 + 4 * PITCH];
                mma16(d[nt], ah, bh0, bh1);
                mma16(d[nt], ah, bl0, bl1);
                mma16(d[nt], al, bh0, bh1);
            }
        }
        int ra = t * 16 + gid, rb = ra + 8;
#pragma unroll
        for (int nt = 0; nt < NT; nt++) {
            const int m = nt >> 2;
            int c = (nt & 3) * 8 + 2 * tig;
            float b0 = ga.bias[m][c], b1 = ga.bias[m][c + 1];
            float o0 = d[nt][0] + b0, o1 = d[nt][1] + b1;
            float o2 = d[nt][2] + b0, o3 = d[nt][3] + b1;
            if (MODE >= 2) {
                int ia = ra * 32 + c, ib = rb * 32 + c;
                o0 += g_aggr[ia]     + g_atom[ia];
                o1 += g_aggr[ia + 1] + g_atom[ia + 1];
                o2 += g_aggr[ib]     + g_atom[ib];
                o3 += g_aggr[ib + 1] + g_atom[ib + 1];
            }
            if (MODE != 0) {
                o0 = fmaxf(o0, 0.f); o1 = fmaxf(o1, 0.f);
                o2 = fmaxf(o2, 0.f); o3 = fmaxf(o3, 0.f);
            }
            if (MODE == 3) {
                float s0 = o0 + __shfl_xor_sync(FULL, o0, 4);
                s0 += __shfl_xor_sync(FULL, s0, 8);
                float s1 = o1 + __shfl_xor_sync(FULL, o1, 4);
                s1 += __shfl_xor_sync(FULL, s1, 8);
                float s2 = o2 + __shfl_xor_sync(FULL, o2, 4);
                s2 += __shfl_xor_sync(FULL, s2, 8);
                float s3 = o3 + __shfl_xor_sync(FULL, o3, 4);
                s3 += __shfl_xor_sync(FULL, s3, 8);
                if ((gid & 3) == 0) {
                    float* op = (float*)ga.out[0];
                    int na = ra >> 2;
                    int nb = rb >> 2;
                    *(float2*)&op[na * 32 + c] = make_float2(0.25f*s0, 0.25f*s1);
                    *(float2*)&op[nb * 32 + c] = make_float2(0.25f*s2, 0.25f*s3);
                }
                continue;
            }
            size_t ia = (size_t)ra * ga.Ostride + c;
            size_t ib = (size_t)rb * ga.Ostride + c;
            if (OUTH) {
                __half* op = (__half*)ga.out[m];
                *(__half2*)&op[ia] = __floats2half2_rn(o0, o1);
                *(__half2*)&op[ib] = __floats2half2_rn(o2, o3);
            } else {
                float* op = (float*)ga.out[m];
                *(float2*)&op[ia] = make_float2(o0, o1);
                *(float2*)&op[ib] = make_float2(o2, o3);
                if (MODE == 1) {
                    float* op2 = (float*)ga.out2[m];
                    *(float2*)&op2[ia] = make_float2(o0, o1);
                    *(float2*)&op2[ib] = make_float2(o2, o3);
                }
            }
        }
    }
}

template<int NM, int KC16, int MODE, int OUTH>
__global__ void __launch_bounds__(256) k_g(GArgs ga) {
    extern __shared__ uint32_t sB[];
    gemm_body<NM, KC16, MODE, OUTH>(ga, sB, blockIdx.x, gridDim.x, threadIdx.x);
}

// ============================================================================
// k_atomf: atom GEMM (K=128, 4 col groups) + relu + dual write, then fused
// layer-0 xs/xd/xm GEMM per head on the in-register h tiles.
// ============================================================================
__global__ void __launch_bounds__(256) k_atomf(GArgs ga, NArgs na) {
    extern __shared__ uint32_t sB[];
    constexpr int PITCH = 4 * 32 + 8;   // 136
    constexpr int KK = 64;              // K=128
    uint32_t* sH = sB;
    uint32_t* sL = sB + KK * PITCH;
    uint32_t* sH2 = sB + 2 * KK * PITCH;
    uint32_t* sL2 = sH2 + 16 * PITCHN;
    int tid = threadIdx.x;

    for (int m = 0; m < 4; m++) {
        const float* Bp = ga.B[m];
        for (int i = tid; i < KK * 32; i += 256) {
            int kk = i >> 5, n = i & 31;
            float v0 = Bp[(size_t)(2 * kk) * 128 + n];
            float v1 = Bp[(size_t)(2 * kk + 1) * 128 + n];
            uint32_t hi, lo; splitH(v0, v1, hi, lo);
            sH[kk * PITCH + m * 32 + n] = hi;
            sL[kk * PITCH + m * 32 + n] = lo;
        }
    }
    stage_nlin(sH2, sL2, na, tid);
    __syncthreads();

    int lane = tid & 31;
    int gid = lane >> 2, tig = lane & 3;
    int gw = blockIdx.x * 8 + (tid >> 5);
    int nw = gridDim.x * 8;
    float* p_atom = (float*)ga.out[0];
    float* p_h    = (float*)ga.out2[0];

    for (int t = gw; t < (NN >> 4); t += nw) {
        const float* Ap = ga.A + (size_t)(t * 16) * 128;
        float d[16][4];
#pragma unroll
        for (int nt = 0; nt < 16; nt++) {
            d[nt][0] = 0.f; d[nt][1] = 0.f; d[nt][2] = 0.f; d[nt][3] = 0.f;
        }
#pragma unroll 2
        for (int kc = 0; kc < 8; kc++) {
            float2 p0 = *(const float2*)(Ap + (size_t)gid * 128 + kc * 16 + 2 * tig);
            float2 p1 = *(const float2*)(Ap + (size_t)(gid + 8) * 128 + kc * 16 + 2 * tig);
            float2 p2 = *(const float2*)(Ap + (size_t)gid * 128 + kc * 16 + 2 * tig + 8);
            float2 p3 = *(const float2*)(Ap + (size_t)(gid + 8) * 128 + kc * 16 + 2 * tig + 8);
            uint32_t ah[4], al[4];
            splitH(p0.x, p0.y, ah[0], al[0]);
            splitH(p1.x, p1.y, ah[1], al[1]);
            splitH(p2.x, p2.y, ah[2], al[2]);
            splitH(p3.x, p3.y, ah[3], al[3]);
            int krow = (kc * 8 + tig) * PITCH + gid;
#pragma unroll
            for (int nt = 0; nt < 16; nt++) {
                int i0 = krow + nt * 8;
                uint32_t bh0 = sH[i0], bh1 = sH[i0 + 4 * PITCH];
                uint32_t bl0 = sL[i0], bl1 = sL[i0 + 4 * PITCH];
                mma16(d[nt], ah, bh0, bh1);
                mma16(d[nt], ah, bl0, bl1);
                mma16(d[nt], al, bh0, bh1);
            }
        }
        int ra = t * 16 + gid, rb = ra + 8;
#pragma unroll
        for (int nt = 0; nt < 16; nt++) {
            int m = nt >> 2;
            int c = (nt & 3) * 8 + 2 * tig;
            float b0 = ga.bias[m][c], b1 = ga.bias[m][c + 1];
            float o0 = fmaxf(d[nt][0] + b0, 0.f);
            float o1 = fmaxf(d[nt][1] + b1, 0.f);
            float o2 = fmaxf(d[nt][2] + b0, 0.f);
            float o3 = fmaxf(d[nt][3] + b1, 0.f);
            size_t ia = (size_t)ra * 128 + m * 32 + c;
            size_t ib = (size_t)rb * 128 + m * 32 + c;
            *(float2*)&p_atom[ia] = make_float2(o0, o1);
            *(float2*)&p_atom[ib] = make_float2(o2, o3);
            *(float2*)&p_h[ia]    = make_float2(o0, o1);
            *(float2*)&p_h[ib]    = make_float2(o2, o3);
            d[nt][0] = o0; d[nt][1] = o1; d[nt][2] = o2; d[nt][3] = o3;
        }
        // fused layer-0 node linears: head m tile rows -> (n,h)=(row,m)
#pragma unroll
        for (int m = 0; m < 4; m++)
            nlin_on_tile(&d[m * 4], sH2, sL2, na, ra * 4 + m, rb * 4 + m, lane);
    }
}

// ============================================================================
// k_combf: layer-0 comb (h = relu(h@wnw + wnb + aggr + atom), writes g_h)
// + fused layer-1 xs/xd/xm GEMM on the in-register h tile.
// ============================================================================
__global__ void __launch_bounds__(256) k_combf(GArgs ga, NArgs na) {
    extern __shared__ uint32_t sB[];
    constexpr int PITCH = 40;   // NM=1
    constexpr int KK = 16;
    uint32_t* sH = sB;
    uint32_t* sL = sB + KK * PITCH;
    uint32_t* sH2 = sB + 2 * KK * PITCH;
    uint32_t* sL2 = sH2 + 16 * PITCHN;
    int tid = threadIdx.x;

    {
        const float* Bp = ga.B[0];
        for (int i = tid; i < KK * 32; i += 256) {
            int kk = i >> 5, n = i & 31;
            float v0 = Bp[(2 * kk) * 32 + n];
            float v1 = Bp[(2 * kk + 1) * 32 + n];
            uint32_t hi, lo; splitH(v0, v1, hi, lo);
            sH[kk * PITCH + n] = hi;
            sL[kk * PITCH + n] = lo;
        }
    }
    stage_nlin(sH2, sL2, na, tid);
    __syncthreads();

    int lane = tid & 31;
    int gid = lane >> 2, tig = lane & 3;
    int gw = blockIdx.x * 8 + (tid >> 5);
    int nw = gridDim.x * 8;
    float* hout = (float*)ga.out[0];

    for (int t = gw; t < (ROWS >> 4); t += nw) {
        const float* Ap = ga.A + (size_t)(t * 16) * 32;
        float d[4][4];
#pragma unroll
        for (int nt = 0; nt < 4; nt++) {
            d[nt][0] = 0.f; d[nt][1] = 0.f; d[nt][2] = 0.f; d[nt][3] = 0.f;
        }
#pragma unroll
        for (int kc = 0; kc < 2; kc++) {
            float2 p0 = *(const float2*)(Ap + (size_t)gid * 32 + kc * 16 + 2 * tig);
            float2 p1 = *(const float2*)(Ap + (size_t)(gid + 8) * 32 + kc * 16 + 2 * tig);
            float2 p2 = *(const float2*)(Ap + (size_t)gid * 32 + kc * 16 + 2 * tig + 8);
            float2 p3 = *(const float2*)(Ap + (size_t)(gid + 8) * 32 + kc * 16 + 2 * tig + 8);
            uint32_t ah[4], al[4];
            splitH(p0.x, p0.y, ah[0], al[0]);
            splitH(p1.x, p1.y, ah[1], al[1]);
            splitH(p2.x, p2.y, ah[2], al[2]);
            splitH(p3.x, p3.y, ah[3], al[3]);
            int krow = (kc * 8 + tig) * PITCH + gid;
#pragma unroll
            for (int nt = 0; nt < 4; nt++) {
                int i0 = krow + nt * 8;
                uint32_t bh0 = sH[i0], bh1 = sH[i0 + 4 * PITCH];
                uint32_t bl0 = sL[i0], bl1 = sL[i0 + 4 * PITCH];
                mma16(d[nt], ah, bh0, bh1);
                mma16(d[nt], ah, bl0, bl1);
                mma16(d[nt], al, bh0, bh1);
            }
        }
        int ra = t * 16 + gid, rb = ra + 8;
#pragma unroll
        for (int nt = 0; nt < 4; nt++) {
            int c = nt * 8 + 2 * tig;
            float b0 = ga.bias[0][c], b1 = ga.bias[0][c + 1];
            int ia = ra * 32 + c, ib = rb * 32 + c;
            float o0 = fmaxf(d[nt][0] + b0 + g_aggr[ia]     + g_atom[ia],     0.f);
            float o1 = fmaxf(d[nt][1] + b1 + g_aggr[ia + 1] + g_atom[ia + 1], 0.f);
            float o2 = fmaxf(d[nt][2] + b0 + g_aggr[ib]     + g_atom[ib],     0.f);
            float o3 = fmaxf(d[nt][3] + b1 + g_aggr[ib + 1] + g_atom[ib + 1], 0.f);
            *(float2*)&hout[ia] = make_float2(o0, o1);
            *(float2*)&hout[ib] = make_float2(o2, o3);
            d[nt][0] = o0; d[nt][1] = o1; d[nt][2] = o2; d[nt][3] = o3;
        }
        // fused layer-1 node linears on the h tile just computed
        nlin_on_tile(d, sH2, sL2, na, ra, rb, lane);
    }
}

// ---- zero aggr/nsum (per layer) ----
__global__ void k_init() {
    int i = blockIdx.x * blockDim.x + threadIdx.x;
    int stride = gridDim.x * blockDim.x;
    for (int j = i; j < ROWS * F / 4; j += stride)
        ((float4*)g_aggr)[j] = make_float4(0.f, 0.f, 0.f, 0.f);
    for (int j = i; j < NN; j += stride)
        g_nsum[j] = 0.f;
}

__device__ __forceinline__ float4 ld4h(const __half* p) {
    uint2 u = *(const uint2*)p;
    float2 lo = __half22float2(*(__half2*)&u.x);
    float2 hi = __half22float2(*(__half2*)&u.y);
    return make_float4(lo.x, lo.y, hi.x, hi.y);
}

// ---- edge attention: scores -> exp -> segment sum, fused; 4-edge unroll ----
__global__ void k_attn(const int* __restrict__ ei, const __half* __restrict__ ea_p,
                       const float* __restrict__ dw, const float* __restrict__ db) {
    int lane = threadIdx.x & 31;
    int q = lane & 7;
    float4 dw4 = ((const float4*)dw)[q];
    float dbv = db[0];
    int gw = (blockIdx.x * blockDim.x + threadIdx.x) >> 5;
    int nw = (gridDim.x * blockDim.x) >> 5;
    for (int e0 = gw * 4; e0 < NE; e0 += nw * 4) {   // NE % 4 == 0
        int s[4], dd[4];
#pragma unroll
        for (int k = 0; k < 4; k++) {
            s[k]  = __ldg(ei + e0 + k);
            dd[k] = __ldg(ei + NE + e0 + k);
        }
        float v[4];
#pragma unroll
        for (int k = 0; k < 4; k++) {
            float4 a  = ld4h(g_xs + (size_t)dd[k] * 128 + lane * 4);
            float4 c  = ld4h(g_xd + (size_t)s[k]  * 128 + lane * 4);
            float4 ea = ld4h(ea_p + (size_t)(e0 + k) * 32 + q * 4);
            v[k] = fmaxf(a.x + c.x + ea.x, 0.f) * dw4.x
                 + fmaxf(a.y + c.y + ea.y, 0.f) * dw4.y
                 + fmaxf(a.z + c.z + ea.z, 0.f) * dw4.z
                 + fmaxf(a.w + c.w + ea.w, 0.f) * dw4.w;
        }
#pragma unroll
        for (int k = 0; k < 4; k++) {
            v[k] += __shfl_xor_sync(FULL, v[k], 4);
            v[k] += __shfl_xor_sync(FULL, v[k], 2);
            v[k] += __shfl_xor_sync(FULL, v[k], 1);
        }
        float ex[4], tt[4];
#pragma unroll
        for (int k = 0; k < 4; k++) {
            float ar = __shfl_sync(FULL, v[k], (lane & 3) * 8) + dbv;
            ex[k] = __expf(ar);
            float t = ex[k] + __shfl_xor_sync(FULL, ex[k], 1);
            t += __shfl_xor_sync(FULL, t, 2);
            tt[k] = t;
        }
        int kk = lane >> 2;
        if (kk < 4) {
            g_exp[(e0 + kk) * 4 + (lane & 3)] = ex[kk];
            if ((lane & 3) == 0)
                atomicAdd(&g_nsum[dd[kk]], tt[kk]);
        }
    }
}

// ---- messages + tiled scatter; 2-group unroll for MLP ----
__global__ void k_msg(const int* __restrict__ ei, const __half* __restrict__ em_p) {
    int lane = threadIdx.x & 31;
    int q = lane & 7;
    int j = lane >> 3;
    int gw = (blockIdx.x * blockDim.x + threadIdx.x) >> 5;
    int nw = (gridDim.x * blockDim.x) >> 5;
    for (int g0 = gw * 2; g0 < NG; g0 += nw * 2) {   // NG even
        int g1 = g0 + 1;
        float4 T0 = make_float4(0.f, 0.f, 0.f, 0.f);
        float4 T1 = make_float4(0.f, 0.f, 0.f, 0.f);
#pragma unroll
        for (int c = 0; c < 4; c++) {
            int e0 = c * NG + g0;
            int e1 = c * NG + g1;
            int d0 = __ldg(ei + NE + e0);
            int d1 = __ldg(ei + NE + e1);
            float4 ex0 = ((const float4*)g_exp)[e0];
            float4 ex1 = ((const float4*)g_exp)[e1];
            float inv0 = 1.f / (g_nsum[d0] + 1e-8f);
            float inv1 = 1.f / (g_nsum[d1] + 1e-8f);
            float eh0 = (j == 0) ? ex0.x : (j == 1) ? ex0.y : (j == 2) ? ex0.z : ex0.w;
            float eh1 = (j == 0) ? ex1.x : (j == 1) ? ex1.y : (j == 2) ? ex1.z : ex1.w;
            float s0 = eh0 * inv0;
            float s1 = eh1 * inv1;
            float4 xm0 = ld4h(g_xm + (size_t)d0 * 128 + lane * 4);
            float4 xm1 = ld4h(g_xm + (size_t)d1 * 128 + lane * 4);
            float4 em0 = ld4h(em_p + (size_t)e0 * 32 + q * 4);
            float4 em1 = ld4h(em_p + (size_t)e1 * 32 + q * 4);
            T0.x += s0 * (xm0.x + em0.x);
            T0.y += s0 * (xm0.y + em0.y);
            T0.z += s0 * (xm0.z + em0.z);
            T0.w += s0 * (xm0.w + em0.w);
            T1.x += s1 * (xm1.x + em1.x);
            T1.y += s1 * (xm1.y + em1.y);
            T1.z += s1 * (xm1.z + em1.z);
            T1.w += s1 * (xm1.w + em1.w);
        }
        int tgt0 = __ldg(ei + NE + 4 * g0 + j);
        int tgt1 = __ldg(ei + NE + 4 * g1 + j);
        float* p0 = g_aggr + (size_t)tgt0 * 32 + q * 4;
        float* p1 = g_aggr + (size_t)tgt1 * 32 + q * 4;
        asm volatile("red.global.add.v4.f32 [%0], {%1,%2,%3,%4};"
                     :: "l"(p0), "f"(T0.x), "f"(T0.y), "f"(T0.z), "f"(T0.w)
                     : "memory");
        asm volatile("red.global.add.v4.f32 [%0], {%1,%2,%3,%4};"
                     :: "l"(p1), "f"(T1.x), "f"(T1.y), "f"(T1.z), "f"(T1.w)
                     : "memory");
    }
}

extern "C" void kernel_launch(void* const* d_in, const int* in_sizes, int n_in,
                              void* d_out, int out_size) {
    const float* x      = (const float*)d_in[0];
    const float* eattr  = (const float*)d_in[1];
    const int*   ei     = (const int*)d_in[2];
    const float* atom_w = (const float*)d_in[3];
    const float* atom_b = (const float*)d_in[4];
    const float* asw  = (const float*)d_in[5];
    const float* asb  = (const float*)d_in[6];
    const float* adw  = (const float*)d_in[7];
    const float* adb  = (const float*)d_in[8];
    const float* aew  = (const float*)d_in[9];
    const float* aeb  = (const float*)d_in[10];
    const float* dotw = (const float*)d_in[11];
    const float* dotb = (const float*)d_in[12];
    const float* mdw  = (const float*)d_in[13];
    const float* mdb  = (const float*)d_in[14];
    const float* mew  = (const float*)d_in[15];
    const float* meb  = (const float*)d_in[16];
    const float* wnw  = (const float*)d_in[17];
    const float* wnb  = (const float*)d_in[18];
    float* out = (float*)d_out;

    float *p_h, *p_atom;
    __half *p_xs, *p_xd, *p_xm, *p_ea, *p_em, *p_ea2, *p_em2;
    cudaGetSymbolAddress((void**)&p_h,    g_h);
    cudaGetSymbolAddress((void**)&p_atom, g_atom);
    cudaGetSymbolAddress((void**)&p_xs,   g_xs);
    cudaGetSymbolAddress((void**)&p_xd,   g_xd);
    cudaGetSymbolAddress((void**)&p_xm,   g_xm);
    cudaGetSymbolAddress((void**)&p_ea,   g_ea);
    cudaGetSymbolAddress((void**)&p_em,   g_em);
    cudaGetSymbolAddress((void**)&p_ea2,  g_ea2);
    cudaGetSymbolAddress((void**)&p_em2,  g_em2);

    const int smem_atomf = (2 * 64 * 136 + 2 * 16 * PITCHN) * 4;  // 82944
    const int smem_combf = (2 * 16 * 40 + 2 * 16 * PITCHN) * 4;   // 18432
    const int smem_e4    = 2 * 16 * (4 * 32 + 8) * 4;             // 17408
    const int smem_c1    = 2 * 16 * (1 * 32 + 8) * 4;             // 5120
    cudaFuncSetAttribute(k_atomf,
                         cudaFuncAttributeMaxDynamicSharedMemorySize, smem_atomf);

    k_init<<<512, 256>>>();   // nsum/aggr for layer 0

    // atom + fused layer-0 node linears
    {
        GArgs ga;
        ga.A = x; ga.M = NN; ga.Astride = 128; ga.Bstride = 128; ga.Ostride = 128;
        for (int m = 0; m < 4; m++) {
            ga.B[m]    = atom_w + m * 32;
            ga.bias[m] = atom_b + m * 32;
        }
        ga.out[0] = p_atom; ga.out2[0] = p_h;
        NArgs na;
        na.W[0] = asw; na.W[1] = adw; na.W[2] = mdw;
        na.bias[0] = asb; na.bias[1] = adb; na.bias[2] = mdb;
        na.out[0] = p_xs; na.out[1] = p_xd; na.out[2] = p_xm;
        k_atomf<<<296, 256, smem_atomf>>>(ga, na);
    }

    // elin both layers in ONE pass over eattr: ea0, em0, ea1, em1 (fp16 out)
    {
        GArgs ge;
        ge.A = eattr; ge.M = NE; ge.Astride = 32; ge.Bstride = 32; ge.Ostride = 32;
        ge.B[0] = aew;        ge.B[1] = mew;        ge.B[2] = aew + 1024; ge.B[3] = mew + 1024;
        ge.bias[0] = aeb;     ge.bias[1] = meb;     ge.bias[2] = aeb + 32; ge.bias[3] = meb + 32;
        ge.out[0] = p_ea; ge.out[1] = p_em; ge.out[2] = p_ea2; ge.out[3] = p_em2;
        for (int m = 0; m < 4; m++) ge.out2[m] = p_ea;
        k_g<4, 2, 0, 1><<<444, 256, smem_e4>>>(ge);
    }

    // ---- layer 0 edge phase ----
    k_attn<<<740, 256>>>(ei, p_ea, dotw, dotb);
    k_msg<<<740, 256>>>(ei, p_em);

    // comb(l0) + fused layer-1 node linears
    {
        GArgs gc;
        gc.A = p_h; gc.M = ROWS; gc.Astride = 32; gc.Bstride = 32; gc.Ostride = 32;
        gc.B[0] = wnw; gc.bias[0] = wnb;
        gc.out[0] = p_h;
        NArgs na;
        na.W[0] = asw + 1024; na.W[1] = adw + 1024; na.W[2] = mdw + 1024;
        na.bias[0] = asb + 32; na.bias[1] = adb + 32; na.bias[2] = mdb + 32;
        na.out[0] = p_xs; na.out[1] = p_xd; na.out[2] = p_xm;
        k_combf<<<444, 256, smem_combf>>>(gc, na);
    }

    k_init<<<512, 256>>>();   // nsum/aggr for layer 1

    // ---- layer 1 edge phase ----
    k_attn<<<740, 256>>>(ei, p_ea2, dotw + 32, dotb + 1);
    k_msg<<<740, 256>>>(ei, p_em2);

    // final comb + head-mean -> out
    {
        GArgs gc;
        gc.A = p_h; gc.M = ROWS; gc.Astride = 32; gc.Bstride = 32; gc.Ostride = 32;
        gc.B[0] = wnw + 1024; gc.B[1] = gc.B[2] = gc.B[3] = gc.B[0];
        gc.bias[0] = wnb + 32; gc.bias[1] = gc.bias[2] = gc.bias[3] = gc.bias[0];
        gc.out[0] = out; gc.out[1] = gc.out[2] = gc.out[3] = out;
        gc.out2[0] = gc.out2[1] = gc.out2[2] = gc.out2[3] = p_h;
        k_g<1, 2, 3, 0><<<444, 256, smem_c1>>>(gc);
    }
}

// round 15
// speedup vs baseline: 1.3756x; 1.0057x over previous
#include <cuda_runtime.h>
#include <cuda_fp16.h>
#include <cstdint>

#define FULL 0xffffffffu

constexpr int NN   = 50000;
constexpr int NE   = 400000;
constexpr int F    = 32;
constexpr int H    = 4;
constexpr int ROWS = NN * H;        // 200000 (n,h) rows
constexpr int NG   = NE / H;        // 100000 message groups

// ---- scratch (device globals; no allocation allowed) ----
__device__ float    g_h[ROWS * F];
__device__ float    g_atom[ROWS * F];
__device__ __half   g_xs[ROWS * F];
__device__ __half   g_xd[ROWS * F];
__device__ __half   g_xm[ROWS * F];
__device__ __half   g_ea[NE * F];       // layer 0
__device__ __half   g_em[NE * F];
__device__ __half   g_ea2[NE * F];      // layer 1
__device__ __half   g_em2[NE * F];
__device__ float    g_exp[NE * H];
__device__ float    g_nsum[NN];
__device__ float    g_aggr[ROWS * F];

__device__ __forceinline__ void mma16(float d[4], const uint32_t a[4],
                                      uint32_t b0, uint32_t b1) {
    asm("mma.sync.aligned.m16n8k16.row.col.f32.f16.f16.f32 "
        "{%0,%1,%2,%3}, {%4,%5,%6,%7}, {%8,%9}, {%0,%1,%2,%3};"
        : "+f"(d[0]), "+f"(d[1]), "+f"(d[2]), "+f"(d[3])
        : "r"(a[0]), "r"(a[1]), "r"(a[2]), "r"(a[3]), "r"(b0), "r"(b1));
}

// split fp32 pair -> fp16 hi + fp16 residual lo (packed half2 as u32)
__device__ __forceinline__ void splitH(float x, float y,
                                       uint32_t& hi, uint32_t& lo) {
    __half2 h = __floats2half2_rn(x, y);
    float2 hf = __half22float2(h);
    __half2 l = __floats2half2_rn(x - hf.x, y - hf.y);
    hi = *(uint32_t*)&h;
    lo = *(uint32_t*)&l;
}

struct GArgs {
    const float* A;
    const float* B[4];
    const float* bias[4];
    void*        out[4];
    void*        out2[4];
    int          M;
    int          Astride;
    int          Bstride;
    int          Ostride;
};

// ---- fused node-linear stage (xs/xd/xm GEMM on an in-register h tile) ----
constexpr int PITCHN = 3 * 32 + 8;   // 104, % 32 == 8 -> conflict-free

struct NArgs {
    const float* W[3];
    const float* bias[3];
    __half*      out[3];
};

__device__ __forceinline__ void stage_nlin(uint32_t* sH2, uint32_t* sL2,
                                           const NArgs& na, int tid) {
    for (int m = 0; m < 3; m++) {
        const float* Bp = na.W[m];
        for (int i = tid; i < 16 * 32; i += 256) {
            int kk = i >> 5, n = i & 31;
            float v0 = Bp[(2 * kk) * 32 + n];
            float v1 = Bp[(2 * kk + 1) * 32 + n];
            uint32_t hi, lo; splitH(v0, v1, hi, lo);
            sH2[kk * PITCHN + m * 32 + n] = hi;
            sL2[kk * PITCHN + m * 32 + n] = lo;
        }
    }
}

__device__ __forceinline__ void nlin_on_tile(const float (*hh)[4],
        const uint32_t* sH2, const uint32_t* sL2, const NArgs& na,
        int ra, int rb, int lane) {
    int gid = lane >> 2, tig = lane & 3;
    float d2[12][4];
#pragma unroll
    for (int nt = 0; nt < 12; nt++) {
        d2[nt][0] = 0.f; d2[nt][1] = 0.f; d2[nt][2] = 0.f; d2[nt][3] = 0.f;
    }
#pragma unroll
    for (int kc = 0; kc < 2; kc++) {
        uint32_t ah[4], al[4];
        splitH(hh[kc*2][0],   hh[kc*2][1],   ah[0], al[0]);
        splitH(hh[kc*2][2],   hh[kc*2][3],   ah[1], al[1]);
        splitH(hh[kc*2+1][0], hh[kc*2+1][1], ah[2], al[2]);
        splitH(hh[kc*2+1][2], hh[kc*2+1][3], ah[3], al[3]);
        int krow = (kc * 8 + tig) * PITCHN + gid;
#pragma unroll
        for (int nt = 0; nt < 12; nt++) {
            int i0 = krow + nt * 8;
            uint32_t bh0 = sH2[i0], bh1 = sH2[i0 + 4 * PITCHN];
            uint32_t bl0 = sL2[i0], bl1 = sL2[i0 + 4 * PITCHN];
            mma16(d2[nt], ah, bh0, bh1);
            mma16(d2[nt], ah, bl0, bl1);
            mma16(d2[nt], al, bh0, bh1);
        }
    }
#pragma unroll
    for (int nt = 0; nt < 12; nt++) {
        int m = nt >> 2;
        int c = (nt & 3) * 8 + 2 * tig;
        float b0 = na.bias[m][c], b1 = na.bias[m][c + 1];
        __half* op = na.out[m];
        *(__half2*)&op[(size_t)ra * 32 + c] =
            __floats2half2_rn(d2[nt][0] + b0, d2[nt][1] + b1);
        *(__half2*)&op[(size_t)rb * 32 + c] =
            __floats2half2_rn(d2[nt][2] + b0, d2[nt][3] + b1);
    }
}

// ============================================================================
// generic gemm (elin and final comb)
// ============================================================================
template<int NM, int KC16, int MODE, int OUTH>
__device__ __forceinline__ void gemm_body(const GArgs& ga, uint32_t* sB,
                                          int bid, int nblocks, int tid) {
    constexpr int NT = NM * 4;
    constexpr int PITCH = NM * 32 + 8;
    constexpr int KK = KC16 * 8;
    uint32_t* sH = sB;
    uint32_t* sL = sB + KK * PITCH;

    for (int m = 0; m < NM; m++) {
        const float* Bp = ga.B[m];
        for (int i = tid; i < KK * 32; i += 256) {
            int kk = i >> 5, n = i & 31;
            float v0 = Bp[(size_t)(2 * kk)     * ga.Bstride + n];
            float v1 = Bp[(size_t)(2 * kk + 1) * ga.Bstride + n];
            uint32_t hi, lo;
            splitH(v0, v1, hi, lo);
            sH[kk * PITCH + m * 32 + n] = hi;
            sL[kk * PITCH + m * 32 + n] = lo;
        }
    }
    __syncthreads();

    int lane = tid & 31;
    int gid = lane >> 2, tig = lane & 3;
    int gw = bid * 8 + (tid >> 5);
    int nw = nblocks * 8;
    int ntile = ga.M >> 4;
    const int As = ga.Astride;

    for (int t = gw; t < ntile; t += nw) {
        const float* Ap = ga.A + (size_t)(t * 16) * As;
        float d[NT][4];
#pragma unroll
        for (int nt = 0; nt < NT; nt++) {
            d[nt][0] = 0.f; d[nt][1] = 0.f; d[nt][2] = 0.f; d[nt][3] = 0.f;
        }
#pragma unroll 2
        for (int kc = 0; kc < KC16; kc++) {
            float2 p0 = *(const float2*)(Ap + (size_t)gid * As + kc * 16 + 2 * tig);
            float2 p1 = *(const float2*)(Ap + (size_t)(gid + 8) * As + kc * 16 + 2 * tig);
            float2 p2 = *(const float2*)(Ap + (size_t)gid * As + kc * 16 + 2 * tig + 8);
            float2 p3 = *(const float2*)(Ap + (size_t)(gid + 8) * As + kc * 16 + 2 * tig + 8);
            uint32_t ah[4], al[4];
            splitH(p0.x, p0.y, ah[0], al[0]);
            splitH(p1.x, p1.y, ah[1], al[1]);
            splitH(p2.x, p2.y, ah[2], al[2]);
            splitH(p3.x, p3.y, ah[3], al[3]);
            int krow = (kc * 8 + tig) * PITCH + gid;
#pragma unroll
            for (int nt = 0; nt < NT; nt++) {
                int i0 = krow + nt * 8;
                uint32_t bh0 = sH[i0], bh1 = sH[i0 + 4 * PITCH];
                uint32_t bl0 = sL[i0], bl1 = sL[i0 + 4 * PITCH];
                mma16(d[nt], ah, bh0, bh1);
                mma16(d[nt], ah, bl0, bl1);
                mma16(d[nt], al, bh0, bh1);
            }
        }
        int ra = t * 16 + gid, rb = ra + 8;
#pragma unroll
        for (int nt = 0; nt < NT; nt++) {
            const int m = nt >> 2;
            int c = (nt & 3) * 8 + 2 * tig;
            float b0 = ga.bias[m][c], b1 = ga.bias[m][c + 1];
            float o0 = d[nt][0] + b0, o1 = d[nt][1] + b1;
            float o2 = d[nt][2] + b0, o3 = d[nt][3] + b1;
            if (MODE >= 2) {
                int ia = ra * 32 + c, ib = rb * 32 + c;
                o0 += g_aggr[ia]     + g_atom[ia];
                o1 += g_aggr[ia + 1] + g_atom[ia + 1];
                o2 += g_aggr[ib]     + g_atom[ib];
                o3 += g_aggr[ib + 1] + g_atom[ib + 1];
            }
            if (MODE != 0) {
                o0 = fmaxf(o0, 0.f); o1 = fmaxf(o1, 0.f);
                o2 = fmaxf(o2, 0.f); o3 = fmaxf(o3, 0.f);
            }
            if (MODE == 3) {
                float s0 = o0 + __shfl_xor_sync(FULL, o0, 4);
                s0 += __shfl_xor_sync(FULL, s0, 8);
                float s1 = o1 + __shfl_xor_sync(FULL, o1, 4);
                s1 += __shfl_xor_sync(FULL, s1, 8);
                float s2 = o2 + __shfl_xor_sync(FULL, o2, 4);
                s2 += __shfl_xor_sync(FULL, s2, 8);
                float s3 = o3 + __shfl_xor_sync(FULL, o3, 4);
                s3 += __shfl_xor_sync(FULL, s3, 8);
                if ((gid & 3) == 0) {
                    float* op = (float*)ga.out[0];
                    int na = ra >> 2;
                    int nb = rb >> 2;
                    *(float2*)&op[na * 32 + c] = make_float2(0.25f*s0, 0.25f*s1);
                    *(float2*)&op[nb * 32 + c] = make_float2(0.25f*s2, 0.25f*s3);
                }
                continue;
            }
            size_t ia = (size_t)ra * ga.Ostride + c;
            size_t ib = (size_t)rb * ga.Ostride + c;
            if (OUTH) {
                __half* op = (__half*)ga.out[m];
                *(__half2*)&op[ia] = __floats2half2_rn(o0, o1);
                *(__half2*)&op[ib] = __floats2half2_rn(o2, o3);
            } else {
                float* op = (float*)ga.out[m];
                *(float2*)&op[ia] = make_float2(o0, o1);
                *(float2*)&op[ib] = make_float2(o2, o3);
                if (MODE == 1) {
                    float* op2 = (float*)ga.out2[m];
                    *(float2*)&op2[ia] = make_float2(o0, o1);
                    *(float2*)&op2[ib] = make_float2(o2, o3);
                }
            }
        }
    }
}

template<int NM, int KC16, int MODE, int OUTH>
__global__ void __launch_bounds__(256) k_g(GArgs ga) {
    extern __shared__ uint32_t sB[];
    gemm_body<NM, KC16, MODE, OUTH>(ga, sB, blockIdx.x, gridDim.x, threadIdx.x);
}

// ============================================================================
// k_atomf: atom GEMM + relu + dual write + fused layer-0 node linears
// ============================================================================
__global__ void __launch_bounds__(256) k_atomf(GArgs ga, NArgs na) {
    extern __shared__ uint32_t sB[];
    constexpr int PITCH = 4 * 32 + 8;   // 136
    constexpr int KK = 64;              // K=128
    uint32_t* sH = sB;
    uint32_t* sL = sB + KK * PITCH;
    uint32_t* sH2 = sB + 2 * KK * PITCH;
    uint32_t* sL2 = sH2 + 16 * PITCHN;
    int tid = threadIdx.x;

    for (int m = 0; m < 4; m++) {
        const float* Bp = ga.B[m];
        for (int i = tid; i < KK * 32; i += 256) {
            int kk = i >> 5, n = i & 31;
            float v0 = Bp[(size_t)(2 * kk) * 128 + n];
            float v1 = Bp[(size_t)(2 * kk + 1) * 128 + n];
            uint32_t hi, lo; splitH(v0, v1, hi, lo);
            sH[kk * PITCH + m * 32 + n] = hi;
            sL[kk * PITCH + m * 32 + n] = lo;
        }
    }
    stage_nlin(sH2, sL2, na, tid);
    __syncthreads();

    int lane = tid & 31;
    int gid = lane >> 2, tig = lane & 3;
    int gw = blockIdx.x * 8 + (tid >> 5);
    int nw = gridDim.x * 8;
    float* p_atom = (float*)ga.out[0];
    float* p_h    = (float*)ga.out2[0];

    for (int t = gw; t < (NN >> 4); t += nw) {
        const float* Ap = ga.A + (size_t)(t * 16) * 128;
        float d[16][4];
#pragma unroll
        for (int nt = 0; nt < 16; nt++) {
            d[nt][0] = 0.f; d[nt][1] = 0.f; d[nt][2] = 0.f; d[nt][3] = 0.f;
        }
#pragma unroll 2
        for (int kc = 0; kc < 8; kc++) {
            float2 p0 = *(const float2*)(Ap + (size_t)gid * 128 + kc * 16 + 2 * tig);
            float2 p1 = *(const float2*)(Ap + (size_t)(gid + 8) * 128 + kc * 16 + 2 * tig);
            float2 p2 = *(const float2*)(Ap + (size_t)gid * 128 + kc * 16 + 2 * tig + 8);
            float2 p3 = *(const float2*)(Ap + (size_t)(gid + 8) * 128 + kc * 16 + 2 * tig + 8);
            uint32_t ah[4], al[4];
            splitH(p0.x, p0.y, ah[0], al[0]);
            splitH(p1.x, p1.y, ah[1], al[1]);
            splitH(p2.x, p2.y, ah[2], al[2]);
            splitH(p3.x, p3.y, ah[3], al[3]);
            int krow = (kc * 8 + tig) * PITCH + gid;
#pragma unroll
            for (int nt = 0; nt < 16; nt++) {
                int i0 = krow + nt * 8;
                uint32_t bh0 = sH[i0], bh1 = sH[i0 + 4 * PITCH];
                uint32_t bl0 = sL[i0], bl1 = sL[i0 + 4 * PITCH];
                mma16(d[nt], ah, bh0, bh1);
                mma16(d[nt], ah, bl0, bl1);
                mma16(d[nt], al, bh0, bh1);
            }
        }
        int ra = t * 16 + gid, rb = ra + 8;
#pragma unroll
        for (int nt = 0; nt < 16; nt++) {
            int m = nt >> 2;
            int c = (nt & 3) * 8 + 2 * tig;
            float b0 = ga.bias[m][c], b1 = ga.bias[m][c + 1];
            float o0 = fmaxf(d[nt][0] + b0, 0.f);
            float o1 = fmaxf(d[nt][1] + b1, 0.f);
            float o2 = fmaxf(d[nt][2] + b0, 0.f);
            float o3 = fmaxf(d[nt][3] + b1, 0.f);
            size_t ia = (size_t)ra * 128 + m * 32 + c;
            size_t ib = (size_t)rb * 128 + m * 32 + c;
            *(float2*)&p_atom[ia] = make_float2(o0, o1);
            *(float2*)&p_atom[ib] = make_float2(o2, o3);
            *(float2*)&p_h[ia]    = make_float2(o0, o1);
            *(float2*)&p_h[ib]    = make_float2(o2, o3);
            d[nt][0] = o0; d[nt][1] = o1; d[nt][2] = o2; d[nt][3] = o3;
        }
#pragma unroll
        for (int m = 0; m < 4; m++)
            nlin_on_tile(&d[m * 4], sH2, sL2, na, ra * 4 + m, rb * 4 + m, lane);
    }
}

// ============================================================================
// k_combf: layer-0 comb + fused layer-1 node linears
// ============================================================================
__global__ void __launch_bounds__(256) k_combf(GArgs ga, NArgs na) {
    extern __shared__ uint32_t sB[];
    constexpr int PITCH = 40;   // NM=1
    constexpr int KK = 16;
    uint32_t* sH = sB;
    uint32_t* sL = sB + KK * PITCH;
    uint32_t* sH2 = sB + 2 * KK * PITCH;
    uint32_t* sL2 = sH2 + 16 * PITCHN;
    int tid = threadIdx.x;

    {
        const float* Bp = ga.B[0];
        for (int i = tid; i < KK * 32; i += 256) {
            int kk = i >> 5, n = i & 31;
            float v0 = Bp[(2 * kk) * 32 + n];
            float v1 = Bp[(2 * kk + 1) * 32 + n];
            uint32_t hi, lo; splitH(v0, v1, hi, lo);
            sH[kk * PITCH + n] = hi;
            sL[kk * PITCH + n] = lo;
        }
    }
    stage_nlin(sH2, sL2, na, tid);
    __syncthreads();

    int lane = tid & 31;
    int gid = lane >> 2, tig = lane & 3;
    int gw = blockIdx.x * 8 + (tid >> 5);
    int nw = gridDim.x * 8;
    float* hout = (float*)ga.out[0];

    for (int t = gw; t < (ROWS >> 4); t += nw) {
        const float* Ap = ga.A + (size_t)(t * 16) * 32;
        float d[4][4];
#pragma unroll
        for (int nt = 0; nt < 4; nt++) {
            d[nt][0] = 0.f; d[nt][1] = 0.f; d[nt][2] = 0.f; d[nt][3] = 0.f;
        }
#pragma unroll
        for (int kc = 0; kc < 2; kc++) {
            float2 p0 = *(const float2*)(Ap + (size_t)gid * 32 + kc * 16 + 2 * tig);
            float2 p1 = *(const float2*)(Ap + (size_t)(gid + 8) * 32 + kc * 16 + 2 * tig);
            float2 p2 = *(const float2*)(Ap + (size_t)gid * 32 + kc * 16 + 2 * tig + 8);
            float2 p3 = *(const float2*)(Ap + (size_t)(gid + 8) * 32 + kc * 16 + 2 * tig + 8);
            uint32_t ah[4], al[4];
            splitH(p0.x, p0.y, ah[0], al[0]);
            splitH(p1.x, p1.y, ah[1], al[1]);
            splitH(p2.x, p2.y, ah[2], al[2]);
            splitH(p3.x, p3.y, ah[3], al[3]);
            int krow = (kc * 8 + tig) * PITCH + gid;
#pragma unroll
            for (int nt = 0; nt < 4; nt++) {
                int i0 = krow + nt * 8;
                uint32_t bh0 = sH[i0], bh1 = sH[i0 + 4 * PITCH];
                uint32_t bl0 = sL[i0], bl1 = sL[i0 + 4 * PITCH];
                mma16(d[nt], ah, bh0, bh1);
                mma16(d[nt], ah, bl0, bl1);
                mma16(d[nt], al, bh0, bh1);
            }
        }
        int ra = t * 16 + gid, rb = ra + 8;
#pragma unroll
        for (int nt = 0; nt < 4; nt++) {
            int c = nt * 8 + 2 * tig;
            float b0 = ga.bias[0][c], b1 = ga.bias[0][c + 1];
            int ia = ra * 32 + c, ib = rb * 32 + c;
            float o0 = fmaxf(d[nt][0] + b0 + g_aggr[ia]     + g_atom[ia],     0.f);
            float o1 = fmaxf(d[nt][1] + b1 + g_aggr[ia + 1] + g_atom[ia + 1], 0.f);
            float o2 = fmaxf(d[nt][2] + b0 + g_aggr[ib]     + g_atom[ib],     0.f);
            float o3 = fmaxf(d[nt][3] + b1 + g_aggr[ib + 1] + g_atom[ib + 1], 0.f);
            *(float2*)&hout[ia] = make_float2(o0, o1);
            *(float2*)&hout[ib] = make_float2(o2, o3);
            d[nt][0] = o0; d[nt][1] = o1; d[nt][2] = o2; d[nt][3] = o3;
        }
        nlin_on_tile(d, sH2, sL2, na, ra, rb, lane);
    }
}

// ---- zero aggr/nsum (per layer) ----
__global__ void k_init() {
    int i = blockIdx.x * blockDim.x + threadIdx.x;
    int stride = gridDim.x * blockDim.x;
    for (int j = i; j < ROWS * F / 4; j += stride)
        ((float4*)g_aggr)[j] = make_float4(0.f, 0.f, 0.f, 0.f);
    for (int j = i; j < NN; j += stride)
        g_nsum[j] = 0.f;
}

// ---- edge attention: half2 math, lean softmax tail, 4-edge unroll ----
__global__ void k_attn(const int* __restrict__ ei, const __half* __restrict__ ea_p,
                       const float* __restrict__ dw, const float* __restrict__ db) {
    int lane = threadIdx.x & 31;
    int q = lane & 7;
    float4 dwf = ((const float4*)dw)[q];
    __half2 dw01 = __floats2half2_rn(dwf.x, dwf.y);
    __half2 dw23 = __floats2half2_rn(dwf.z, dwf.w);
    __half2 z2 = __floats2half2_rn(0.f, 0.f);
    float dbv = db[0];
    int gw = (blockIdx.x * blockDim.x + threadIdx.x) >> 5;
    int nw = (gridDim.x * blockDim.x) >> 5;
    for (int e0 = gw * 4; e0 < NE; e0 += nw * 4) {   // NE % 4 == 0
        int s[4], dd[4];
#pragma unroll
        for (int k = 0; k < 4; k++) {
            s[k]  = __ldg(ei + e0 + k);
            dd[k] = __ldg(ei + NE + e0 + k);
        }
        float v[4];
#pragma unroll
        for (int k = 0; k < 4; k++) {
            // 32-bit offsets: all arrays < 2^24 elements
            uint2 ua = *(const uint2*)(g_xs + dd[k] * 128 + lane * 4);
            uint2 uc = *(const uint2*)(g_xd + s[k]  * 128 + lane * 4);
            uint2 ue = *(const uint2*)(ea_p + (e0 + k) * 32 + q * 4);
            __half2 s01 = __hadd2(*(__half2*)&ua.x, *(__half2*)&uc.x);
            __half2 s23 = __hadd2(*(__half2*)&ua.y, *(__half2*)&uc.y);
            s01 = __hmax2(__hadd2(s01, *(__half2*)&ue.x), z2);
            s23 = __hmax2(__hadd2(s23, *(__half2*)&ue.y), z2);
            __half2 p = __hfma2(s01, dw01, __hmul2(s23, dw23));
            float2 pf = __half22float2(p);
            v[k] = pf.x + pf.y;
        }
#pragma unroll
        for (int k = 0; k < 4; k++) {
            v[k] += __shfl_xor_sync(FULL, v[k], 4);
            v[k] += __shfl_xor_sync(FULL, v[k], 2);
            v[k] += __shfl_xor_sync(FULL, v[k], 1);
        }
        // broadcast: b[k] = score(edge k, head lane&3)
        float b0 = __shfl_sync(FULL, v[0], (lane & 3) * 8);
        float b1 = __shfl_sync(FULL, v[1], (lane & 3) * 8);
        float b2 = __shfl_sync(FULL, v[2], (lane & 3) * 8);
        float b3 = __shfl_sync(FULL, v[3], (lane & 3) * 8);
        // lane l owns (edge kk = (l>>2)&3, head l&3): ONE exp per lane
        int kk = (lane >> 2) & 3;
        float sel = (kk == 0) ? b0 : (kk == 1) ? b1 : (kk == 2) ? b2 : b3;
        float ex1 = __expf(sel + dbv);
        float t = ex1 + __shfl_xor_sync(FULL, ex1, 1);
        t += __shfl_xor_sync(FULL, t, 2);
        if (lane < 16) {
            g_exp[(e0 + kk) * 4 + (lane & 3)] = ex1;
            if ((lane & 3) == 0)
                atomicAdd(&g_nsum[dd[kk]], t);
        }
    }
}

// ---- messages + tiled scatter; 2-group unroll, half2 adds, 32-bit addr ----
__global__ void k_msg(const int* __restrict__ ei, const __half* __restrict__ em_p) {
    int lane = threadIdx.x & 31;
    int q = lane & 7;
    int j = lane >> 3;
    int gw = (blockIdx.x * blockDim.x + threadIdx.x) >> 5;
    int nw = (gridDim.x * blockDim.x) >> 5;
    for (int g0 = gw * 2; g0 < NG; g0 += nw * 2) {   // NG even
        int g1 = g0 + 1;
        float4 T0 = make_float4(0.f, 0.f, 0.f, 0.f);
        float4 T1 = make_float4(0.f, 0.f, 0.f, 0.f);
#pragma unroll
        for (int c = 0; c < 4; c++) {
            int e0 = c * NG + g0;
            int e1 = c * NG + g1;
            int d0 = __ldg(ei + NE + e0);
            int d1 = __ldg(ei + NE + e1);
            float4 ex0 = ((const float4*)g_exp)[e0];
            float4 ex1 = ((const float4*)g_exp)[e1];
            float inv0 = 1.f / (g_nsum[d0] + 1e-8f);
            float inv1 = 1.f / (g_nsum[d1] + 1e-8f);
            float eh0 = (j == 0) ? ex0.x : (j == 1) ? ex0.y : (j == 2) ? ex0.z : ex0.w;
            float eh1 = (j == 0) ? ex1.x : (j == 1) ? ex1.y : (j == 2) ? ex1.z : ex1.w;
            float s0 = eh0 * inv0;
            float s1 = eh1 * inv1;
            uint2 uxm0 = *(const uint2*)(g_xm + d0 * 128 + lane * 4);
            uint2 uxm1 = *(const uint2*)(g_xm + d1 * 128 + lane * 4);
            uint2 uem0 = *(const uint2*)(em_p + e0 * 32 + q * 4);
            uint2 uem1 = *(const uint2*)(em_p + e1 * 32 + q * 4);
            __half2 m0a = __hadd2(*(__half2*)&uxm0.x, *(__half2*)&uem0.x);
            __half2 m0b = __hadd2(*(__half2*)&uxm0.y, *(__half2*)&uem0.y);
            __half2 m1a = __hadd2(*(__half2*)&uxm1.x, *(__half2*)&uem1.x);
            __half2 m1b = __hadd2(*(__half2*)&uxm1.y, *(__half2*)&uem1.y);
            float2 f0a = __half22float2(m0a), f0b = __half22float2(m0b);
            float2 f1a = __half22float2(m1a), f1b = __half22float2(m1b);
            T0.x += s0 * f0a.x; T0.y += s0 * f0a.y;
            T0.z += s0 * f0b.x; T0.w += s0 * f0b.y;
            T1.x += s1 * f1a.x; T1.y += s1 * f1a.y;
            T1.z += s1 * f1b.x; T1.w += s1 * f1b.y;
        }
        int tgt0 = __ldg(ei + NE + 4 * g0 + j);
        int tgt1 = __ldg(ei + NE + 4 * g1 + j);
        float* p0 = g_aggr + tgt0 * 32 + q * 4;
        float* p1 = g_aggr + tgt1 * 32 + q * 4;
        asm volatile("red.global.add.v4.f32 [%0], {%1,%2,%3,%4};"
                     :: "l"(p0), "f"(T0.x), "f"(T0.y), "f"(T0.z), "f"(T0.w)
                     : "memory");
        asm volatile("red.global.add.v4.f32 [%0], {%1,%2,%3,%4};"
                     :: "l"(p1), "f"(T1.x), "f"(T1.y), "f"(T1.z), "f"(T1.w)
                     : "memory");
    }
}

extern "C" void kernel_launch(void* const* d_in, const int* in_sizes, int n_in,
                              void* d_out, int out_size) {
    const float* x      = (const float*)d_in[0];
    const float* eattr  = (const float*)d_in[1];
    const int*   ei     = (const int*)d_in[2];
    const float* atom_w = (const float*)d_in[3];
    const float* atom_b = (const float*)d_in[4];
    const float* asw  = (const float*)d_in[5];
    const float* asb  = (const float*)d_in[6];
    const float* adw  = (const float*)d_in[7];
    const float* adb  = (const float*)d_in[8];
    const float* aew  = (const float*)d_in[9];
    const float* aeb  = (const float*)d_in[10];
    const float* dotw = (const float*)d_in[11];
    const float* dotb = (const float*)d_in[12];
    const float* mdw  = (const float*)d_in[13];
    const float* mdb  = (const float*)d_in[14];
    const float* mew  = (const float*)d_in[15];
    const float* meb  = (const float*)d_in[16];
    const float* wnw  = (const float*)d_in[17];
    const float* wnb  = (const float*)d_in[18];
    float* out = (float*)d_out;

    float *p_h, *p_atom;
    __half *p_xs, *p_xd, *p_xm, *p_ea, *p_em, *p_ea2, *p_em2;
    cudaGetSymbolAddress((void**)&p_h,    g_h);
    cudaGetSymbolAddress((void**)&p_atom, g_atom);
    cudaGetSymbolAddress((void**)&p_xs,   g_xs);
    cudaGetSymbolAddress((void**)&p_xd,   g_xd);
    cudaGetSymbolAddress((void**)&p_xm,   g_xm);
    cudaGetSymbolAddress((void**)&p_ea,   g_ea);
    cudaGetSymbolAddress((void**)&p_em,   g_em);
    cudaGetSymbolAddress((void**)&p_ea2,  g_ea2);
    cudaGetSymbolAddress((void**)&p_em2,  g_em2);

    const int smem_atomf = (2 * 64 * 136 + 2 * 16 * PITCHN) * 4;  // 82944
    const int smem_combf = (2 * 16 * 40 + 2 * 16 * PITCHN) * 4;   // 18432
    const int smem_e4    = 2 * 16 * (4 * 32 + 8) * 4;             // 17408
    const int smem_c1    = 2 * 16 * (1 * 32 + 8) * 4;             // 5120
    cudaFuncSetAttribute(k_atomf,
                         cudaFuncAttributeMaxDynamicSharedMemorySize, smem_atomf);

    k_init<<<512, 256>>>();   // nsum/aggr for layer 0

    // atom + fused layer-0 node linears
    {
        GArgs ga;
        ga.A = x; ga.M = NN; ga.Astride = 128; ga.Bstride = 128; ga.Ostride = 128;
        for (int m = 0; m < 4; m++) {
            ga.B[m]    = atom_w + m * 32;
            ga.bias[m] = atom_b + m * 32;
        }
        ga.out[0] = p_atom; ga.out2[0] = p_h;
        NArgs na;
        na.W[0] = asw; na.W[1] = adw; na.W[2] = mdw;
        na.bias[0] = asb; na.bias[1] = adb; na.bias[2] = mdb;
        na.out[0] = p_xs; na.out[1] = p_xd; na.out[2] = p_xm;
        k_atomf<<<296, 256, smem_atomf>>>(ga, na);
    }

    // elin both layers in ONE pass over eattr: ea0, em0, ea1, em1 (fp16 out)
    {
        GArgs ge;
        ge.A = eattr; ge.M = NE; ge.Astride = 32; ge.Bstride = 32; ge.Ostride = 32;
        ge.B[0] = aew;        ge.B[1] = mew;        ge.B[2] = aew + 1024; ge.B[3] = mew + 1024;
        ge.bias[0] = aeb;     ge.bias[1] = meb;     ge.bias[2] = aeb + 32; ge.bias[3] = meb + 32;
        ge.out[0] = p_ea; ge.out[1] = p_em; ge.out[2] = p_ea2; ge.out[3] = p_em2;
        for (int m = 0; m < 4; m++) ge.out2[m] = p_ea;
        k_g<4, 2, 0, 1><<<444, 256, smem_e4>>>(ge);
    }

    // ---- layer 0 edge phase ----
    k_attn<<<740, 256>>>(ei, p_ea, dotw, dotb);
    k_msg<<<740, 256>>>(ei, p_em);

    // comb(l0) + fused layer-1 node linears
    {
        GArgs gc;
        gc.A = p_h; gc.M = ROWS; gc.Astride = 32; gc.Bstride = 32; gc.Ostride = 32;
        gc.B[0] = wnw; gc.bias[0] = wnb;
        gc.out[0] = p_h;
        NArgs na;
        na.W[0] = asw + 1024; na.W[1] = adw + 1024; na.W[2] = mdw + 1024;
        na.bias[0] = asb + 32; na.bias[1] = adb + 32; na.bias[2] = mdb + 32;
        na.out[0] = p_xs; na.out[1] = p_xd; na.out[2] = p_xm;
        k_combf<<<444, 256, smem_combf>>>(gc, na);
    }

    k_init<<<512, 256>>>();   // nsum/aggr for layer 1

    // ---- layer 1 edge phase ----
    k_attn<<<740, 256>>>(ei, p_ea2, dotw + 32, dotb + 1);
    k_msg<<<740, 256>>>(ei, p_em2);

    // final comb + head-mean -> out
    {
        GArgs gc;
        gc.A = p_h; gc.M = ROWS; gc.Astride = 32; gc.Bstride = 32; gc.Ostride = 32;
        gc.B[0] = wnw + 1024; gc.B[1] = gc.B[2] = gc.B[3] = gc.B[0];
        gc.bias[0] = wnb + 32; gc.bias[1] = gc.bias[2] = gc.bias[3] = gc.bias[0];
        gc.out[0] = out; gc.out[1] = gc.out[2] = gc.out[3] = out;
        gc.out2[0] = gc.out2[1] = gc.out2[2] = gc.out2[3] = p_h;
        k_g<1, 2, 3, 0><<<444, 256, smem_c1>>>(gc);
    }
}

// round 16
// speedup vs baseline: 1.3997x; 1.0175x over previous
#include <cuda_runtime.h>
#include <cuda_fp16.h>
#include <cstdint>

#define FULL 0xffffffffu

constexpr int NN   = 50000;
constexpr int NE   = 400000;
constexpr int F    = 32;
constexpr int H    = 4;
constexpr int ROWS = NN * H;        // 200000 (n,h) rows
constexpr int NG   = NE / H;        // 100000 message groups

// ---- scratch (device globals; no allocation allowed) ----
__device__ float    g_h[ROWS * F];
__device__ float    g_atom[ROWS * F];
__device__ __half   g_xs[ROWS * F];
__device__ __half   g_xd[ROWS * F];
__device__ __half   g_xm[ROWS * F];
__device__ __half   g_ea[NE * F];       // layer 0
__device__ __half   g_em[NE * F];
__device__ __half   g_ea2[NE * F];      // layer 1
__device__ __half   g_em2[NE * F];
__device__ float    g_exp[NE * H];
__device__ float    g_nsum[NN];
__device__ float    g_aggr[ROWS * F];

__device__ __forceinline__ void mma16(float d[4], const uint32_t a[4],
                                      uint32_t b0, uint32_t b1) {
    asm("mma.sync.aligned.m16n8k16.row.col.f32.f16.f16.f32 "
        "{%0,%1,%2,%3}, {%4,%5,%6,%7}, {%8,%9}, {%0,%1,%2,%3};"
        : "+f"(d[0]), "+f"(d[1]), "+f"(d[2]), "+f"(d[3])
        : "r"(a[0]), "r"(a[1]), "r"(a[2]), "r"(a[3]), "r"(b0), "r"(b1));
}

// split fp32 pair -> fp16 hi + fp16 residual lo (packed half2 as u32)
__device__ __forceinline__ void splitH(float x, float y,
                                       uint32_t& hi, uint32_t& lo) {
    __half2 h = __floats2half2_rn(x, y);
    float2 hf = __half22float2(h);
    __half2 l = __floats2half2_rn(x - hf.x, y - hf.y);
    hi = *(uint32_t*)&h;
    lo = *(uint32_t*)&l;
}

struct GArgs {
    const float* A;
    const float* B[4];
    const float* bias[4];
    void*        out[4];
    void*        out2[4];
    int          M;
    int          Astride;
    int          Bstride;
    int          Ostride;
};

// ---- fused node-linear stage (xs/xd/xm GEMM on an in-register h tile) ----
constexpr int PITCHN = 3 * 32 + 8;   // 104, % 32 == 8 -> conflict-free

struct NArgs {
    const float* W[3];
    const float* bias[3];
    __half*      out[3];
};

__device__ __forceinline__ void stage_nlin(uint32_t* sH2, uint32_t* sL2,
                                           const NArgs& na, int tid) {
    for (int m = 0; m < 3; m++) {
        const float* Bp = na.W[m];
        for (int i = tid; i < 16 * 32; i += 256) {
            int kk = i >> 5, n = i & 31;
            float v0 = Bp[(2 * kk) * 32 + n];
            float v1 = Bp[(2 * kk + 1) * 32 + n];
            uint32_t hi, lo; splitH(v0, v1, hi, lo);
            sH2[kk * PITCHN + m * 32 + n] = hi;
            sL2[kk * PITCHN + m * 32 + n] = lo;
        }
    }
}

__device__ __forceinline__ void nlin_on_tile(const float (*hh)[4],
        const uint32_t* sH2, const uint32_t* sL2, const NArgs& na,
        int ra, int rb, int lane) {
    int gid = lane >> 2, tig = lane & 3;
    float d2[12][4];
#pragma unroll
    for (int nt = 0; nt < 12; nt++) {
        d2[nt][0] = 0.f; d2[nt][1] = 0.f; d2[nt][2] = 0.f; d2[nt][3] = 0.f;
    }
#pragma unroll
    for (int kc = 0; kc < 2; kc++) {
        uint32_t ah[4], al[4];
        splitH(hh[kc*2][0],   hh[kc*2][1],   ah[0], al[0]);
        splitH(hh[kc*2][2],   hh[kc*2][3],   ah[1], al[1]);
        splitH(hh[kc*2+1][0], hh[kc*2+1][1], ah[2], al[2]);
        splitH(hh[kc*2+1][2], hh[kc*2+1][3], ah[3], al[3]);
        int krow = (kc * 8 + tig) * PITCHN + gid;
#pragma unroll
        for (int nt = 0; nt < 12; nt++) {
            int i0 = krow + nt * 8;
            uint32_t bh0 = sH2[i0], bh1 = sH2[i0 + 4 * PITCHN];
            uint32_t bl0 = sL2[i0], bl1 = sL2[i0 + 4 * PITCHN];
            mma16(d2[nt], ah, bh0, bh1);
            mma16(d2[nt], ah, bl0, bl1);
            mma16(d2[nt], al, bh0, bh1);
        }
    }
#pragma unroll
    for (int nt = 0; nt < 12; nt++) {
        int m = nt >> 2;
        int c = (nt & 3) * 8 + 2 * tig;
        float b0 = na.bias[m][c], b1 = na.bias[m][c + 1];
        __half* op = na.out[m];
        *(__half2*)&op[(size_t)ra * 32 + c] =
            __floats2half2_rn(d2[nt][0] + b0, d2[nt][1] + b1);
        *(__half2*)&op[(size_t)rb * 32 + c] =
            __floats2half2_rn(d2[nt][2] + b0, d2[nt][3] + b1);
    }
}

// ============================================================================
// generic gemm (elin and final comb)
// ============================================================================
template<int NM, int KC16, int MODE, int OUTH>
__device__ __forceinline__ void gemm_body(const GArgs& ga, uint32_t* sB,
                                          int bid, int nblocks, int tid) {
    constexpr int NT = NM * 4;
    constexpr int PITCH = NM * 32 + 8;
    constexpr int KK = KC16 * 8;
    uint32_t* sH = sB;
    uint32_t* sL = sB + KK * PITCH;

    for (int m = 0; m < NM; m++) {
        const float* Bp = ga.B[m];
        for (int i = tid; i < KK * 32; i += 256) {
            int kk = i >> 5, n = i & 31;
            float v0 = Bp[(size_t)(2 * kk)     * ga.Bstride + n];
            float v1 = Bp[(size_t)(2 * kk + 1) * ga.Bstride + n];
            uint32_t hi, lo;
            splitH(v0, v1, hi, lo);
            sH[kk * PITCH + m * 32 + n] = hi;
            sL[kk * PITCH + m * 32 + n] = lo;
        }
    }
    __syncthreads();

    int lane = tid & 31;
    int gid = lane >> 2, tig = lane & 3;
    int gw = bid * 8 + (tid >> 5);
    int nw = nblocks * 8;
    int ntile = ga.M >> 4;
    const int As = ga.Astride;

    for (int t = gw; t < ntile; t += nw) {
        const float* Ap = ga.A + (size_t)(t * 16) * As;
        float d[NT][4];
#pragma unroll
        for (int nt = 0; nt < NT; nt++) {
            d[nt][0] = 0.f; d[nt][1] = 0.f; d[nt][2] = 0.f; d[nt][3] = 0.f;
        }
#pragma unroll 2
        for (int kc = 0; kc < KC16; kc++) {
            float2 p0 = *(const float2*)(Ap + (size_t)gid * As + kc * 16 + 2 * tig);
            float2 p1 = *(const float2*)(Ap + (size_t)(gid + 8) * As + kc * 16 + 2 * tig);
            float2 p2 = *(const float2*)(Ap + (size_t)gid * As + kc * 16 + 2 * tig + 8);
            float2 p3 = *(const float2*)(Ap + (size_t)(gid + 8) * As + kc * 16 + 2 * tig + 8);
            uint32_t ah[4], al[4];
            splitH(p0.x, p0.y, ah[0], al[0]);
            splitH(p1.x, p1.y, ah[1], al[1]);
            splitH(p2.x, p2.y, ah[2], al[2]);
            splitH(p3.x, p3.y, ah[3], al[3]);
            int krow = (kc * 8 + tig) * PITCH + gid;
#pragma unroll
            for (int nt = 0; nt < NT; nt++) {
                int i0 = krow + nt * 8;
                uint32_t bh0 = sH[i0], bh1 = sH[i0 + 4 * PITCH];
                uint32_t bl0 = sL[i0], bl1 = sL[i0 + 4 * PITCH];
                mma16(d[nt], ah, bh0, bh1);
                mma16(d[nt], ah, bl0, bl1);
                mma16(d[nt], al, bh0, bh1);
            }
        }
        int ra = t * 16 + gid, rb = ra + 8;
#pragma unroll
        for (int nt = 0; nt < NT; nt++) {
            const int m = nt >> 2;
            int c = (nt & 3) * 8 + 2 * tig;
            float b0 = ga.bias[m][c], b1 = ga.bias[m][c + 1];
            float o0 = d[nt][0] + b0, o1 = d[nt][1] + b1;
            float o2 = d[nt][2] + b0, o3 = d[nt][3] + b1;
            if (MODE >= 2) {
                int ia = ra * 32 + c, ib = rb * 32 + c;
                o0 += g_aggr[ia]     + g_atom[ia];
                o1 += g_aggr[ia + 1] + g_atom[ia + 1];
                o2 += g_aggr[ib]     + g_atom[ib];
                o3 += g_aggr[ib + 1] + g_atom[ib + 1];
            }
            if (MODE != 0) {
                o0 = fmaxf(o0, 0.f); o1 = fmaxf(o1, 0.f);
                o2 = fmaxf(o2, 0.f); o3 = fmaxf(o3, 0.f);
            }
            if (MODE == 3) {
                float s0 = o0 + __shfl_xor_sync(FULL, o0, 4);
                s0 += __shfl_xor_sync(FULL, s0, 8);
                float s1 = o1 + __shfl_xor_sync(FULL, o1, 4);
                s1 += __shfl_xor_sync(FULL, s1, 8);
                float s2 = o2 + __shfl_xor_sync(FULL, o2, 4);
                s2 += __shfl_xor_sync(FULL, s2, 8);
                float s3 = o3 + __shfl_xor_sync(FULL, o3, 4);
                s3 += __shfl_xor_sync(FULL, s3, 8);
                if ((gid & 3) == 0) {
                    float* op = (float*)ga.out[0];
                    int na = ra >> 2;
                    int nb = rb >> 2;
                    *(float2*)&op[na * 32 + c] = make_float2(0.25f*s0, 0.25f*s1);
                    *(float2*)&op[nb * 32 + c] = make_float2(0.25f*s2, 0.25f*s3);
                }
                continue;
            }
            size_t ia = (size_t)ra * ga.Ostride + c;
            size_t ib = (size_t)rb * ga.Ostride + c;
            if (OUTH) {
                __half* op = (__half*)ga.out[m];
                *(__half2*)&op[ia] = __floats2half2_rn(o0, o1);
                *(__half2*)&op[ib] = __floats2half2_rn(o2, o3);
            } else {
                float* op = (float*)ga.out[m];
                *(float2*)&op[ia] = make_float2(o0, o1);
                *(float2*)&op[ib] = make_float2(o2, o3);
                if (MODE == 1) {
                    float* op2 = (float*)ga.out2[m];
                    *(float2*)&op2[ia] = make_float2(o0, o1);
                    *(float2*)&op2[ib] = make_float2(o2, o3);
                }
            }
        }
    }
}

template<int NM, int KC16, int MODE, int OUTH>
__global__ void __launch_bounds__(256) k_g(GArgs ga) {
    extern __shared__ uint32_t sB[];
    gemm_body<NM, KC16, MODE, OUTH>(ga, sB, blockIdx.x, gridDim.x, threadIdx.x);
}

// ============================================================================
// k_atomf: atom GEMM + relu + dual write + fused layer-0 node linears
// ============================================================================
__global__ void __launch_bounds__(256) k_atomf(GArgs ga, NArgs na) {
    extern __shared__ uint32_t sB[];
    constexpr int PITCH = 4 * 32 + 8;   // 136
    constexpr int KK = 64;              // K=128
    uint32_t* sH = sB;
    uint32_t* sL = sB + KK * PITCH;
    uint32_t* sH2 = sB + 2 * KK * PITCH;
    uint32_t* sL2 = sH2 + 16 * PITCHN;
    int tid = threadIdx.x;

    for (int m = 0; m < 4; m++) {
        const float* Bp = ga.B[m];
        for (int i = tid; i < KK * 32; i += 256) {
            int kk = i >> 5, n = i & 31;
            float v0 = Bp[(size_t)(2 * kk) * 128 + n];
            float v1 = Bp[(size_t)(2 * kk + 1) * 128 + n];
            uint32_t hi, lo; splitH(v0, v1, hi, lo);
            sH[kk * PITCH + m * 32 + n] = hi;
            sL[kk * PITCH + m * 32 + n] = lo;
        }
    }
    stage_nlin(sH2, sL2, na, tid);
    __syncthreads();

    int lane = tid & 31;
    int gid = lane >> 2, tig = lane & 3;
    int gw = blockIdx.x * 8 + (tid >> 5);
    int nw = gridDim.x * 8;
    float* p_atom = (float*)ga.out[0];
    float* p_h    = (float*)ga.out2[0];

    for (int t = gw; t < (NN >> 4); t += nw) {
        const float* Ap = ga.A + (size_t)(t * 16) * 128;
        float d[16][4];
#pragma unroll
        for (int nt = 0; nt < 16; nt++) {
            d[nt][0] = 0.f; d[nt][1] = 0.f; d[nt][2] = 0.f; d[nt][3] = 0.f;
        }
#pragma unroll 2
        for (int kc = 0; kc < 8; kc++) {
            float2 p0 = *(const float2*)(Ap + (size_t)gid * 128 + kc * 16 + 2 * tig);
            float2 p1 = *(const float2*)(Ap + (size_t)(gid + 8) * 128 + kc * 16 + 2 * tig);
            float2 p2 = *(const float2*)(Ap + (size_t)gid * 128 + kc * 16 + 2 * tig + 8);
            float2 p3 = *(const float2*)(Ap + (size_t)(gid + 8) * 128 + kc * 16 + 2 * tig + 8);
            uint32_t ah[4], al[4];
            splitH(p0.x, p0.y, ah[0], al[0]);
            splitH(p1.x, p1.y, ah[1], al[1]);
            splitH(p2.x, p2.y, ah[2], al[2]);
            splitH(p3.x, p3.y, ah[3], al[3]);
            int krow = (kc * 8 + tig) * PITCH + gid;
#pragma unroll
            for (int nt = 0; nt < 16; nt++) {
                int i0 = krow + nt * 8;
                uint32_t bh0 = sH[i0], bh1 = sH[i0 + 4 * PITCH];
                uint32_t bl0 = sL[i0], bl1 = sL[i0 + 4 * PITCH];
                mma16(d[nt], ah, bh0, bh1);
                mma16(d[nt], ah, bl0, bl1);
                mma16(d[nt], al, bh0, bh1);
            }
        }
        int ra = t * 16 + gid, rb = ra + 8;
#pragma unroll
        for (int nt = 0; nt < 16; nt++) {
            int m = nt >> 2;
            int c = (nt & 3) * 8 + 2 * tig;
            float b0 = ga.bias[m][c], b1 = ga.bias[m][c + 1];
            float o0 = fmaxf(d[nt][0] + b0, 0.f);
            float o1 = fmaxf(d[nt][1] + b1, 0.f);
            float o2 = fmaxf(d[nt][2] + b0, 0.f);
            float o3 = fmaxf(d[nt][3] + b1, 0.f);
            size_t ia = (size_t)ra * 128 + m * 32 + c;
            size_t ib = (size_t)rb * 128 + m * 32 + c;
            *(float2*)&p_atom[ia] = make_float2(o0, o1);
            *(float2*)&p_atom[ib] = make_float2(o2, o3);
            *(float2*)&p_h[ia]    = make_float2(o0, o1);
            *(float2*)&p_h[ib]    = make_float2(o2, o3);
            d[nt][0] = o0; d[nt][1] = o1; d[nt][2] = o2; d[nt][3] = o3;
        }
#pragma unroll
        for (int m = 0; m < 4; m++)
            nlin_on_tile(&d[m * 4], sH2, sL2, na, ra * 4 + m, rb * 4 + m, lane);
    }
}

// ============================================================================
// k_combf: layer-0 comb + fused layer-1 node linears
// ============================================================================
__global__ void __launch_bounds__(256) k_combf(GArgs ga, NArgs na) {
    extern __shared__ uint32_t sB[];
    constexpr int PITCH = 40;   // NM=1
    constexpr int KK = 16;
    uint32_t* sH = sB;
    uint32_t* sL = sB + KK * PITCH;
    uint32_t* sH2 = sB + 2 * KK * PITCH;
    uint32_t* sL2 = sH2 + 16 * PITCHN;
    int tid = threadIdx.x;

    {
        const float* Bp = ga.B[0];
        for (int i = tid; i < KK * 32; i += 256) {
            int kk = i >> 5, n = i & 31;
            float v0 = Bp[(2 * kk) * 32 + n];
            float v1 = Bp[(2 * kk + 1) * 32 + n];
            uint32_t hi, lo; splitH(v0, v1, hi, lo);
            sH[kk * PITCH + n] = hi;
            sL[kk * PITCH + n] = lo;
        }
    }
    stage_nlin(sH2, sL2, na, tid);
    __syncthreads();

    int lane = tid & 31;
    int gid = lane >> 2, tig = lane & 3;
    int gw = blockIdx.x * 8 + (tid >> 5);
    int nw = gridDim.x * 8;
    float* hout = (float*)ga.out[0];

    for (int t = gw; t < (ROWS >> 4); t += nw) {
        const float* Ap = ga.A + (size_t)(t * 16) * 32;
        float d[4][4];
#pragma unroll
        for (int nt = 0; nt < 4; nt++) {
            d[nt][0] = 0.f; d[nt][1] = 0.f; d[nt][2] = 0.f; d[nt][3] = 0.f;
        }
#pragma unroll
        for (int kc = 0; kc < 2; kc++) {
            float2 p0 = *(const float2*)(Ap + (size_t)gid * 32 + kc * 16 + 2 * tig);
            float2 p1 = *(const float2*)(Ap + (size_t)(gid + 8) * 32 + kc * 16 + 2 * tig);
            float2 p2 = *(const float2*)(Ap + (size_t)gid * 32 + kc * 16 + 2 * tig + 8);
            float2 p3 = *(const float2*)(Ap + (size_t)(gid + 8) * 32 + kc * 16 + 2 * tig + 8);
            uint32_t ah[4], al[4];
            splitH(p0.x, p0.y, ah[0], al[0]);
            splitH(p1.x, p1.y, ah[1], al[1]);
            splitH(p2.x, p2.y, ah[2], al[2]);
            splitH(p3.x, p3.y, ah[3], al[3]);
            int krow = (kc * 8 + tig) * PITCH + gid;
#pragma unroll
            for (int nt = 0; nt < 4; nt++) {
                int i0 = krow + nt * 8;
                uint32_t bh0 = sH[i0], bh1 = sH[i0 + 4 * PITCH];
                uint32_t bl0 = sL[i0], bl1 = sL[i0 + 4 * PITCH];
                mma16(d[nt], ah, bh0, bh1);
                mma16(d[nt], ah, bl0, bl1);
                mma16(d[nt], al, bh0, bh1);
            }
        }
        int ra = t * 16 + gid, rb = ra + 8;
#pragma unroll
        for (int nt = 0; nt < 4; nt++) {
            int c = nt * 8 + 2 * tig;
            float b0 = ga.bias[0][c], b1 = ga.bias[0][c + 1];
            int ia = ra * 32 + c, ib = rb * 32 + c;
            float o0 = fmaxf(d[nt][0] + b0 + g_aggr[ia]     + g_atom[ia],     0.f);
            float o1 = fmaxf(d[nt][1] + b1 + g_aggr[ia + 1] + g_atom[ia + 1], 0.f);
            float o2 = fmaxf(d[nt][2] + b0 + g_aggr[ib]     + g_atom[ib],     0.f);
            float o3 = fmaxf(d[nt][3] + b1 + g_aggr[ib + 1] + g_atom[ib + 1], 0.f);
            *(float2*)&hout[ia] = make_float2(o0, o1);
            *(float2*)&hout[ib] = make_float2(o2, o3);
            d[nt][0] = o0; d[nt][1] = o1; d[nt][2] = o2; d[nt][3] = o3;
        }
        nlin_on_tile(d, sH2, sL2, na, ra, rb, lane);
    }
}

// ---- zero helpers (split so they can overlap independently) ----
__global__ void k_zero_aggr() {
    int i = blockIdx.x * blockDim.x + threadIdx.x;
    int stride = gridDim.x * blockDim.x;
    for (int j = i; j < ROWS * F / 4; j += stride)
        ((float4*)g_aggr)[j] = make_float4(0.f, 0.f, 0.f, 0.f);
}
__global__ void k_zero_nsum() {
    int i = blockIdx.x * blockDim.x + threadIdx.x;
    int stride = gridDim.x * blockDim.x;
    for (int j = i; j < NN; j += stride)
        g_nsum[j] = 0.f;
}
__global__ void k_init() {   // both (layer 0)
    int i = blockIdx.x * blockDim.x + threadIdx.x;
    int stride = gridDim.x * blockDim.x;
    for (int j = i; j < ROWS * F / 4; j += stride)
        ((float4*)g_aggr)[j] = make_float4(0.f, 0.f, 0.f, 0.f);
    for (int j = i; j < NN; j += stride)
        g_nsum[j] = 0.f;
}

// ---- edge attention: half2 math, lean softmax tail, 4-edge unroll ----
__global__ void k_attn(const int* __restrict__ ei, const __half* __restrict__ ea_p,
                       const float* __restrict__ dw, const float* __restrict__ db) {
    int lane = threadIdx.x & 31;
    int q = lane & 7;
    float4 dwf = ((const float4*)dw)[q];
    __half2 dw01 = __floats2half2_rn(dwf.x, dwf.y);
    __half2 dw23 = __floats2half2_rn(dwf.z, dwf.w);
    __half2 z2 = __floats2half2_rn(0.f, 0.f);
    float dbv = db[0];
    int gw = (blockIdx.x * blockDim.x + threadIdx.x) >> 5;
    int nw = (gridDim.x * blockDim.x) >> 5;
    for (int e0 = gw * 4; e0 < NE; e0 += nw * 4) {   // NE % 4 == 0
        int s[4], dd[4];
#pragma unroll
        for (int k = 0; k < 4; k++) {
            s[k]  = __ldg(ei + e0 + k);
            dd[k] = __ldg(ei + NE + e0 + k);
        }
        float v[4];
#pragma unroll
        for (int k = 0; k < 4; k++) {
            uint2 ua = *(const uint2*)(g_xs + dd[k] * 128 + lane * 4);
            uint2 uc = *(const uint2*)(g_xd + s[k]  * 128 + lane * 4);
            uint2 ue = *(const uint2*)(ea_p + (e0 + k) * 32 + q * 4);
            __half2 s01 = __hadd2(*(__half2*)&ua.x, *(__half2*)&uc.x);
            __half2 s23 = __hadd2(*(__half2*)&ua.y, *(__half2*)&uc.y);
            s01 = __hmax2(__hadd2(s01, *(__half2*)&ue.x), z2);
            s23 = __hmax2(__hadd2(s23, *(__half2*)&ue.y), z2);
            __half2 p = __hfma2(s01, dw01, __hmul2(s23, dw23));
            float2 pf = __half22float2(p);
            v[k] = pf.x + pf.y;
        }
#pragma unroll
        for (int k = 0; k < 4; k++) {
            v[k] += __shfl_xor_sync(FULL, v[k], 4);
            v[k] += __shfl_xor_sync(FULL, v[k], 2);
            v[k] += __shfl_xor_sync(FULL, v[k], 1);
        }
        float b0 = __shfl_sync(FULL, v[0], (lane & 3) * 8);
        float b1 = __shfl_sync(FULL, v[1], (lane & 3) * 8);
        float b2 = __shfl_sync(FULL, v[2], (lane & 3) * 8);
        float b3 = __shfl_sync(FULL, v[3], (lane & 3) * 8);
        int kk = (lane >> 2) & 3;
        float sel = (kk == 0) ? b0 : (kk == 1) ? b1 : (kk == 2) ? b2 : b3;
        float ex1 = __expf(sel + dbv);
        float t = ex1 + __shfl_xor_sync(FULL, ex1, 1);
        t += __shfl_xor_sync(FULL, t, 2);
        if (lane < 16) {
            g_exp[(e0 + kk) * 4 + (lane & 3)] = ex1;
            if ((lane & 3) == 0)
                atomicAdd(&g_nsum[dd[kk]], t);
        }
    }
}

// ---- messages + tiled scatter; 2-group unroll, half2 adds, 32-bit addr ----
__global__ void k_msg(const int* __restrict__ ei, const __half* __restrict__ em_p) {
    int lane = threadIdx.x & 31;
    int q = lane & 7;
    int j = lane >> 3;
    int gw = (blockIdx.x * blockDim.x + threadIdx.x) >> 5;
    int nw = (gridDim.x * blockDim.x) >> 5;
    for (int g0 = gw * 2; g0 < NG; g0 += nw * 2) {   // NG even
        int g1 = g0 + 1;
        float4 T0 = make_float4(0.f, 0.f, 0.f, 0.f);
        float4 T1 = make_float4(0.f, 0.f, 0.f, 0.f);
#pragma unroll
        for (int c = 0; c < 4; c++) {
            int e0 = c * NG + g0;
            int e1 = c * NG + g1;
            int d0 = __ldg(ei + NE + e0);
            int d1 = __ldg(ei + NE + e1);
            float4 ex0 = ((const float4*)g_exp)[e0];
            float4 ex1 = ((const float4*)g_exp)[e1];
            float inv0 = 1.f / (g_nsum[d0] + 1e-8f);
            float inv1 = 1.f / (g_nsum[d1] + 1e-8f);
            float eh0 = (j == 0) ? ex0.x : (j == 1) ? ex0.y : (j == 2) ? ex0.z : ex0.w;
            float eh1 = (j == 0) ? ex1.x : (j == 1) ? ex1.y : (j == 2) ? ex1.z : ex1.w;
            float s0 = eh0 * inv0;
            float s1 = eh1 * inv1;
            uint2 uxm0 = *(const uint2*)(g_xm + d0 * 128 + lane * 4);
            uint2 uxm1 = *(const uint2*)(g_xm + d1 * 128 + lane * 4);
            uint2 uem0 = *(const uint2*)(em_p + e0 * 32 + q * 4);
            uint2 uem1 = *(const uint2*)(em_p + e1 * 32 + q * 4);
            __half2 m0a = __hadd2(*(__half2*)&uxm0.x, *(__half2*)&uem0.x);
            __half2 m0b = __hadd2(*(__half2*)&uxm0.y, *(__half2*)&uem0.y);
            __half2 m1a = __hadd2(*(__half2*)&uxm1.x, *(__half2*)&uem1.x);
            __half2 m1b = __hadd2(*(__half2*)&uxm1.y, *(__half2*)&uem1.y);
            float2 f0a = __half22float2(m0a), f0b = __half22float2(m0b);
            float2 f1a = __half22float2(m1a), f1b = __half22float2(m1b);
            T0.x += s0 * f0a.x; T0.y += s0 * f0a.y;
            T0.z += s0 * f0b.x; T0.w += s0 * f0b.y;
            T1.x += s1 * f1a.x; T1.y += s1 * f1a.y;
            T1.z += s1 * f1b.x; T1.w += s1 * f1b.y;
        }
        int tgt0 = __ldg(ei + NE + 4 * g0 + j);
        int tgt1 = __ldg(ei + NE + 4 * g1 + j);
        float* p0 = g_aggr + tgt0 * 32 + q * 4;
        float* p1 = g_aggr + tgt1 * 32 + q * 4;
        asm volatile("red.global.add.v4.f32 [%0], {%1,%2,%3,%4};"
                     :: "l"(p0), "f"(T0.x), "f"(T0.y), "f"(T0.z), "f"(T0.w)
                     : "memory");
        asm volatile("red.global.add.v4.f32 [%0], {%1,%2,%3,%4};"
                     :: "l"(p1), "f"(T1.x), "f"(T1.y), "f"(T1.z), "f"(T1.w)
                     : "memory");
    }
}

extern "C" void kernel_launch(void* const* d_in, const int* in_sizes, int n_in,
                              void* d_out, int out_size) {
    const float* x      = (const float*)d_in[0];
    const float* eattr  = (const float*)d_in[1];
    const int*   ei     = (const int*)d_in[2];
    const float* atom_w = (const float*)d_in[3];
    const float* atom_b = (const float*)d_in[4];
    const float* asw  = (const float*)d_in[5];
    const float* asb  = (const float*)d_in[6];
    const float* adw  = (const float*)d_in[7];
    const float* adb  = (const float*)d_in[8];
    const float* aew  = (const float*)d_in[9];
    const float* aeb  = (const float*)d_in[10];
    const float* dotw = (const float*)d_in[11];
    const float* dotb = (const float*)d_in[12];
    const float* mdw  = (const float*)d_in[13];
    const float* mdb  = (const float*)d_in[14];
    const float* mew  = (const float*)d_in[15];
    const float* meb  = (const float*)d_in[16];
    const float* wnw  = (const float*)d_in[17];
    const float* wnb  = (const float*)d_in[18];
    float* out = (float*)d_out;

    float *p_h, *p_atom;
    __half *p_xs, *p_xd, *p_xm, *p_ea, *p_em, *p_ea2, *p_em2;
    cudaGetSymbolAddress((void**)&p_h,    g_h);
    cudaGetSymbolAddress((void**)&p_atom, g_atom);
    cudaGetSymbolAddress((void**)&p_xs,   g_xs);
    cudaGetSymbolAddress((void**)&p_xd,   g_xd);
    cudaGetSymbolAddress((void**)&p_xm,   g_xm);
    cudaGetSymbolAddress((void**)&p_ea,   g_ea);
    cudaGetSymbolAddress((void**)&p_em,   g_em);
    cudaGetSymbolAddress((void**)&p_ea2,  g_ea2);
    cudaGetSymbolAddress((void**)&p_em2,  g_em2);

    const int smem_atomf = (2 * 64 * 136 + 2 * 16 * PITCHN) * 4;  // 82944
    const int smem_combf = (2 * 16 * 40 + 2 * 16 * PITCHN) * 4;   // 18432
    const int smem_e4    = 2 * 16 * (4 * 32 + 8) * 4;             // 17408
    const int smem_c1    = 2 * 16 * (1 * 32 + 8) * 4;             // 5120
    cudaFuncSetAttribute(k_atomf,
                         cudaFuncAttributeMaxDynamicSharedMemorySize, smem_atomf);

    // side stream + events (created per call; never destroyed — kernel_launch
    // runs only a handful of times and destroy-during-capture is illegal)
    cudaStream_t s2;
    cudaStreamCreateWithFlags(&s2, cudaStreamNonBlocking);
    cudaEvent_t evFork, evSide, evMsg0, evNsum, evCombf, evAggr;
    cudaEventCreateWithFlags(&evFork,  cudaEventDisableTiming);
    cudaEventCreateWithFlags(&evSide,  cudaEventDisableTiming);
    cudaEventCreateWithFlags(&evMsg0,  cudaEventDisableTiming);
    cudaEventCreateWithFlags(&evNsum,  cudaEventDisableTiming);
    cudaEventCreateWithFlags(&evCombf, cudaEventDisableTiming);
    cudaEventCreateWithFlags(&evAggr,  cudaEventDisableTiming);

    // ---- fork: side stream does init0 + elin while main does atomf ----
    cudaEventRecord(evFork, 0);
    cudaStreamWaitEvent(s2, evFork, 0);

    k_init<<<512, 256, 0, s2>>>();
    {
        GArgs ge;
        ge.A = eattr; ge.M = NE; ge.Astride = 32; ge.Bstride = 32; ge.Ostride = 32;
        ge.B[0] = aew;        ge.B[1] = mew;        ge.B[2] = aew + 1024; ge.B[3] = mew + 1024;
        ge.bias[0] = aeb;     ge.bias[1] = meb;     ge.bias[2] = aeb + 32; ge.bias[3] = meb + 32;
        ge.out[0] = p_ea; ge.out[1] = p_em; ge.out[2] = p_ea2; ge.out[3] = p_em2;
        for (int m = 0; m < 4; m++) ge.out2[m] = p_ea;
        k_g<4, 2, 0, 1><<<444, 256, smem_e4, s2>>>(ge);
    }
    cudaEventRecord(evSide, s2);

    // main: atom + fused layer-0 node linears
    {
        GArgs ga;
        ga.A = x; ga.M = NN; ga.Astride = 128; ga.Bstride = 128; ga.Ostride = 128;
        for (int m = 0; m < 4; m++) {
            ga.B[m]    = atom_w + m * 32;
            ga.bias[m] = atom_b + m * 32;
        }
        ga.out[0] = p_atom; ga.out2[0] = p_h;
        NArgs na;
        na.W[0] = asw; na.W[1] = adw; na.W[2] = mdw;
        na.bias[0] = asb; na.bias[1] = adb; na.bias[2] = mdb;
        na.out[0] = p_xs; na.out[1] = p_xd; na.out[2] = p_xm;
        k_atomf<<<296, 256, smem_atomf>>>(ga, na);
    }
    cudaStreamWaitEvent(0, evSide, 0);   // join: elin + init0 done

    // ---- layer 0 edge phase ----
    k_attn<<<740, 256>>>(ei, p_ea, dotw, dotb);
    k_msg<<<740, 256>>>(ei, p_em);
    cudaEventRecord(evMsg0, 0);

    // side: zero nsum for layer 1 (msg0 was the last reader)
    cudaStreamWaitEvent(s2, evMsg0, 0);
    k_zero_nsum<<<98, 256, 0, s2>>>();
    cudaEventRecord(evNsum, s2);

    // main: comb(l0) + fused layer-1 node linears
    {
        GArgs gc;
        gc.A = p_h; gc.M = ROWS; gc.Astride = 32; gc.Bstride = 32; gc.Ostride = 32;
        gc.B[0] = wnw; gc.bias[0] = wnb;
        gc.out[0] = p_h;
        NArgs na;
        na.W[0] = asw + 1024; na.W[1] = adw + 1024; na.W[2] = mdw + 1024;
        na.bias[0] = asb + 32; na.bias[1] = adb + 32; na.bias[2] = mdb + 32;
        na.out[0] = p_xs; na.out[1] = p_xd; na.out[2] = p_xm;
        k_combf<<<444, 256, smem_combf>>>(gc, na);
    }
    cudaEventRecord(evCombf, 0);

    // side: zero aggr for layer 1 (combf was the last reader); runs
    // concurrently with attn1 (which doesn't touch aggr)
    cudaStreamWaitEvent(s2, evCombf, 0);
    k_zero_aggr<<<444, 256, 0, s2>>>();
    cudaEventRecord(evAggr, s2);

    // ---- layer 1 edge phase ----
    cudaStreamWaitEvent(0, evNsum, 0);
    k_attn<<<740, 256>>>(ei, p_ea2, dotw + 32, dotb + 1);
    cudaStreamWaitEvent(0, evAggr, 0);   // join side stream before msg1
    k_msg<<<740, 256>>>(ei, p_em2);

    // final comb + head-mean -> out
    {
        GArgs gc;
        gc.A = p_h; gc.M = ROWS; gc.Astride = 32; gc.Bstride = 32; gc.Ostride = 32;
        gc.B[0] = wnw + 1024; gc.B[1] = gc.B[2] = gc.B[3] = gc.B[0];
        gc.bias[0] = wnb + 32; gc.bias[1] = gc.bias[2] = gc.bias[3] = gc.bias[0];
        gc.out[0] = out; gc.out[1] = gc.out[2] = gc.out[3] = out;
        gc.out2[0] = gc.out2[1] = gc.out2[2] = gc.out2[3] = p_h;
        k_g<1, 2, 3, 0><<<444, 256, smem_c1>>>(gc);
    }
}

// round 17
// speedup vs baseline: 1.4481x; 1.0346x over previous
#include <cuda_runtime.h>
#include <cuda_fp16.h>
#include <cstdint>

#define FULL 0xffffffffu

constexpr int NN   = 50000;
constexpr int NE   = 400000;
constexpr int F    = 32;
constexpr int H    = 4;
constexpr int ROWS = NN * H;        // 200000 (n,h) rows
constexpr int NG   = NE / H;        // 100000 message groups

// ---- scratch (device globals; no allocation allowed) ----
__device__ float    g_h[ROWS * F];
__device__ float    g_atom[ROWS * F];
__device__ __half   g_xs[ROWS * F];
__device__ __half   g_xd[ROWS * F];
__device__ __half   g_xm[ROWS * F];
__device__ __half   g_ea[NE * F];       // layer 0
__device__ __half   g_em[NE * F];
__device__ __half   g_ea2[NE * F];      // layer 1
__device__ __half   g_em2[NE * F];
__device__ float    g_exp[NE * H];
__device__ float    g_nsum[NN];
__device__ float    g_aggr[ROWS * F];

__device__ __forceinline__ void mma16(float d[4], const uint32_t a[4],
                                      uint32_t b0, uint32_t b1) {
    asm("mma.sync.aligned.m16n8k16.row.col.f32.f16.f16.f32 "
        "{%0,%1,%2,%3}, {%4,%5,%6,%7}, {%8,%9}, {%0,%1,%2,%3};"
        : "+f"(d[0]), "+f"(d[1]), "+f"(d[2]), "+f"(d[3])
        : "r"(a[0]), "r"(a[1]), "r"(a[2]), "r"(a[3]), "r"(b0), "r"(b1));
}

// split fp32 pair -> fp16 hi + fp16 residual lo (packed half2 as u32)
__device__ __forceinline__ void splitH(float x, float y,
                                       uint32_t& hi, uint32_t& lo) {
    __half2 h = __floats2half2_rn(x, y);
    float2 hf = __half22float2(h);
    __half2 l = __floats2half2_rn(x - hf.x, y - hf.y);
    hi = *(uint32_t*)&h;
    lo = *(uint32_t*)&l;
}

struct GArgs {
    const float* A;
    const float* B[4];
    const float* bias[4];
    void*        out[4];
    void*        out2[4];
    int          M;
    int          Astride;
    int          Bstride;
    int          Ostride;
};

// ---- fused node-linear stage (xs/xd/xm GEMM on an in-register h tile) ----
constexpr int PITCHN = 3 * 32 + 8;   // 104, % 32 == 8 -> conflict-free

struct NArgs {
    const float* W[3];
    const float* bias[3];
    __half*      out[3];
};

__device__ __forceinline__ void stage_nlin(uint32_t* sH2, uint32_t* sL2,
                                           const NArgs& na, int tid) {
    for (int m = 0; m < 3; m++) {
        const float* Bp = na.W[m];
        for (int i = tid; i < 16 * 32; i += 256) {
            int kk = i >> 5, n = i & 31;
            float v0 = Bp[(2 * kk) * 32 + n];
            float v1 = Bp[(2 * kk + 1) * 32 + n];
            uint32_t hi, lo; splitH(v0, v1, hi, lo);
            sH2[kk * PITCHN + m * 32 + n] = hi;
            sL2[kk * PITCHN + m * 32 + n] = lo;
        }
    }
}

__device__ __forceinline__ void nlin_on_tile(const float (*hh)[4],
        const uint32_t* sH2, const uint32_t* sL2, const NArgs& na,
        int ra, int rb, int lane) {
    int gid = lane >> 2, tig = lane & 3;
    float d2[12][4];
#pragma unroll
    for (int nt = 0; nt < 12; nt++) {
        d2[nt][0] = 0.f; d2[nt][1] = 0.f; d2[nt][2] = 0.f; d2[nt][3] = 0.f;
    }
#pragma unroll
    for (int kc = 0; kc < 2; kc++) {
        uint32_t ah[4], al[4];
        splitH(hh[kc*2][0],   hh[kc*2][1],   ah[0], al[0]);
        splitH(hh[kc*2][2],   hh[kc*2][3],   ah[1], al[1]);
        splitH(hh[kc*2+1][0], hh[kc*2+1][1], ah[2], al[2]);
        splitH(hh[kc*2+1][2], hh[kc*2+1][3], ah[3], al[3]);
        int krow = (kc * 8 + tig) * PITCHN + gid;
#pragma unroll
        for (int nt = 0; nt < 12; nt++) {
            int i0 = krow + nt * 8;
            uint32_t bh0 = sH2[i0], bh1 = sH2[i0 + 4 * PITCHN];
            uint32_t bl0 = sL2[i0], bl1 = sL2[i0 + 4 * PITCHN];
            mma16(d2[nt], ah, bh0, bh1);
            mma16(d2[nt], ah, bl0, bl1);
            mma16(d2[nt], al, bh0, bh1);
        }
    }
#pragma unroll
    for (int nt = 0; nt < 12; nt++) {
        int m = nt >> 2;
        int c = (nt & 3) * 8 + 2 * tig;
        float b0 = na.bias[m][c], b1 = na.bias[m][c + 1];
        __half* op = na.out[m];
        *(__half2*)&op[(size_t)ra * 32 + c] =
            __floats2half2_rn(d2[nt][0] + b0, d2[nt][1] + b1);
        *(__half2*)&op[(size_t)rb * 32 + c] =
            __floats2half2_rn(d2[nt][2] + b0, d2[nt][3] + b1);
    }
}

// ============================================================================
// generic gemm (elin and final comb)
// ============================================================================
template<int NM, int KC16, int MODE, int OUTH>
__device__ __forceinline__ void gemm_body(const GArgs& ga, uint32_t* sB,
                                          int bid, int nblocks, int tid) {
    constexpr int NT = NM * 4;
    constexpr int PITCH = NM * 32 + 8;
    constexpr int KK = KC16 * 8;
    uint32_t* sH = sB;
    uint32_t* sL = sB + KK * PITCH;

    for (int m = 0; m < NM; m++) {
        const float* Bp = ga.B[m];
        for (int i = tid; i < KK * 32; i += 256) {
            int kk = i >> 5, n = i & 31;
            float v0 = Bp[(size_t)(2 * kk)     * ga.Bstride + n];
            float v1 = Bp[(size_t)(2 * kk + 1) * ga.Bstride + n];
            uint32_t hi, lo;
            splitH(v0, v1, hi, lo);
            sH[kk * PITCH + m * 32 + n] = hi;
            sL[kk * PITCH + m * 32 + n] = lo;
        }
    }
    __syncthreads();

    int lane = tid & 31;
    int gid = lane >> 2, tig = lane & 3;
    int gw = bid * 8 + (tid >> 5);
    int nw = nblocks * 8;
    int ntile = ga.M >> 4;
    const int As = ga.Astride;

    for (int t = gw; t < ntile; t += nw) {
        const float* Ap = ga.A + (size_t)(t * 16) * As;
        float d[NT][4];
#pragma unroll
        for (int nt = 0; nt < NT; nt++) {
            d[nt][0] = 0.f; d[nt][1] = 0.f; d[nt][2] = 0.f; d[nt][3] = 0.f;
        }
#pragma unroll 2
        for (int kc = 0; kc < KC16; kc++) {
            float2 p0 = *(const float2*)(Ap + (size_t)gid * As + kc * 16 + 2 * tig);
            float2 p1 = *(const float2*)(Ap + (size_t)(gid + 8) * As + kc * 16 + 2 * tig);
            float2 p2 = *(const float2*)(Ap + (size_t)gid * As + kc * 16 + 2 * tig + 8);
            float2 p3 = *(const float2*)(Ap + (size_t)(gid + 8) * As + kc * 16 + 2 * tig + 8);
            uint32_t ah[4], al[4];
            splitH(p0.x, p0.y, ah[0], al[0]);
            splitH(p1.x, p1.y, ah[1], al[1]);
            splitH(p2.x, p2.y, ah[2], al[2]);
            splitH(p3.x, p3.y, ah[3], al[3]);
            int krow = (kc * 8 + tig) * PITCH + gid;
#pragma unroll
            for (int nt = 0; nt < NT; nt++) {
                int i0 = krow + nt * 8;
                uint32_t bh0 = sH[i0], bh1 = sH[i0 + 4 * PITCH];
                uint32_t bl0 = sL[i0], bl1 = sL[i0 + 4 * PITCH];
                mma16(d[nt], ah, bh0, bh1);
                mma16(d[nt], ah, bl0, bl1);
                mma16(d[nt], al, bh0, bh1);
            }
        }
        int ra = t * 16 + gid, rb = ra + 8;
#pragma unroll
        for (int nt = 0; nt < NT; nt++) {
            const int m = nt >> 2;
            int c = (nt & 3) * 8 + 2 * tig;
            float b0 = ga.bias[m][c], b1 = ga.bias[m][c + 1];
            float o0 = d[nt][0] + b0, o1 = d[nt][1] + b1;
            float o2 = d[nt][2] + b0, o3 = d[nt][3] + b1;
            if (MODE >= 2) {
                int ia = ra * 32 + c, ib = rb * 32 + c;
                o0 += g_aggr[ia]     + g_atom[ia];
                o1 += g_aggr[ia + 1] + g_atom[ia + 1];
                o2 += g_aggr[ib]     + g_atom[ib];
                o3 += g_aggr[ib + 1] + g_atom[ib + 1];
            }
            if (MODE != 0) {
                o0 = fmaxf(o0, 0.f); o1 = fmaxf(o1, 0.f);
                o2 = fmaxf(o2, 0.f); o3 = fmaxf(o3, 0.f);
            }
            if (MODE == 3) {
                float s0 = o0 + __shfl_xor_sync(FULL, o0, 4);
                s0 += __shfl_xor_sync(FULL, s0, 8);
                float s1 = o1 + __shfl_xor_sync(FULL, o1, 4);
                s1 += __shfl_xor_sync(FULL, s1, 8);
                float s2 = o2 + __shfl_xor_sync(FULL, o2, 4);
                s2 += __shfl_xor_sync(FULL, s2, 8);
                float s3 = o3 + __shfl_xor_sync(FULL, o3, 4);
                s3 += __shfl_xor_sync(FULL, s3, 8);
                if ((gid & 3) == 0) {
                    float* op = (float*)ga.out[0];
                    int na = ra >> 2;
                    int nb = rb >> 2;
                    *(float2*)&op[na * 32 + c] = make_float2(0.25f*s0, 0.25f*s1);
                    *(float2*)&op[nb * 32 + c] = make_float2(0.25f*s2, 0.25f*s3);
                }
                continue;
            }
            size_t ia = (size_t)ra * ga.Ostride + c;
            size_t ib = (size_t)rb * ga.Ostride + c;
            if (OUTH) {
                __half* op = (__half*)ga.out[m];
                *(__half2*)&op[ia] = __floats2half2_rn(o0, o1);
                *(__half2*)&op[ib] = __floats2half2_rn(o2, o3);
            } else {
                float* op = (float*)ga.out[m];
                *(float2*)&op[ia] = make_float2(o0, o1);
                *(float2*)&op[ib] = make_float2(o2, o3);
                if (MODE == 1) {
                    float* op2 = (float*)ga.out2[m];
                    *(float2*)&op2[ia] = make_float2(o0, o1);
                    *(float2*)&op2[ib] = make_float2(o2, o3);
                }
            }
        }
    }
}

template<int NM, int KC16, int MODE, int OUTH>
__global__ void __launch_bounds__(256) k_g(GArgs ga) {
    extern __shared__ uint32_t sB[];
    gemm_body<NM, KC16, MODE, OUTH>(ga, sB, blockIdx.x, gridDim.x, threadIdx.x);
}

// ============================================================================
// k_atomf: atom GEMM + relu + dual write + fused layer-0 node linears
// ============================================================================
__global__ void __launch_bounds__(256) k_atomf(GArgs ga, NArgs na) {
    extern __shared__ uint32_t sB[];
    constexpr int PITCH = 4 * 32 + 8;   // 136
    constexpr int KK = 64;              // K=128
    uint32_t* sH = sB;
    uint32_t* sL = sB + KK * PITCH;
    uint32_t* sH2 = sB + 2 * KK * PITCH;
    uint32_t* sL2 = sH2 + 16 * PITCHN;
    int tid = threadIdx.x;

    for (int m = 0; m < 4; m++) {
        const float* Bp = ga.B[m];
        for (int i = tid; i < KK * 32; i += 256) {
            int kk = i >> 5, n = i & 31;
            float v0 = Bp[(size_t)(2 * kk) * 128 + n];
            float v1 = Bp[(size_t)(2 * kk + 1) * 128 + n];
            uint32_t hi, lo; splitH(v0, v1, hi, lo);
            sH[kk * PITCH + m * 32 + n] = hi;
            sL[kk * PITCH + m * 32 + n] = lo;
        }
    }
    stage_nlin(sH2, sL2, na, tid);
    __syncthreads();

    int lane = tid & 31;
    int gid = lane >> 2, tig = lane & 3;
    int gw = blockIdx.x * 8 + (tid >> 5);
    int nw = gridDim.x * 8;
    float* p_atom = (float*)ga.out[0];
    float* p_h    = (float*)ga.out2[0];

    for (int t = gw; t < (NN >> 4); t += nw) {
        const float* Ap = ga.A + (size_t)(t * 16) * 128;
        float d[16][4];
#pragma unroll
        for (int nt = 0; nt < 16; nt++) {
            d[nt][0] = 0.f; d[nt][1] = 0.f; d[nt][2] = 0.f; d[nt][3] = 0.f;
        }
#pragma unroll 2
        for (int kc = 0; kc < 8; kc++) {
            float2 p0 = *(const float2*)(Ap + (size_t)gid * 128 + kc * 16 + 2 * tig);
            float2 p1 = *(const float2*)(Ap + (size_t)(gid + 8) * 128 + kc * 16 + 2 * tig);
            float2 p2 = *(const float2*)(Ap + (size_t)gid * 128 + kc * 16 + 2 * tig + 8);
            float2 p3 = *(const float2*)(Ap + (size_t)(gid + 8) * 128 + kc * 16 + 2 * tig + 8);
            uint32_t ah[4], al[4];
            splitH(p0.x, p0.y, ah[0], al[0]);
            splitH(p1.x, p1.y, ah[1], al[1]);
            splitH(p2.x, p2.y, ah[2], al[2]);
            splitH(p3.x, p3.y, ah[3], al[3]);
            int krow = (kc * 8 + tig) * PITCH + gid;
#pragma unroll
            for (int nt = 0; nt < 16; nt++) {
                int i0 = krow + nt * 8;
                uint32_t bh0 = sH[i0], bh1 = sH[i0 + 4 * PITCH];
                uint32_t bl0 = sL[i0], bl1 = sL[i0 + 4 * PITCH];
                mma16(d[nt], ah, bh0, bh1);
                mma16(d[nt], ah, bl0, bl1);
                mma16(d[nt], al, bh0, bh1);
            }
        }
        int ra = t * 16 + gid, rb = ra + 8;
#pragma unroll
        for (int nt = 0; nt < 16; nt++) {
            int m = nt >> 2;
            int c = (nt & 3) * 8 + 2 * tig;
            float b0 = ga.bias[m][c], b1 = ga.bias[m][c + 1];
            float o0 = fmaxf(d[nt][0] + b0, 0.f);
            float o1 = fmaxf(d[nt][1] + b1, 0.f);
            float o2 = fmaxf(d[nt][2] + b0, 0.f);
            float o3 = fmaxf(d[nt][3] + b1, 0.f);
            size_t ia = (size_t)ra * 128 + m * 32 + c;
            size_t ib = (size_t)rb * 128 + m * 32 + c;
            *(float2*)&p_atom[ia] = make_float2(o0, o1);
            *(float2*)&p_atom[ib] = make_float2(o2, o3);
            *(float2*)&p_h[ia]    = make_float2(o0, o1);
            *(float2*)&p_h[ib]    = make_float2(o2, o3);
            d[nt][0] = o0; d[nt][1] = o1; d[nt][2] = o2; d[nt][3] = o3;
        }
#pragma unroll
        for (int m = 0; m < 4; m++)
            nlin_on_tile(&d[m * 4], sH2, sL2, na, ra * 4 + m, rb * 4 + m, lane);
    }
}

// ============================================================================
// k_combf: layer-0 comb + fused layer-1 node linears
// ============================================================================
__global__ void __launch_bounds__(256) k_combf(GArgs ga, NArgs na) {
    extern __shared__ uint32_t sB[];
    constexpr int PITCH = 40;   // NM=1
    constexpr int KK = 16;
    uint32_t* sH = sB;
    uint32_t* sL = sB + KK * PITCH;
    uint32_t* sH2 = sB + 2 * KK * PITCH;
    uint32_t* sL2 = sH2 + 16 * PITCHN;
    int tid = threadIdx.x;

    {
        const float* Bp = ga.B[0];
        for (int i = tid; i < KK * 32; i += 256) {
            int kk = i >> 5, n = i & 31;
            float v0 = Bp[(2 * kk) * 32 + n];
            float v1 = Bp[(2 * kk + 1) * 32 + n];
            uint32_t hi, lo; splitH(v0, v1, hi, lo);
            sH[kk * PITCH + n] = hi;
            sL[kk * PITCH + n] = lo;
        }
    }
    stage_nlin(sH2, sL2, na, tid);
    __syncthreads();

    int lane = tid & 31;
    int gid = lane >> 2, tig = lane & 3;
    int gw = blockIdx.x * 8 + (tid >> 5);
    int nw = gridDim.x * 8;
    float* hout = (float*)ga.out[0];

    for (int t = gw; t < (ROWS >> 4); t += nw) {
        const float* Ap = ga.A + (size_t)(t * 16) * 32;
        float d[4][4];
#pragma unroll
        for (int nt = 0; nt < 4; nt++) {
            d[nt][0] = 0.f; d[nt][1] = 0.f; d[nt][2] = 0.f; d[nt][3] = 0.f;
        }
#pragma unroll
        for (int kc = 0; kc < 2; kc++) {
            float2 p0 = *(const float2*)(Ap + (size_t)gid * 32 + kc * 16 + 2 * tig);
            float2 p1 = *(const float2*)(Ap + (size_t)(gid + 8) * 32 + kc * 16 + 2 * tig);
            float2 p2 = *(const float2*)(Ap + (size_t)gid * 32 + kc * 16 + 2 * tig + 8);
            float2 p3 = *(const float2*)(Ap + (size_t)(gid + 8) * 32 + kc * 16 + 2 * tig + 8);
            uint32_t ah[4], al[4];
            splitH(p0.x, p0.y, ah[0], al[0]);
            splitH(p1.x, p1.y, ah[1], al[1]);
            splitH(p2.x, p2.y, ah[2], al[2]);
            splitH(p3.x, p3.y, ah[3], al[3]);
            int krow = (kc * 8 + tig) * PITCH + gid;
#pragma unroll
            for (int nt = 0; nt < 4; nt++) {
                int i0 = krow + nt * 8;
                uint32_t bh0 = sH[i0], bh1 = sH[i0 + 4 * PITCH];
                uint32_t bl0 = sL[i0], bl1 = sL[i0 + 4 * PITCH];
                mma16(d[nt], ah, bh0, bh1);
                mma16(d[nt], ah, bl0, bl1);
                mma16(d[nt], al, bh0, bh1);
            }
        }
        int ra = t * 16 + gid, rb = ra + 8;
#pragma unroll
        for (int nt = 0; nt < 4; nt++) {
            int c = nt * 8 + 2 * tig;
            float b0 = ga.bias[0][c], b1 = ga.bias[0][c + 1];
            int ia = ra * 32 + c, ib = rb * 32 + c;
            float o0 = fmaxf(d[nt][0] + b0 + g_aggr[ia]     + g_atom[ia],     0.f);
            float o1 = fmaxf(d[nt][1] + b1 + g_aggr[ia + 1] + g_atom[ia + 1], 0.f);
            float o2 = fmaxf(d[nt][2] + b0 + g_aggr[ib]     + g_atom[ib],     0.f);
            float o3 = fmaxf(d[nt][3] + b1 + g_aggr[ib + 1] + g_atom[ib + 1], 0.f);
            *(float2*)&hout[ia] = make_float2(o0, o1);
            *(float2*)&hout[ib] = make_float2(o2, o3);
            d[nt][0] = o0; d[nt][1] = o1; d[nt][2] = o2; d[nt][3] = o3;
        }
        nlin_on_tile(d, sH2, sL2, na, ra, rb, lane);
    }
}

// ---- zero helpers ----
__global__ void k_zero_aggr() {
    int i = blockIdx.x * blockDim.x + threadIdx.x;
    int stride = gridDim.x * blockDim.x;
    for (int j = i; j < ROWS * F / 4; j += stride)
        ((float4*)g_aggr)[j] = make_float4(0.f, 0.f, 0.f, 0.f);
}
__global__ void k_zero_nsum() {
    int i = blockIdx.x * blockDim.x + threadIdx.x;
    int stride = gridDim.x * blockDim.x;
    for (int j = i; j < NN; j += stride)
        g_nsum[j] = 0.f;
}
__global__ void k_init() {
    int i = blockIdx.x * blockDim.x + threadIdx.x;
    int stride = gridDim.x * blockDim.x;
    for (int j = i; j < ROWS * F / 4; j += stride)
        ((float4*)g_aggr)[j] = make_float4(0.f, 0.f, 0.f, 0.f);
    for (int j = i; j < NN; j += stride)
        g_nsum[j] = 0.f;
}

// ---- edge attention: half2 math, lean softmax tail, 4-edge unroll ----
__global__ void k_attn(const int* __restrict__ ei, const __half* __restrict__ ea_p,
                       const float* __restrict__ dw, const float* __restrict__ db) {
    int lane = threadIdx.x & 31;
    int q = lane & 7;
    float4 dwf = ((const float4*)dw)[q];
    __half2 dw01 = __floats2half2_rn(dwf.x, dwf.y);
    __half2 dw23 = __floats2half2_rn(dwf.z, dwf.w);
    __half2 z2 = __floats2half2_rn(0.f, 0.f);
    float dbv = db[0];
    int gw = (blockIdx.x * blockDim.x + threadIdx.x) >> 5;
    int nw = (gridDim.x * blockDim.x) >> 5;
    for (int e0 = gw * 4; e0 < NE; e0 += nw * 4) {   // NE % 4 == 0
        int s[4], dd[4];
#pragma unroll
        for (int k = 0; k < 4; k++) {
            s[k]  = __ldg(ei + e0 + k);
            dd[k] = __ldg(ei + NE + e0 + k);
        }
        float v[4];
#pragma unroll
        for (int k = 0; k < 4; k++) {
            uint2 ua = *(const uint2*)(g_xs + dd[k] * 128 + lane * 4);
            uint2 uc = *(const uint2*)(g_xd + s[k]  * 128 + lane * 4);
            uint2 ue = *(const uint2*)(ea_p + (e0 + k) * 32 + q * 4);
            __half2 s01 = __hadd2(*(__half2*)&ua.x, *(__half2*)&uc.x);
            __half2 s23 = __hadd2(*(__half2*)&ua.y, *(__half2*)&uc.y);
            s01 = __hmax2(__hadd2(s01, *(__half2*)&ue.x), z2);
            s23 = __hmax2(__hadd2(s23, *(__half2*)&ue.y), z2);
            __half2 p = __hfma2(s01, dw01, __hmul2(s23, dw23));
            float2 pf = __half22float2(p);
            v[k] = pf.x + pf.y;
        }
#pragma unroll
        for (int k = 0; k < 4; k++) {
            v[k] += __shfl_xor_sync(FULL, v[k], 4);
            v[k] += __shfl_xor_sync(FULL, v[k], 2);
            v[k] += __shfl_xor_sync(FULL, v[k], 1);
        }
        float b0 = __shfl_sync(FULL, v[0], (lane & 3) * 8);
        float b1 = __shfl_sync(FULL, v[1], (lane & 3) * 8);
        float b2 = __shfl_sync(FULL, v[2], (lane & 3) * 8);
        float b3 = __shfl_sync(FULL, v[3], (lane & 3) * 8);
        int kk = (lane >> 2) & 3;
        float sel = (kk == 0) ? b0 : (kk == 1) ? b1 : (kk == 2) ? b2 : b3;
        float ex1 = __expf(sel + dbv);
        float t = ex1 + __shfl_xor_sync(FULL, ex1, 1);
        t += __shfl_xor_sync(FULL, t, 2);
        if (lane < 16) {
            g_exp[(e0 + kk) * 4 + (lane & 3)] = ex1;
            if ((lane & 3) == 0)
                atomicAdd(&g_nsum[dd[kk]], t);
        }
    }
}

// ---- messages + tiled scatter; 2-group unroll, half2 adds, 32-bit addr ----
__global__ void k_msg(const int* __restrict__ ei, const __half* __restrict__ em_p) {
    int lane = threadIdx.x & 31;
    int q = lane & 7;
    int j = lane >> 3;
    int gw = (blockIdx.x * blockDim.x + threadIdx.x) >> 5;
    int nw = (gridDim.x * blockDim.x) >> 5;
    for (int g0 = gw * 2; g0 < NG; g0 += nw * 2) {   // NG even
        int g1 = g0 + 1;
        float4 T0 = make_float4(0.f, 0.f, 0.f, 0.f);
        float4 T1 = make_float4(0.f, 0.f, 0.f, 0.f);
#pragma unroll
        for (int c = 0; c < 4; c++) {
            int e0 = c * NG + g0;
            int e1 = c * NG + g1;
            int d0 = __ldg(ei + NE + e0);
            int d1 = __ldg(ei + NE + e1);
            float4 ex0 = ((const float4*)g_exp)[e0];
            float4 ex1 = ((const float4*)g_exp)[e1];
            float inv0 = 1.f / (g_nsum[d0] + 1e-8f);
            float inv1 = 1.f / (g_nsum[d1] + 1e-8f);
            float eh0 = (j == 0) ? ex0.x : (j == 1) ? ex0.y : (j == 2) ? ex0.z : ex0.w;
            float eh1 = (j == 0) ? ex1.x : (j == 1) ? ex1.y : (j == 2) ? ex1.z : ex1.w;
            float s0 = eh0 * inv0;
            float s1 = eh1 * inv1;
            uint2 uxm0 = *(const uint2*)(g_xm + d0 * 128 + lane * 4);
            uint2 uxm1 = *(const uint2*)(g_xm + d1 * 128 + lane * 4);
            uint2 uem0 = *(const uint2*)(em_p + e0 * 32 + q * 4);
            uint2 uem1 = *(const uint2*)(em_p + e1 * 32 + q * 4);
            __half2 m0a = __hadd2(*(__half2*)&uxm0.x, *(__half2*)&uem0.x);
            __half2 m0b = __hadd2(*(__half2*)&uxm0.y, *(__half2*)&uem0.y);
            __half2 m1a = __hadd2(*(__half2*)&uxm1.x, *(__half2*)&uem1.x);
            __half2 m1b = __hadd2(*(__half2*)&uxm1.y, *(__half2*)&uem1.y);
            float2 f0a = __half22float2(m0a), f0b = __half22float2(m0b);
            float2 f1a = __half22float2(m1a), f1b = __half22float2(m1b);
            T0.x += s0 * f0a.x; T0.y += s0 * f0a.y;
            T0.z += s0 * f0b.x; T0.w += s0 * f0b.y;
            T1.x += s1 * f1a.x; T1.y += s1 * f1a.y;
            T1.z += s1 * f1b.x; T1.w += s1 * f1b.y;
        }
        int tgt0 = __ldg(ei + NE + 4 * g0 + j);
        int tgt1 = __ldg(ei + NE + 4 * g1 + j);
        float* p0 = g_aggr + tgt0 * 32 + q * 4;
        float* p1 = g_aggr + tgt1 * 32 + q * 4;
        asm volatile("red.global.add.v4.f32 [%0], {%1,%2,%3,%4};"
                     :: "l"(p0), "f"(T0.x), "f"(T0.y), "f"(T0.z), "f"(T0.w)
                     : "memory");
        asm volatile("red.global.add.v4.f32 [%0], {%1,%2,%3,%4};"
                     :: "l"(p1), "f"(T1.x), "f"(T1.y), "f"(T1.z), "f"(T1.w)
                     : "memory");
    }
}

extern "C" void kernel_launch(void* const* d_in, const int* in_sizes, int n_in,
                              void* d_out, int out_size) {
    const float* x      = (const float*)d_in[0];
    const float* eattr  = (const float*)d_in[1];
    const int*   ei     = (const int*)d_in[2];
    const float* atom_w = (const float*)d_in[3];
    const float* atom_b = (const float*)d_in[4];
    const float* asw  = (const float*)d_in[5];
    const float* asb  = (const float*)d_in[6];
    const float* adw  = (const float*)d_in[7];
    const float* adb  = (const float*)d_in[8];
    const float* aew  = (const float*)d_in[9];
    const float* aeb  = (const float*)d_in[10];
    const float* dotw = (const float*)d_in[11];
    const float* dotb = (const float*)d_in[12];
    const float* mdw  = (const float*)d_in[13];
    const float* mdb  = (const float*)d_in[14];
    const float* mew  = (const float*)d_in[15];
    const float* meb  = (const float*)d_in[16];
    const float* wnw  = (const float*)d_in[17];
    const float* wnb  = (const float*)d_in[18];
    float* out = (float*)d_out;

    float *p_h, *p_atom;
    __half *p_xs, *p_xd, *p_xm, *p_ea, *p_em, *p_ea2, *p_em2;
    cudaGetSymbolAddress((void**)&p_h,    g_h);
    cudaGetSymbolAddress((void**)&p_atom, g_atom);
    cudaGetSymbolAddress((void**)&p_xs,   g_xs);
    cudaGetSymbolAddress((void**)&p_xd,   g_xd);
    cudaGetSymbolAddress((void**)&p_xm,   g_xm);
    cudaGetSymbolAddress((void**)&p_ea,   g_ea);
    cudaGetSymbolAddress((void**)&p_em,   g_em);
    cudaGetSymbolAddress((void**)&p_ea2,  g_ea2);
    cudaGetSymbolAddress((void**)&p_em2,  g_em2);

    const int smem_atomf = (2 * 64 * 136 + 2 * 16 * PITCHN) * 4;  // 82944
    const int smem_combf = (2 * 16 * 40 + 2 * 16 * PITCHN) * 4;   // 18432
    const int smem_e4    = 2 * 16 * (4 * 32 + 8) * 4;             // 17408
    const int smem_c1    = 2 * 16 * (1 * 32 + 8) * 4;             // 5120
    cudaFuncSetAttribute(k_atomf,
                         cudaFuncAttributeMaxDynamicSharedMemorySize, smem_atomf);

    cudaStream_t s2;
    cudaStreamCreateWithFlags(&s2, cudaStreamNonBlocking);
    cudaEvent_t evFork, evSide, evMsg0, evNsum, evCombf, evAggr;
    cudaEventCreateWithFlags(&evFork,  cudaEventDisableTiming);
    cudaEventCreateWithFlags(&evSide,  cudaEventDisableTiming);
    cudaEventCreateWithFlags(&evMsg0,  cudaEventDisableTiming);
    cudaEventCreateWithFlags(&evNsum,  cudaEventDisableTiming);
    cudaEventCreateWithFlags(&evCombf, cudaEventDisableTiming);
    cudaEventCreateWithFlags(&evAggr,  cudaEventDisableTiming);

    // ---- fork: side stream does init0 + elin while main does atomf ----
    cudaEventRecord(evFork, 0);
    cudaStreamWaitEvent(s2, evFork, 0);

    k_init<<<512, 256, 0, s2>>>();
    {
        GArgs ge;
        ge.A = eattr; ge.M = NE; ge.Astride = 32; ge.Bstride = 32; ge.Ostride = 32;
        ge.B[0] = aew;        ge.B[1] = mew;        ge.B[2] = aew + 1024; ge.B[3] = mew + 1024;
        ge.bias[0] = aeb;     ge.bias[1] = meb;     ge.bias[2] = aeb + 32; ge.bias[3] = meb + 32;
        ge.out[0] = p_ea; ge.out[1] = p_em; ge.out[2] = p_ea2; ge.out[3] = p_em2;
        for (int m = 0; m < 4; m++) ge.out2[m] = p_ea;
        k_g<4, 2, 0, 1><<<444, 256, smem_e4, s2>>>(ge);
    }
    cudaEventRecord(evSide, s2);

    // main: atom + fused layer-0 node linears
    {
        GArgs ga;
        ga.A = x; ga.M = NN; ga.Astride = 128; ga.Bstride = 128; ga.Ostride = 128;
        for (int m = 0; m < 4; m++) {
            ga.B[m]    = atom_w + m * 32;
            ga.bias[m] = atom_b + m * 32;
        }
        ga.out[0] = p_atom; ga.out2[0] = p_h;
        NArgs na;
        na.W[0] = asw; na.W[1] = adw; na.W[2] = mdw;
        na.bias[0] = asb; na.bias[1] = adb; na.bias[2] = mdb;
        na.out[0] = p_xs; na.out[1] = p_xd; na.out[2] = p_xm;
        k_atomf<<<296, 256, smem_atomf>>>(ga, na);
    }
    cudaStreamWaitEvent(0, evSide, 0);   // join: elin + init0 done

    // ---- layer 0 edge phase (full-residency grids: 8 blocks/SM) ----
    k_attn<<<1184, 256>>>(ei, p_ea, dotw, dotb);
    k_msg<<<1184, 256>>>(ei, p_em);
    cudaEventRecord(evMsg0, 0);

    cudaStreamWaitEvent(s2, evMsg0, 0);
    k_zero_nsum<<<98, 256, 0, s2>>>();
    cudaEventRecord(evNsum, s2);

    // main: comb(l0) + fused layer-1 node linears
    {
        GArgs gc;
        gc.A = p_h; gc.M = ROWS; gc.Astride = 32; gc.Bstride = 32; gc.Ostride = 32;
        gc.B[0] = wnw; gc.bias[0] = wnb;
        gc.out[0] = p_h;
        NArgs na;
        na.W[0] = asw + 1024; na.W[1] = adw + 1024; na.W[2] = mdw + 1024;
        na.bias[0] = asb + 32; na.bias[1] = adb + 32; na.bias[2] = mdb + 32;
        na.out[0] = p_xs; na.out[1] = p_xd; na.out[2] = p_xm;
        k_combf<<<444, 256, smem_combf>>>(gc, na);
    }
    cudaEventRecord(evCombf, 0);

    cudaStreamWaitEvent(s2, evCombf, 0);
    k_zero_aggr<<<444, 256, 0, s2>>>();
    cudaEventRecord(evAggr, s2);

    // ---- layer 1 edge phase ----
    cudaStreamWaitEvent(0, evNsum, 0);
    k_attn<<<1184, 256>>>(ei, p_ea2, dotw + 32, dotb + 1);
    cudaStreamWaitEvent(0, evAggr, 0);
    k_msg<<<1184, 256>>>(ei, p_em2);

    // final comb + head-mean -> out
    {
        GArgs gc;
        gc.A = p_h; gc.M = ROWS; gc.Astride = 32; gc.Bstride = 32; gc.Ostride = 32;
        gc.B[0] = wnw + 1024; gc.B[1] = gc.B[2] = gc.B[3] = gc.B[0];
        gc.bias[0] = wnb + 32; gc.bias[1] = gc.bias[2] = gc.bias[3] = gc.bias[0];
        gc.out[0] = out; gc.out[1] = gc.out[2] = gc.out[3] = out;
        gc.out2[0] = gc.out2[1] = gc.out2[2] = gc.out2[3] = p_h;
        k_g<1, 2, 3, 0><<<444, 256, smem_c1>>>(gc);
    }
}